// round 1
// baseline (speedup 1.0000x reference)
#include <cuda_runtime.h>
#include <math.h>
#include <stddef.h>

#define CDIM 768
#define NHEAD 12
#define HDIM 64
#define BBATCH 4
#define TT 16
#define KPATCH 196
#define LSEQ 3137           // 1 + K*T
#define BKR 784             // B*K
#define MT 12544            // BKR*TT
#define SSP 64              // B*T
#define LSP 197             // 1 + K
#define MSP 12608           // SSP*LSP
#define MOUT 12548          // B*LSEQ
#define HID 3072
#define ATT_SCALE 0.125f    // (64)^-0.5

// ------------------------- device scratch (static, allocation-free) ---------
__device__ float g_xtn   [(size_t)MT   * CDIM];
__device__ float g_gath  [(size_t)BKR * 8 * CDIM];
__device__ float g_qkv   [(size_t)MSP  * 3 * CDIM];
__device__ float g_att   [(size_t)MSP  * CDIM];
__device__ float g_x16   [(size_t)MT   * CDIM];
__device__ float g_x8    [(size_t)BKR * 8 * CDIM];
__device__ float g_x4    [(size_t)BKR * 4 * CDIM];
__device__ float g_xtfull[(size_t)MT   * CDIM];
__device__ float g_xsn   [(size_t)MSP  * CDIM];   // spatial LN input; reused for LN2(x_cat)
__device__ float g_ressp [(size_t)MSP  * CDIM];
__device__ float g_scores[(size_t)SSP * NHEAD * LSP * LSP];
__device__ float g_clssp [(size_t)SSP  * CDIM];
__device__ float g_clsout[(size_t)BBATCH * CDIM];
__device__ float g_xcat  [(size_t)MOUT * CDIM];
__device__ float g_h1    [(size_t)MOUT * HID];
__device__ float g_h2    [(size_t)MOUT * CDIM];

// ------------------------- SGEMM: C = A(MxK) * B(KxN) [+bias] [gelu] --------
// Requires K % 16 == 0, N % 64 == 0 (true for all call sites: K in {768,3072},
// N in {768,2304,3072}). M arbitrary.
__global__ void sgemm_kernel(const float* __restrict__ A, const float* __restrict__ Bm,
                             const float* __restrict__ bias, float* __restrict__ Cm,
                             int M, int N, int Kd, int act) {
    __shared__ float As[16][65];
    __shared__ float Bs[16][64];
    const int tx = threadIdx.x, ty = threadIdx.y;
    const int tid = ty * 16 + tx;
    const int rowBase = blockIdx.y * 64;
    const int colBase = blockIdx.x * 64;

    float acc[4][4] = {};

    const int aCol  = tid % 16;   // k within tile
    const int aRow0 = tid / 16;   // 0..15
    const int bCol  = tid % 64;
    const int bRow0 = tid / 64;   // 0..3

    for (int k0 = 0; k0 < Kd; k0 += 16) {
        #pragma unroll
        for (int i = 0; i < 4; i++) {
            int m = rowBase + aRow0 + i * 16;
            As[aCol][aRow0 + i * 16] = (m < M) ? A[(size_t)m * Kd + k0 + aCol] : 0.f;
        }
        #pragma unroll
        for (int i = 0; i < 4; i++) {
            int kk = bRow0 + i * 4;
            Bs[kk][bCol] = Bm[(size_t)(k0 + kk) * N + colBase + bCol];
        }
        __syncthreads();
        #pragma unroll
        for (int k = 0; k < 16; k++) {
            float a[4], b[4];
            #pragma unroll
            for (int i = 0; i < 4; i++) a[i] = As[k][ty + i * 16];
            #pragma unroll
            for (int j = 0; j < 4; j++) b[j] = Bs[k][tx + j * 16];
            #pragma unroll
            for (int i = 0; i < 4; i++)
                #pragma unroll
                for (int j = 0; j < 4; j++)
                    acc[i][j] = fmaf(a[i], b[j], acc[i][j]);
        }
        __syncthreads();
    }

    #pragma unroll
    for (int i = 0; i < 4; i++) {
        int m = rowBase + ty + i * 16;
        if (m >= M) continue;
        #pragma unroll
        for (int j = 0; j < 4; j++) {
            int n = colBase + tx + j * 16;
            float v = acc[i][j];
            if (bias) v += bias[n];
            if (act == 1) v = 0.5f * v * (1.f + erff(v * 0.70710678118654752f));
            Cm[(size_t)m * N + n] = v;
        }
    }
}

// ------------------------- LayerNorm primitives -----------------------------
__device__ __forceinline__ void ln_row(const float* __restrict__ src,
                                       float* __restrict__ dst,
                                       const float* __restrict__ g,
                                       const float* __restrict__ bta) {
    __shared__ float sm0[8], sm1[8];
    float s = 0.f, ss = 0.f;
    for (int c = threadIdx.x; c < CDIM; c += blockDim.x) {
        float v = src[c];
        s += v; ss += v * v;
    }
    #pragma unroll
    for (int o = 16; o > 0; o >>= 1) {
        s  += __shfl_down_sync(0xffffffffu, s,  o);
        ss += __shfl_down_sync(0xffffffffu, ss, o);
    }
    int w = threadIdx.x >> 5;
    if ((threadIdx.x & 31) == 0) { sm0[w] = s; sm1[w] = ss; }
    __syncthreads();
    if (threadIdx.x == 0) {
        float a = 0.f, b2 = 0.f;
        int nw = blockDim.x >> 5;
        for (int i = 0; i < nw; i++) { a += sm0[i]; b2 += sm1[i]; }
        sm0[0] = a; sm1[0] = b2;
    }
    __syncthreads();
    float mean = sm0[0] * (1.f / CDIM);
    float var  = sm1[0] * (1.f / CDIM) - mean * mean;
    float rstd = rsqrtf(var + 1e-5f);
    for (int c = threadIdx.x; c < CDIM; c += blockDim.x)
        dst[c] = (src[c] - mean) * rstd * g[c] + bta[c];
}

// LN over xt = x[:,1:,:].reshape(B*K, T, C)
__global__ void ln_xt_kernel(const float* __restrict__ x, float* __restrict__ out,
                             const float* __restrict__ g, const float* __restrict__ b) {
    int r = blockIdx.x;                 // 0..MT
    int bb = r / (KPATCH * TT);
    int off = r % (KPATCH * TT);
    const float* src = x + ((size_t)bb * LSEQ + 1 + off) * CDIM;
    ln_row(src, out + (size_t)r * CDIM, g, b);
}

// Contiguous LN
__global__ void ln_contig_kernel(const float* __restrict__ in, float* __restrict__ out,
                                 const float* __restrict__ g, const float* __restrict__ b,
                                 int M) {
    int r = blockIdx.x;
    if (r >= M) return;
    ln_row(in + (size_t)r * CDIM, out + (size_t)r * CDIM, g, b);
}

// LN of res_spatial[:,0,:] (row stride LSP) -> g_clssp
__global__ void ln_cls_kernel(const float* __restrict__ in, float* __restrict__ out,
                              const float* __restrict__ g, const float* __restrict__ b) {
    int r = blockIdx.x; // 0..SSP
    ln_row(in + (size_t)r * LSP * CDIM, out + (size_t)r * CDIM, g, b);
}

// Build spatial sequences + LN1 in one pass
__global__ void build_xs_ln_kernel(const float* __restrict__ x, const float* __restrict__ xtfull,
                                   const float* __restrict__ g, const float* __restrict__ bta,
                                   float* __restrict__ out) {
    int r = blockIdx.x;                 // 0..MSP
    int s = r / LSP, i = r % LSP;
    int bb = s / TT, t = s % TT;
    const float* src = (i == 0)
        ? (x + (size_t)bb * LSEQ * CDIM)
        : (xtfull + ((size_t)bb * KPATCH * TT + (size_t)(i - 1) * TT + t) * CDIM);
    ln_row(src, out + (size_t)r * CDIM, g, bta);
}

// ------------------------- gather temporal tail tokens ----------------------
__global__ void gather_tail_kernel(const float* __restrict__ in, float* __restrict__ out, int Ts) {
    size_t idx = (size_t)blockIdx.x * blockDim.x + threadIdx.x;
    size_t tot = (size_t)BKR * Ts * CDIM;
    if (idx >= tot) return;
    int c = (int)(idx % CDIM);
    size_t row = idx / CDIM;
    int j = (int)(row / Ts), t = (int)(row % Ts);
    out[idx] = in[((size_t)j * TT + (TT - Ts) + t) * CDIM + c];
}

// ------------------------- batched attention (shared for all MHAs) ----------
// qkv layout: row m = s*L + token, cols [q|k|v] each C wide, head h at h*HDIM.
__global__ void attn_scores_kernel(const float* __restrict__ qkv, float* __restrict__ S,
                                   int L, float scale) {
    int bh = blockIdx.z;
    int s = bh / NHEAD, h = bh % NHEAD;
    int qT = blockIdx.y * 16, kT = blockIdx.x * 16;
    __shared__ float qs[16][17], ks[16][17];
    float acc = 0.f;
    const float* qbase = qkv + (size_t)s * L * 3 * CDIM + (size_t)h * HDIM;
    const float* kbase = qbase + CDIM;
    for (int d0 = 0; d0 < HDIM; d0 += 16) {
        int qr = qT + threadIdx.y;
        qs[threadIdx.y][threadIdx.x] = (qr < L) ? qbase[(size_t)qr * 3 * CDIM + d0 + threadIdx.x] : 0.f;
        int kr = kT + threadIdx.y;
        ks[threadIdx.y][threadIdx.x] = (kr < L) ? kbase[(size_t)kr * 3 * CDIM + d0 + threadIdx.x] : 0.f;
        __syncthreads();
        #pragma unroll
        for (int dd = 0; dd < 16; dd++)
            acc = fmaf(qs[threadIdx.y][dd], ks[threadIdx.x][dd], acc);
        __syncthreads();
    }
    int qi = qT + threadIdx.y, ki = kT + threadIdx.x;
    if (qi < L && ki < L)
        S[(size_t)bh * L * L + (size_t)qi * L + ki] = acc * scale;
}

__global__ void softmax_kernel(float* __restrict__ S, int rows, int L) {
    int row = blockIdx.x * 8 + (threadIdx.x >> 5);
    if (row >= rows) return;
    int lane = threadIdx.x & 31;
    float* p = S + (size_t)row * L;
    float mx = -1e30f;
    for (int i = lane; i < L; i += 32) mx = fmaxf(mx, p[i]);
    #pragma unroll
    for (int o = 16; o > 0; o >>= 1) mx = fmaxf(mx, __shfl_xor_sync(0xffffffffu, mx, o));
    float sum = 0.f;
    for (int i = lane; i < L; i += 32) { float e = expf(p[i] - mx); p[i] = e; sum += e; }
    #pragma unroll
    for (int o = 16; o > 0; o >>= 1) sum += __shfl_xor_sync(0xffffffffu, sum, o);
    float inv = 1.f / sum;
    for (int i = lane; i < L; i += 32) p[i] *= inv;
}

__global__ void attn_out_kernel(const float* __restrict__ qkv, const float* __restrict__ S,
                                float* __restrict__ out, int L) {
    int bh = blockIdx.y;
    int s = bh / NHEAD, h = bh % NHEAD;
    int q = blockIdx.x * blockDim.y + threadIdx.y;
    if (q >= L) return;
    int d = threadIdx.x;
    const float* p  = S + ((size_t)bh * L + q) * L;
    const float* vb = qkv + (size_t)s * L * 3 * CDIM + 2 * CDIM + (size_t)h * HDIM + d;
    float acc = 0.f;
    for (int k = 0; k < L; k++)
        acc = fmaf(p[k], vb[(size_t)k * 3 * CDIM], acc);
    out[((size_t)s * L + q) * CDIM + (size_t)h * HDIM + d] = acc;
}

// ------------------------- pointwise steps ----------------------------------
// Blend x4/x8 into x16 in place
__global__ void combine_kernel(float* __restrict__ x16, const float* __restrict__ x8,
                               const float* __restrict__ x4) {
    size_t idx = (size_t)blockIdx.x * blockDim.x + threadIdx.x;
    size_t tot = (size_t)MT * CDIM;
    if (idx >= tot) return;
    int c = (int)(idx % CDIM);
    size_t row = idx / CDIM;
    int j = (int)(row / TT), t = (int)(row % TT);
    float v = x16[idx];
    if (t >= 8) {
        float v8 = x8[((size_t)j * 8 + (t - 8)) * CDIM + c];
        if (t >= 12) v8 = 0.5f * v8 + 0.5f * x4[((size_t)j * 4 + (t - 12)) * CDIM + c];
        v = 0.5f * v + 0.5f * v8;
    }
    x16[idx] = v;
}

// xt_full += x[:,1:,:]
__global__ void add_x_residual_kernel(float* __restrict__ xtfull, const float* __restrict__ x) {
    size_t idx = (size_t)blockIdx.x * blockDim.x + threadIdx.x;
    size_t tot = (size_t)MT * CDIM;
    if (idx >= tot) return;
    int c = (int)(idx % CDIM);
    size_t row = idx / CDIM;
    int bb = (int)(row / (KPATCH * TT));
    int off = (int)(row % (KPATCH * TT));
    xtfull[idx] += x[((size_t)bb * LSEQ + 1 + off) * CDIM + c];
}

// CLS token attention (tiny): per batch b
__global__ void cls_attn_kernel(const float* __restrict__ clssp, float* __restrict__ out) {
    int b = blockIdx.x;
    __shared__ float dots[TT];
    __shared__ float wts[TT];
    int w = threadIdx.x >> 5, lane = threadIdx.x & 31;
    const float* base = clssp + (size_t)b * TT * CDIM;
    const float* tgt = base + (size_t)(TT - 1) * CDIM;
    for (int t = w; t < TT; t += 8) {
        float sd = 0.f;
        for (int c = lane; c < CDIM; c += 32) sd = fmaf(tgt[c], base[(size_t)t * CDIM + c], sd);
        #pragma unroll
        for (int o = 16; o > 0; o >>= 1) sd += __shfl_xor_sync(0xffffffffu, sd, o);
        if (lane == 0) dots[t] = sd;
    }
    __syncthreads();
    if (threadIdx.x == 0) {
        float mx = -1e30f;
        for (int t = 0; t < TT; t++) mx = fmaxf(mx, dots[t]);
        float s = 0.f;
        for (int t = 0; t < TT; t++) { float e = expf(dots[t] - mx); wts[t] = e; s += e; }
        float inv = 1.f / s;
        for (int t = 0; t < TT; t++) wts[t] *= inv;
    }
    __syncthreads();
    for (int c = threadIdx.x; c < CDIM; c += blockDim.x) {
        float a = 0.f;
        #pragma unroll
        for (int t = 0; t < TT; t++) a = fmaf(wts[t], base[(size_t)t * CDIM + c], a);
        out[(size_t)b * CDIM + c] = a;
    }
}

// x_cat = concat([init_cls, xt_full]) + concat([cls_out, x_s])
__global__ void build_xcat_kernel(const float* __restrict__ x, const float* __restrict__ xtfull,
                                  const float* __restrict__ ressp, const float* __restrict__ clsout,
                                  float* __restrict__ xcat) {
    size_t idx = (size_t)blockIdx.x * blockDim.x + threadIdx.x;
    size_t tot = (size_t)MOUT * CDIM;
    if (idx >= tot) return;
    int c = (int)(idx % CDIM);
    size_t row = idx / CDIM;
    int bb = (int)(row / LSEQ);
    int i = (int)(row % LSEQ);
    float v;
    if (i == 0) {
        v = x[idx] + clsout[(size_t)bb * CDIM + c];
    } else {
        int n = i - 1;
        int k = n / TT, t = n % TT;
        v = xtfull[((size_t)bb * KPATCH * TT + n) * CDIM + c]
          + ressp[(((size_t)(bb * TT + t)) * LSP + 1 + k) * CDIM + c];
    }
    xcat[idx] = v;
}

__global__ void final_add_kernel(const float* __restrict__ xcat, const float* __restrict__ h2,
                                 float* __restrict__ out) {
    size_t idx = (size_t)blockIdx.x * blockDim.x + threadIdx.x;
    size_t tot = (size_t)MOUT * CDIM;
    if (idx >= tot) return;
    out[idx] = xcat[idx] + h2[idx];
}

// ------------------------- host orchestration -------------------------------
static inline void sgemm_launch(const float* A, const float* B, const float* bias,
                                float* C, int M, int N, int K, int act) {
    dim3 blk(16, 16);
    dim3 grd(N / 64, (M + 63) / 64);
    sgemm_kernel<<<grd, blk>>>(A, B, bias, C, M, N, K, act);
}

static inline void run_mha(const float* Ain, const float* Wqkv, const float* Wp,
                           const float* bp, float* qkv, float* scores, float* att,
                           float* outbuf, int nseq, int L) {
    int M = nseq * L;
    sgemm_launch(Ain, Wqkv, nullptr, qkv, M, 3 * CDIM, CDIM, 0);
    {
        dim3 blk(16, 16);
        dim3 grd((L + 15) / 16, (L + 15) / 16, nseq * NHEAD);
        attn_scores_kernel<<<grd, blk>>>(qkv, scores, L, ATT_SCALE);
    }
    {
        int rows = nseq * NHEAD * L;
        softmax_kernel<<<(rows + 7) / 8, 256>>>(scores, rows, L);
    }
    {
        dim3 blk(HDIM, 4);
        dim3 grd((L + 3) / 4, nseq * NHEAD);
        attn_out_kernel<<<grd, blk>>>(qkv, scores, att, L);
    }
    sgemm_launch(att, Wp, bp, outbuf, M, CDIM, CDIM, 0);
}

extern "C" void kernel_launch(void* const* d_in, const int* in_sizes, int n_in,
                              void* d_out, int out_size) {
    const float* x       = (const float*)d_in[0];
    const float* ln1_g   = (const float*)d_in[4];
    const float* ln1_b   = (const float*)d_in[5];
    const float* lnt_g   = (const float*)d_in[6];
    const float* lnt_b   = (const float*)d_in[7];
    const float* ln2_g   = (const float*)d_in[8];
    const float* ln2_b   = (const float*)d_in[9];
    const float* lncls_g = (const float*)d_in[10];
    const float* lncls_b = (const float*)d_in[11];
    const float* Wqkv_s  = (const float*)d_in[12];
    const float* Wproj_s = (const float*)d_in[13];
    const float* bproj_s = (const float*)d_in[14];
    const float* Wqkv4   = (const float*)d_in[15];
    const float* Wqkv8   = (const float*)d_in[16];
    const float* Wqkv16  = (const float*)d_in[17];
    const float* Wp4     = (const float*)d_in[18];
    const float* bp4     = (const float*)d_in[19];
    const float* Wp8     = (const float*)d_in[20];
    const float* bp8     = (const float*)d_in[21];
    const float* Wp16    = (const float*)d_in[22];
    const float* bp16    = (const float*)d_in[23];
    const float* Wtfc    = (const float*)d_in[24];
    const float* btfc    = (const float*)d_in[25];
    const float* Wfc1    = (const float*)d_in[26];
    const float* bfc1    = (const float*)d_in[27];
    const float* Wfc2    = (const float*)d_in[28];
    const float* bfc2    = (const float*)d_in[29];
    float* out = (float*)d_out;

    float *xtn, *gath, *qkv, *att, *x16, *x8, *x4, *xtfull, *xsn, *ressp,
          *scores, *clssp, *clsout, *xcat, *h1, *h2;
    cudaGetSymbolAddress((void**)&xtn,    g_xtn);
    cudaGetSymbolAddress((void**)&gath,   g_gath);
    cudaGetSymbolAddress((void**)&qkv,    g_qkv);
    cudaGetSymbolAddress((void**)&att,    g_att);
    cudaGetSymbolAddress((void**)&x16,    g_x16);
    cudaGetSymbolAddress((void**)&x8,     g_x8);
    cudaGetSymbolAddress((void**)&x4,     g_x4);
    cudaGetSymbolAddress((void**)&xtfull, g_xtfull);
    cudaGetSymbolAddress((void**)&xsn,    g_xsn);
    cudaGetSymbolAddress((void**)&ressp,  g_ressp);
    cudaGetSymbolAddress((void**)&scores, g_scores);
    cudaGetSymbolAddress((void**)&clssp,  g_clssp);
    cudaGetSymbolAddress((void**)&clsout, g_clsout);
    cudaGetSymbolAddress((void**)&xcat,   g_xcat);
    cudaGetSymbolAddress((void**)&h1,     g_h1);
    cudaGetSymbolAddress((void**)&h2,     g_h2);

    const size_t EW = 256;

    // 1) LN over temporal sequences
    ln_xt_kernel<<<MT, 256>>>(x, xtn, lnt_g, lnt_b);

    // 2) Temporal MHAs at 3 scales
    run_mha(xtn, Wqkv16, Wp16, bp16, qkv, scores, att, x16, BKR, 16);

    {
        size_t tot = (size_t)BKR * 8 * CDIM;
        gather_tail_kernel<<<(int)((tot + EW - 1) / EW), (int)EW>>>(xtn, gath, 8);
    }
    run_mha(gath, Wqkv8, Wp8, bp8, qkv, scores, att, x8, BKR, 8);

    {
        size_t tot = (size_t)BKR * 4 * CDIM;
        gather_tail_kernel<<<(int)((tot + EW - 1) / EW), (int)EW>>>(xtn, gath, 4);
    }
    run_mha(gath, Wqkv4, Wp4, bp4, qkv, scores, att, x4, BKR, 4);

    // 3) Blend scales (in place on x16)
    {
        size_t tot = (size_t)MT * CDIM;
        combine_kernel<<<(int)((tot + EW - 1) / EW), (int)EW>>>(x16, x8, x4);
    }

    // 4) xt_full = x16 @ Wtfc + btfc + x[:,1:,:]
    sgemm_launch(x16, Wtfc, btfc, xtfull, MT, CDIM, CDIM, 0);
    {
        size_t tot = (size_t)MT * CDIM;
        add_x_residual_kernel<<<(int)((tot + EW - 1) / EW), (int)EW>>>(xtfull, x);
    }

    // 5) Spatial MHA
    build_xs_ln_kernel<<<MSP, 256>>>(x, xtfull, ln1_g, ln1_b, xsn);
    run_mha(xsn, Wqkv_s, Wproj_s, bproj_s, qkv, scores, att, ressp, SSP, LSP);

    // 6) CLS path
    ln_cls_kernel<<<SSP, 256>>>(ressp, clssp, lncls_g, lncls_b);
    cls_attn_kernel<<<BBATCH, 256>>>(clssp, clsout);

    // 7) x_cat
    {
        size_t tot = (size_t)MOUT * CDIM;
        build_xcat_kernel<<<(int)((tot + EW - 1) / EW), (int)EW>>>(x, xtfull, ressp, clsout, xcat);
    }

    // 8) MLP: LN2 -> fc1 (GELU exact) -> fc2 -> residual
    ln_contig_kernel<<<MOUT, 256>>>(xcat, xsn, ln2_g, ln2_b, MOUT);
    sgemm_launch(xsn, Wfc1, bfc1, h1, MOUT, HID, CDIM, 1);
    sgemm_launch(h1, Wfc2, bfc2, h2, MOUT, CDIM, HID, 0);
    {
        size_t tot = (size_t)MOUT * CDIM;
        final_add_kernel<<<(int)((tot + EW - 1) / EW), (int)EW>>>(xcat, h2, out);
    }
}

// round 2
// speedup vs baseline: 2.2139x; 2.2139x over previous
#include <cuda_runtime.h>
#include <cuda_bf16.h>
#include <math.h>
#include <stddef.h>
#include <stdint.h>

#define CDIM 768
#define NHEAD 12
#define HDIM 64
#define BBATCH 4
#define TT 16
#define KPATCH 196
#define LSEQ 3137           // 1 + K*T
#define BKR 784             // B*K
#define MT 12544            // BKR*TT
#define SSP 64              // B*T
#define LSP 197             // 1 + K
#define MSP 12608           // SSP*LSP
#define MOUT 12548          // B*LSEQ
#define HID 3072
#define ATT_SCALE 0.125f    // (64)^-0.5

// ------------------------- device scratch (static, allocation-free) ---------
__device__ float g_xtn   [(size_t)MT   * CDIM];
__device__ float g_gath  [(size_t)BKR * 8 * CDIM];
__device__ float g_qkv   [(size_t)MSP  * 3 * CDIM];
__device__ float g_att   [(size_t)MSP  * CDIM];
__device__ float g_x16   [(size_t)MT   * CDIM];
__device__ float g_x8    [(size_t)BKR * 8 * CDIM];
__device__ float g_x4    [(size_t)BKR * 4 * CDIM];
__device__ float g_xtfull[(size_t)MT   * CDIM];
__device__ float g_xsn   [(size_t)MSP  * CDIM];
__device__ float g_ressp [(size_t)MSP  * CDIM];
__device__ float g_scores[(size_t)SSP * NHEAD * LSP * LSP];
__device__ float g_clssp [(size_t)SSP  * CDIM];
__device__ float g_clsout[(size_t)BBATCH * CDIM];
__device__ float g_xcat  [(size_t)MOUT * CDIM];
__device__ float g_h1    [(size_t)MOUT * HID];
__device__ float g_h2    [(size_t)MOUT * CDIM];

// ======================= tensor-core GEMM (bf16 x3 split) ===================
// C[M,N] = A[M,K](f32,row) * B[K,N](f32,row) [+bias] [gelu]
// Accuracy: A=Ah+Al, B=Bh+Bl (bf16); C ~= AhBh + AhBl + AlBh  (err ~2^-16)
// CTA tile 128x128, K-chunk 32, 8 warps of 64x32.

#define LDSM4(R, addr) \
    asm volatile("ldmatrix.sync.aligned.m8n8.x4.shared.b16 {%0,%1,%2,%3}, [%4];" \
                 : "=r"(R[0]), "=r"(R[1]), "=r"(R[2]), "=r"(R[3]) : "r"(addr))
#define LDSM4T(R, addr) \
    asm volatile("ldmatrix.sync.aligned.m8n8.x4.trans.shared.b16 {%0,%1,%2,%3}, [%4];" \
                 : "=r"(R[0]), "=r"(R[1]), "=r"(R[2]), "=r"(R[3]) : "r"(addr))
#define MMA_BF16(d, a, b0, b1) \
    asm volatile("mma.sync.aligned.m16n8k16.row.col.f32.bf16.bf16.f32 " \
                 "{%0,%1,%2,%3}, {%4,%5,%6,%7}, {%8,%9}, {%0,%1,%2,%3};" \
                 : "+f"(d[0]), "+f"(d[1]), "+f"(d[2]), "+f"(d[3]) \
                 : "r"(a[0]), "r"(a[1]), "r"(a[2]), "r"(a[3]), "r"(b0), "r"(b1))

// A smem tile 128x32 bf16 (row = 64B). Swizzle 16B chunks by 128B-line idx.
__device__ __forceinline__ int swizA(int r, int c) {
    int b = (r << 6) | (c << 1);
    return b ^ (((r >> 1) & 7) << 4);
}
// B smem tile 32x128 bf16 (row = 256B). Swizzle 16B chunks by k row.
__device__ __forceinline__ int swizB(int k, int n) {
    int b = (k << 8) | (n << 1);
    return b ^ ((k & 7) << 4);
}

__device__ __forceinline__ void split2(float v, unsigned short& h, unsigned short& l) {
    __nv_bfloat16 bh = __float2bfloat16_rn(v);
    __nv_bfloat16 bl = __float2bfloat16_rn(v - __bfloat162float(bh));
    h = __bfloat16_as_ushort(bh);
    l = __bfloat16_as_ushort(bl);
}

__device__ __forceinline__ void gemm_load_chunk(
    const float* __restrict__ A, const float* __restrict__ Bm,
    int M, int N, int Kd, int bm, int bn, int k0,
    int aR, int aC, int bK, int bN,
    float4 (&bufA)[4], float4 (&bufB)[4]) {
    #pragma unroll
    for (int i = 0; i < 4; i++) {
        int r = bm + aR + 32 * i;
        bufA[i] = (r < M) ? *(const float4*)&A[(size_t)r * Kd + k0 + aC]
                          : make_float4(0.f, 0.f, 0.f, 0.f);
        bufB[i] = *(const float4*)&Bm[(size_t)(k0 + bK + 8 * i) * N + bn + bN];
    }
}

__device__ __forceinline__ void gemm_store_chunk(
    char* sm, int aR, int aC, int bK, int bN,
    const float4 (&bufA)[4], const float4 (&bufB)[4]) {
    #pragma unroll
    for (int i = 0; i < 4; i++) {
        unsigned short h0, h1, h2, h3, l0, l1, l2, l3;
        // A
        split2(bufA[i].x, h0, l0); split2(bufA[i].y, h1, l1);
        split2(bufA[i].z, h2, l2); split2(bufA[i].w, h3, l3);
        {
            int off = swizA(aR + 32 * i, aC);
            uint2 hi = make_uint2((uint32_t)h0 | ((uint32_t)h1 << 16),
                                  (uint32_t)h2 | ((uint32_t)h3 << 16));
            uint2 lo = make_uint2((uint32_t)l0 | ((uint32_t)l1 << 16),
                                  (uint32_t)l2 | ((uint32_t)l3 << 16));
            *(uint2*)(sm + off)        = hi;
            *(uint2*)(sm + 8192 + off) = lo;
        }
        // B
        split2(bufB[i].x, h0, l0); split2(bufB[i].y, h1, l1);
        split2(bufB[i].z, h2, l2); split2(bufB[i].w, h3, l3);
        {
            int off = swizB(bK + 8 * i, bN);
            uint2 hi = make_uint2((uint32_t)h0 | ((uint32_t)h1 << 16),
                                  (uint32_t)h2 | ((uint32_t)h3 << 16));
            uint2 lo = make_uint2((uint32_t)l0 | ((uint32_t)l1 << 16),
                                  (uint32_t)l2 | ((uint32_t)l3 << 16));
            *(uint2*)(sm + 16384 + off) = hi;
            *(uint2*)(sm + 24576 + off) = lo;
        }
    }
}

__global__ void __launch_bounds__(256)
gemm_tc_kernel(const float* __restrict__ A, const float* __restrict__ Bm,
               const float* __restrict__ bias, float* __restrict__ Cm,
               int M, int N, int Kd, int act) {
    __shared__ __align__(16) char sm[32768];   // Ah | Al | Bh | Bl  (8KB each)
    const int tid  = threadIdx.x;
    const int lane = tid & 31;
    const int w    = tid >> 5;
    const int wm   = w & 1;    // 2 M-groups of 64
    const int wn   = w >> 1;   // 4 N-groups of 32
    const int bm   = blockIdx.y * 128;
    const int bn   = blockIdx.x * 128;

    uint32_t sb = (uint32_t)__cvta_generic_to_shared(sm);

    // ldmatrix lane addresses (hi planes; +8192 for lo)
    uint32_t aAd[4][2], bAd[2][2];
    {
        int ar = wm * 64 + (lane & 15);
        int ac = (lane >> 4) << 3;
        #pragma unroll
        for (int i = 0; i < 4; i++)
            #pragma unroll
            for (int s = 0; s < 2; s++)
                aAd[i][s] = sb + swizA(ar + 16 * i, ac + 16 * s);
        int bk  = lane & 15;
        int bn0 = wn * 32 + ((lane >> 4) << 3);
        #pragma unroll
        for (int jp = 0; jp < 2; jp++)
            #pragma unroll
            for (int s = 0; s < 2; s++)
                bAd[jp][s] = sb + 16384 + swizB(bk + 16 * s, bn0 + 16 * jp);
    }

    const int aR = tid >> 3, aC = (tid & 7) * 4;
    const int bK = tid >> 5, bN = (tid & 31) * 4;

    float acc[4][4][4];
    #pragma unroll
    for (int i = 0; i < 4; i++)
        #pragma unroll
        for (int j = 0; j < 4; j++)
            #pragma unroll
            for (int r = 0; r < 4; r++) acc[i][j][r] = 0.f;

    const int nCh = Kd >> 5;
    float4 bufA[4], bufB[4];
    gemm_load_chunk(A, Bm, M, N, Kd, bm, bn, 0, aR, aC, bK, bN, bufA, bufB);

    for (int kc = 0; kc < nCh; kc++) {
        __syncthreads();
        gemm_store_chunk(sm, aR, aC, bK, bN, bufA, bufB);
        __syncthreads();
        if (kc + 1 < nCh)
            gemm_load_chunk(A, Bm, M, N, Kd, bm, bn, (kc + 1) * 32,
                            aR, aC, bK, bN, bufA, bufB);
        #pragma unroll
        for (int s = 0; s < 2; s++) {
            uint32_t ah[4][4], al[4][4], bh[2][4], bl[2][4];
            #pragma unroll
            for (int i = 0; i < 4; i++) {
                LDSM4(ah[i], aAd[i][s]);
                LDSM4(al[i], aAd[i][s] + 8192);
            }
            #pragma unroll
            for (int jp = 0; jp < 2; jp++) {
                LDSM4T(bh[jp], bAd[jp][s]);
                LDSM4T(bl[jp], bAd[jp][s] + 8192);
            }
            #pragma unroll
            for (int i = 0; i < 4; i++) {
                #pragma unroll
                for (int j = 0; j < 4; j++) {
                    const uint32_t* bhj = &bh[j >> 1][(j & 1) * 2];
                    const uint32_t* blj = &bl[j >> 1][(j & 1) * 2];
                    MMA_BF16(acc[i][j], ah[i], bhj[0], bhj[1]);
                    MMA_BF16(acc[i][j], ah[i], blj[0], blj[1]);
                    MMA_BF16(acc[i][j], al[i], bhj[0], bhj[1]);
                }
            }
        }
    }

    // epilogue
    #pragma unroll
    for (int i = 0; i < 4; i++) {
        int r0 = bm + wm * 64 + i * 16 + (lane >> 2);
        #pragma unroll
        for (int j = 0; j < 4; j++) {
            int c0 = bn + wn * 32 + j * 8 + (lane & 3) * 2;
            float b0 = bias ? bias[c0] : 0.f;
            float b1 = bias ? bias[c0 + 1] : 0.f;
            float v0 = acc[i][j][0] + b0, v1 = acc[i][j][1] + b1;
            float v2 = acc[i][j][2] + b0, v3 = acc[i][j][3] + b1;
            if (act == 1) {
                v0 = 0.5f * v0 * (1.f + erff(v0 * 0.70710678118654752f));
                v1 = 0.5f * v1 * (1.f + erff(v1 * 0.70710678118654752f));
                v2 = 0.5f * v2 * (1.f + erff(v2 * 0.70710678118654752f));
                v3 = 0.5f * v3 * (1.f + erff(v3 * 0.70710678118654752f));
            }
            if (r0 < M)     *(float2*)&Cm[(size_t)r0 * N + c0]       = make_float2(v0, v1);
            if (r0 + 8 < M) *(float2*)&Cm[(size_t)(r0 + 8) * N + c0] = make_float2(v2, v3);
        }
    }
}

// ------------------------- LayerNorm primitives -----------------------------
__device__ __forceinline__ void ln_row(const float* __restrict__ src,
                                       float* __restrict__ dst,
                                       const float* __restrict__ g,
                                       const float* __restrict__ bta) {
    __shared__ float sm0[8], sm1[8];
    float s = 0.f, ss = 0.f;
    for (int c = threadIdx.x; c < CDIM; c += blockDim.x) {
        float v = src[c];
        s += v; ss += v * v;
    }
    #pragma unroll
    for (int o = 16; o > 0; o >>= 1) {
        s  += __shfl_down_sync(0xffffffffu, s,  o);
        ss += __shfl_down_sync(0xffffffffu, ss, o);
    }
    int w = threadIdx.x >> 5;
    if ((threadIdx.x & 31) == 0) { sm0[w] = s; sm1[w] = ss; }
    __syncthreads();
    if (threadIdx.x == 0) {
        float a = 0.f, b2 = 0.f;
        int nw = blockDim.x >> 5;
        for (int i = 0; i < nw; i++) { a += sm0[i]; b2 += sm1[i]; }
        sm0[0] = a; sm1[0] = b2;
    }
    __syncthreads();
    float mean = sm0[0] * (1.f / CDIM);
    float var  = sm1[0] * (1.f / CDIM) - mean * mean;
    float rstd = rsqrtf(var + 1e-5f);
    for (int c = threadIdx.x; c < CDIM; c += blockDim.x)
        dst[c] = (src[c] - mean) * rstd * g[c] + bta[c];
}

__global__ void ln_xt_kernel(const float* __restrict__ x, float* __restrict__ out,
                             const float* __restrict__ g, const float* __restrict__ b) {
    int r = blockIdx.x;
    int bb = r / (KPATCH * TT);
    int off = r % (KPATCH * TT);
    const float* src = x + ((size_t)bb * LSEQ + 1 + off) * CDIM;
    ln_row(src, out + (size_t)r * CDIM, g, b);
}

__global__ void ln_contig_kernel(const float* __restrict__ in, float* __restrict__ out,
                                 const float* __restrict__ g, const float* __restrict__ b,
                                 int M) {
    int r = blockIdx.x;
    if (r >= M) return;
    ln_row(in + (size_t)r * CDIM, out + (size_t)r * CDIM, g, b);
}

__global__ void ln_cls_kernel(const float* __restrict__ in, float* __restrict__ out,
                              const float* __restrict__ g, const float* __restrict__ b) {
    int r = blockIdx.x;
    ln_row(in + (size_t)r * LSP * CDIM, out + (size_t)r * CDIM, g, b);
}

__global__ void build_xs_ln_kernel(const float* __restrict__ x, const float* __restrict__ xtfull,
                                   const float* __restrict__ g, const float* __restrict__ bta,
                                   float* __restrict__ out) {
    int r = blockIdx.x;
    int s = r / LSP, i = r % LSP;
    int bb = s / TT, t = s % TT;
    const float* src = (i == 0)
        ? (x + (size_t)bb * LSEQ * CDIM)
        : (xtfull + ((size_t)bb * KPATCH * TT + (size_t)(i - 1) * TT + t) * CDIM);
    ln_row(src, out + (size_t)r * CDIM, g, bta);
}

// ------------------------- gather temporal tail tokens ----------------------
__global__ void gather_tail_kernel(const float* __restrict__ in, float* __restrict__ out, int Ts) {
    size_t idx = (size_t)blockIdx.x * blockDim.x + threadIdx.x;
    size_t tot = (size_t)BKR * Ts * CDIM;
    if (idx >= tot) return;
    int c = (int)(idx % CDIM);
    size_t row = idx / CDIM;
    int j = (int)(row / Ts), t = (int)(row % Ts);
    out[idx] = in[((size_t)j * TT + (TT - Ts) + t) * CDIM + c];
}

// ------------------------- batched attention --------------------------------
__global__ void attn_scores_kernel(const float* __restrict__ qkv, float* __restrict__ S,
                                   int L, float scale) {
    int bh = blockIdx.z;
    int s = bh / NHEAD, h = bh % NHEAD;
    int qT = blockIdx.y * 16, kT = blockIdx.x * 16;
    __shared__ float qs[16][17], ks[16][17];
    float acc = 0.f;
    const float* qbase = qkv + (size_t)s * L * 3 * CDIM + (size_t)h * HDIM;
    const float* kbase = qbase + CDIM;
    for (int d0 = 0; d0 < HDIM; d0 += 16) {
        int qr = qT + threadIdx.y;
        qs[threadIdx.y][threadIdx.x] = (qr < L) ? qbase[(size_t)qr * 3 * CDIM + d0 + threadIdx.x] : 0.f;
        int kr = kT + threadIdx.y;
        ks[threadIdx.y][threadIdx.x] = (kr < L) ? kbase[(size_t)kr * 3 * CDIM + d0 + threadIdx.x] : 0.f;
        __syncthreads();
        #pragma unroll
        for (int dd = 0; dd < 16; dd++)
            acc = fmaf(qs[threadIdx.y][dd], ks[threadIdx.x][dd], acc);
        __syncthreads();
    }
    int qi = qT + threadIdx.y, ki = kT + threadIdx.x;
    if (qi < L && ki < L)
        S[(size_t)bh * L * L + (size_t)qi * L + ki] = acc * scale;
}

__global__ void softmax_kernel(float* __restrict__ S, int rows, int L) {
    int row = blockIdx.x * 8 + (threadIdx.x >> 5);
    if (row >= rows) return;
    int lane = threadIdx.x & 31;
    float* p = S + (size_t)row * L;
    float mx = -1e30f;
    for (int i = lane; i < L; i += 32) mx = fmaxf(mx, p[i]);
    #pragma unroll
    for (int o = 16; o > 0; o >>= 1) mx = fmaxf(mx, __shfl_xor_sync(0xffffffffu, mx, o));
    float sum = 0.f;
    for (int i = lane; i < L; i += 32) { float e = expf(p[i] - mx); p[i] = e; sum += e; }
    #pragma unroll
    for (int o = 16; o > 0; o >>= 1) sum += __shfl_xor_sync(0xffffffffu, sum, o);
    float inv = 1.f / sum;
    for (int i = lane; i < L; i += 32) p[i] *= inv;
}

__global__ void attn_out_kernel(const float* __restrict__ qkv, const float* __restrict__ S,
                                float* __restrict__ out, int L) {
    int bh = blockIdx.y;
    int s = bh / NHEAD, h = bh % NHEAD;
    int q = blockIdx.x * blockDim.y + threadIdx.y;
    if (q >= L) return;
    int d = threadIdx.x;
    const float* p  = S + ((size_t)bh * L + q) * L;
    const float* vb = qkv + (size_t)s * L * 3 * CDIM + 2 * CDIM + (size_t)h * HDIM + d;
    float acc = 0.f;
    for (int k = 0; k < L; k++)
        acc = fmaf(p[k], vb[(size_t)k * 3 * CDIM], acc);
    out[((size_t)s * L + q) * CDIM + (size_t)h * HDIM + d] = acc;
}

// ------------------------- pointwise steps ----------------------------------
__global__ void combine_kernel(float* __restrict__ x16, const float* __restrict__ x8,
                               const float* __restrict__ x4) {
    size_t idx = (size_t)blockIdx.x * blockDim.x + threadIdx.x;
    size_t tot = (size_t)MT * CDIM;
    if (idx >= tot) return;
    int c = (int)(idx % CDIM);
    size_t row = idx / CDIM;
    int j = (int)(row / TT), t = (int)(row % TT);
    float v = x16[idx];
    if (t >= 8) {
        float v8 = x8[((size_t)j * 8 + (t - 8)) * CDIM + c];
        if (t >= 12) v8 = 0.5f * v8 + 0.5f * x4[((size_t)j * 4 + (t - 12)) * CDIM + c];
        v = 0.5f * v + 0.5f * v8;
    }
    x16[idx] = v;
}

__global__ void add_x_residual_kernel(float* __restrict__ xtfull, const float* __restrict__ x) {
    size_t idx = (size_t)blockIdx.x * blockDim.x + threadIdx.x;
    size_t tot = (size_t)MT * CDIM;
    if (idx >= tot) return;
    int c = (int)(idx % CDIM);
    size_t row = idx / CDIM;
    int bb = (int)(row / (KPATCH * TT));
    int off = (int)(row % (KPATCH * TT));
    xtfull[idx] += x[((size_t)bb * LSEQ + 1 + off) * CDIM + c];
}

__global__ void cls_attn_kernel(const float* __restrict__ clssp, float* __restrict__ out) {
    int b = blockIdx.x;
    __shared__ float dots[TT];
    __shared__ float wts[TT];
    int w = threadIdx.x >> 5, lane = threadIdx.x & 31;
    const float* base = clssp + (size_t)b * TT * CDIM;
    const float* tgt = base + (size_t)(TT - 1) * CDIM;
    for (int t = w; t < TT; t += 8) {
        float sd = 0.f;
        for (int c = lane; c < CDIM; c += 32) sd = fmaf(tgt[c], base[(size_t)t * CDIM + c], sd);
        #pragma unroll
        for (int o = 16; o > 0; o >>= 1) sd += __shfl_xor_sync(0xffffffffu, sd, o);
        if (lane == 0) dots[t] = sd;
    }
    __syncthreads();
    if (threadIdx.x == 0) {
        float mx = -1e30f;
        for (int t = 0; t < TT; t++) mx = fmaxf(mx, dots[t]);
        float s = 0.f;
        for (int t = 0; t < TT; t++) { float e = expf(dots[t] - mx); wts[t] = e; s += e; }
        float inv = 1.f / s;
        for (int t = 0; t < TT; t++) wts[t] *= inv;
    }
    __syncthreads();
    for (int c = threadIdx.x; c < CDIM; c += blockDim.x) {
        float a = 0.f;
        #pragma unroll
        for (int t = 0; t < TT; t++) a = fmaf(wts[t], base[(size_t)t * CDIM + c], a);
        out[(size_t)b * CDIM + c] = a;
    }
}

__global__ void build_xcat_kernel(const float* __restrict__ x, const float* __restrict__ xtfull,
                                  const float* __restrict__ ressp, const float* __restrict__ clsout,
                                  float* __restrict__ xcat) {
    size_t idx = (size_t)blockIdx.x * blockDim.x + threadIdx.x;
    size_t tot = (size_t)MOUT * CDIM;
    if (idx >= tot) return;
    int c = (int)(idx % CDIM);
    size_t row = idx / CDIM;
    int bb = (int)(row / LSEQ);
    int i = (int)(row % LSEQ);
    float v;
    if (i == 0) {
        v = x[idx] + clsout[(size_t)bb * CDIM + c];
    } else {
        int n = i - 1;
        int k = n / TT, t = n % TT;
        v = xtfull[((size_t)bb * KPATCH * TT + n) * CDIM + c]
          + ressp[(((size_t)(bb * TT + t)) * LSP + 1 + k) * CDIM + c];
    }
    xcat[idx] = v;
}

__global__ void final_add_kernel(const float* __restrict__ xcat, const float* __restrict__ h2,
                                 float* __restrict__ out) {
    size_t idx = (size_t)blockIdx.x * blockDim.x + threadIdx.x;
    size_t tot = (size_t)MOUT * CDIM;
    if (idx >= tot) return;
    out[idx] = xcat[idx] + h2[idx];
}

// ------------------------- host orchestration -------------------------------
static inline void sgemm_launch(const float* A, const float* B, const float* bias,
                                float* C, int M, int N, int K, int act) {
    dim3 blk(256);
    dim3 grd(N / 128, (M + 127) / 128);
    gemm_tc_kernel<<<grd, blk>>>(A, B, bias, C, M, N, K, act);
}

static inline void run_mha(const float* Ain, const float* Wqkv, const float* Wp,
                           const float* bp, float* qkv, float* scores, float* att,
                           float* outbuf, int nseq, int L) {
    int M = nseq * L;
    sgemm_launch(Ain, Wqkv, nullptr, qkv, M, 3 * CDIM, CDIM, 0);
    {
        dim3 blk(16, 16);
        dim3 grd((L + 15) / 16, (L + 15) / 16, nseq * NHEAD);
        attn_scores_kernel<<<grd, blk>>>(qkv, scores, L, ATT_SCALE);
    }
    {
        int rows = nseq * NHEAD * L;
        softmax_kernel<<<(rows + 7) / 8, 256>>>(scores, rows, L);
    }
    {
        dim3 blk(HDIM, 4);
        dim3 grd((L + 3) / 4, nseq * NHEAD);
        attn_out_kernel<<<grd, blk>>>(qkv, scores, att, L);
    }
    sgemm_launch(att, Wp, bp, outbuf, M, CDIM, CDIM, 0);
}

extern "C" void kernel_launch(void* const* d_in, const int* in_sizes, int n_in,
                              void* d_out, int out_size) {
    const float* x       = (const float*)d_in[0];
    const float* ln1_g   = (const float*)d_in[4];
    const float* ln1_b   = (const float*)d_in[5];
    const float* lnt_g   = (const float*)d_in[6];
    const float* lnt_b   = (const float*)d_in[7];
    const float* ln2_g   = (const float*)d_in[8];
    const float* ln2_b   = (const float*)d_in[9];
    const float* lncls_g = (const float*)d_in[10];
    const float* lncls_b = (const float*)d_in[11];
    const float* Wqkv_s  = (const float*)d_in[12];
    const float* Wproj_s = (const float*)d_in[13];
    const float* bproj_s = (const float*)d_in[14];
    const float* Wqkv4   = (const float*)d_in[15];
    const float* Wqkv8   = (const float*)d_in[16];
    const float* Wqkv16  = (const float*)d_in[17];
    const float* Wp4     = (const float*)d_in[18];
    const float* bp4     = (const float*)d_in[19];
    const float* Wp8     = (const float*)d_in[20];
    const float* bp8     = (const float*)d_in[21];
    const float* Wp16    = (const float*)d_in[22];
    const float* bp16    = (const float*)d_in[23];
    const float* Wtfc    = (const float*)d_in[24];
    const float* btfc    = (const float*)d_in[25];
    const float* Wfc1    = (const float*)d_in[26];
    const float* bfc1    = (const float*)d_in[27];
    const float* Wfc2    = (const float*)d_in[28];
    const float* bfc2    = (const float*)d_in[29];
    float* out = (float*)d_out;

    float *xtn, *gath, *qkv, *att, *x16, *x8, *x4, *xtfull, *xsn, *ressp,
          *scores, *clssp, *clsout, *xcat, *h1, *h2;
    cudaGetSymbolAddress((void**)&xtn,    g_xtn);
    cudaGetSymbolAddress((void**)&gath,   g_gath);
    cudaGetSymbolAddress((void**)&qkv,    g_qkv);
    cudaGetSymbolAddress((void**)&att,    g_att);
    cudaGetSymbolAddress((void**)&x16,    g_x16);
    cudaGetSymbolAddress((void**)&x8,     g_x8);
    cudaGetSymbolAddress((void**)&x4,     g_x4);
    cudaGetSymbolAddress((void**)&xtfull, g_xtfull);
    cudaGetSymbolAddress((void**)&xsn,    g_xsn);
    cudaGetSymbolAddress((void**)&ressp,  g_ressp);
    cudaGetSymbolAddress((void**)&scores, g_scores);
    cudaGetSymbolAddress((void**)&clssp,  g_clssp);
    cudaGetSymbolAddress((void**)&clsout, g_clsout);
    cudaGetSymbolAddress((void**)&xcat,   g_xcat);
    cudaGetSymbolAddress((void**)&h1,     g_h1);
    cudaGetSymbolAddress((void**)&h2,     g_h2);

    const size_t EW = 256;

    // 1) LN over temporal sequences
    ln_xt_kernel<<<MT, 256>>>(x, xtn, lnt_g, lnt_b);

    // 2) Temporal MHAs at 3 scales
    run_mha(xtn, Wqkv16, Wp16, bp16, qkv, scores, att, x16, BKR, 16);

    {
        size_t tot = (size_t)BKR * 8 * CDIM;
        gather_tail_kernel<<<(int)((tot + EW - 1) / EW), (int)EW>>>(xtn, gath, 8);
    }
    run_mha(gath, Wqkv8, Wp8, bp8, qkv, scores, att, x8, BKR, 8);

    {
        size_t tot = (size_t)BKR * 4 * CDIM;
        gather_tail_kernel<<<(int)((tot + EW - 1) / EW), (int)EW>>>(xtn, gath, 4);
    }
    run_mha(gath, Wqkv4, Wp4, bp4, qkv, scores, att, x4, BKR, 4);

    // 3) Blend scales
    {
        size_t tot = (size_t)MT * CDIM;
        combine_kernel<<<(int)((tot + EW - 1) / EW), (int)EW>>>(x16, x8, x4);
    }

    // 4) xt_full = x16 @ Wtfc + btfc + x[:,1:,:]
    sgemm_launch(x16, Wtfc, btfc, xtfull, MT, CDIM, CDIM, 0);
    {
        size_t tot = (size_t)MT * CDIM;
        add_x_residual_kernel<<<(int)((tot + EW - 1) / EW), (int)EW>>>(xtfull, x);
    }

    // 5) Spatial MHA
    build_xs_ln_kernel<<<MSP, 256>>>(x, xtfull, ln1_g, ln1_b, xsn);
    run_mha(xsn, Wqkv_s, Wproj_s, bproj_s, qkv, scores, att, ressp, SSP, LSP);

    // 6) CLS path
    ln_cls_kernel<<<SSP, 256>>>(ressp, clssp, lncls_g, lncls_b);
    cls_attn_kernel<<<BBATCH, 256>>>(clssp, clsout);

    // 7) x_cat
    {
        size_t tot = (size_t)MOUT * CDIM;
        build_xcat_kernel<<<(int)((tot + EW - 1) / EW), (int)EW>>>(x, xtfull, ressp, clsout, xcat);
    }

    // 8) MLP
    ln_contig_kernel<<<MOUT, 256>>>(xcat, xsn, ln2_g, ln2_b, MOUT);
    sgemm_launch(xsn, Wfc1, bfc1, h1, MOUT, HID, CDIM, 1);
    sgemm_launch(h1, Wfc2, bfc2, h2, MOUT, CDIM, HID, 0);
    {
        size_t tot = (size_t)MOUT * CDIM;
        final_add_kernel<<<(int)((tot + EW - 1) / EW), (int)EW>>>(xcat, h2, out);
    }
}

// round 4
// speedup vs baseline: 2.4634x; 1.1127x over previous
#include <cuda_runtime.h>
#include <cuda_bf16.h>
#include <math.h>
#include <stddef.h>
#include <stdint.h>

#define CDIM 768
#define NHEAD 12
#define HDIM 64
#define BBATCH 4
#define TT 16
#define KPATCH 196
#define LSEQ 3137           // 1 + K*T
#define BKR 784             // B*K
#define MT 12544            // BKR*TT
#define SSP 64              // B*T
#define LSP 197             // 1 + K
#define MSP 12608           // SSP*LSP
#define MOUT 12548          // B*LSEQ
#define HID 3072
#define ATT_SCALE 0.125f    // (64)^-0.5

typedef __nv_bfloat16 bf16;

// ------------------------- device scratch (static, allocation-free) ---------
__device__ float g_xtn   [(size_t)MT   * CDIM];
__device__ float g_gathf [(size_t)BKR * 8 * CDIM];
__device__ float g_qkv   [(size_t)MSP  * 3 * CDIM];
__device__ float g_x16   [(size_t)MT   * CDIM];
__device__ float g_x8    [(size_t)BKR * 8 * CDIM];
__device__ float g_x4    [(size_t)BKR * 4 * CDIM];
__device__ float g_xtfull[(size_t)MT   * CDIM];
__device__ float g_xsn   [(size_t)MSP  * CDIM];
__device__ float g_ressp [(size_t)MSP  * CDIM];
__device__ float g_scores[(size_t)SSP * NHEAD * LSP * LSP];
__device__ float g_clssp [(size_t)SSP  * CDIM];
__device__ float g_clsout[(size_t)BBATCH * CDIM];
__device__ float g_xcat  [(size_t)MOUT * CDIM];
__device__ float g_h2    [(size_t)MOUT * CDIM];

// activation planes (bf16 hi/lo)
#define PA_ELEMS ((size_t)MSP * CDIM)
__device__ bf16 g_pah[PA_ELEMS];
__device__ bf16 g_pal[PA_ELEMS];
__device__ bf16 g_pbh[PA_ELEMS];
__device__ bf16 g_pbl[PA_ELEMS];
__device__ bf16 g_h1h[(size_t)MOUT * HID];
__device__ bf16 g_h1l[(size_t)MOUT * HID];

// weight planes (bf16 hi/lo), [K,N] row-major, same layout as f32 source
#define WPOOL 14745600
__device__ bf16 g_wh[(size_t)WPOOL];
__device__ bf16 g_wl[(size_t)WPOOL];
#define OFF_QKV_S   0u
#define OFF_QKV4    1769472u
#define OFF_QKV8    3538944u
#define OFF_QKV16   5308416u
#define OFF_P_S     7077888u
#define OFF_P4      7667712u
#define OFF_P8      8257536u
#define OFF_P16     8847360u
#define OFF_TFC     9437184u
#define OFF_FC1    10027008u
#define OFF_FC2    12386304u

// ------------------------- split helpers ------------------------------------
__device__ __forceinline__ void split2(float v, unsigned short& h, unsigned short& l) {
    bf16 bh = __float2bfloat16_rn(v);
    bf16 bl = __float2bfloat16_rn(v - __bfloat162float(bh));
    h = __bfloat16_as_ushort(bh);
    l = __bfloat16_as_ushort(bl);
}

// elementwise f32 -> bf16 hi/lo planes (vectorized)
__global__ void convA_kernel(const float* __restrict__ in,
                             bf16* __restrict__ hp, bf16* __restrict__ lp,
                             size_t n4) {
    size_t i = (size_t)blockIdx.x * blockDim.x + threadIdx.x;
    if (i >= n4) return;
    float4 v = ((const float4*)in)[i];
    unsigned short h0,l0,h1,l1,h2,l2,h3,l3;
    split2(v.x, h0, l0); split2(v.y, h1, l1);
    split2(v.z, h2, l2); split2(v.w, h3, l3);
    ((uint2*)hp)[i] = make_uint2((uint32_t)h0 | ((uint32_t)h1 << 16),
                                 (uint32_t)h2 | ((uint32_t)h3 << 16));
    ((uint2*)lp)[i] = make_uint2((uint32_t)l0 | ((uint32_t)l1 << 16),
                                 (uint32_t)l2 | ((uint32_t)l3 << 16));
}

// ======================= tensor-core GEMM (pre-split bf16) ==================
// C = A * B, A planes [M,K], B planes [K,N]. 3 terms: AhBh + AhBl + AlBh.
// CTA 128x128, BK=32, cp.async 3 stages, 8 warps (64x32 warp tiles).

#define LDSM4(R, addr) \
    asm volatile("ldmatrix.sync.aligned.m8n8.x4.shared.b16 {%0,%1,%2,%3}, [%4];" \
                 : "=r"(R[0]), "=r"(R[1]), "=r"(R[2]), "=r"(R[3]) : "r"(addr))
#define LDSM4T(R, addr) \
    asm volatile("ldmatrix.sync.aligned.m8n8.x4.trans.shared.b16 {%0,%1,%2,%3}, [%4];" \
                 : "=r"(R[0]), "=r"(R[1]), "=r"(R[2]), "=r"(R[3]) : "r"(addr))
#define MMA_BF16(d, a, b0, b1) \
    asm volatile("mma.sync.aligned.m16n8k16.row.col.f32.bf16.bf16.f32 " \
                 "{%0,%1,%2,%3}, {%4,%5,%6,%7}, {%8,%9}, {%0,%1,%2,%3};" \
                 : "+f"(d[0]), "+f"(d[1]), "+f"(d[2]), "+f"(d[3]) \
                 : "r"(a[0]), "r"(a[1]), "r"(a[2]), "r"(a[3]), "r"(b0), "r"(b1))

__device__ __forceinline__ int swizA(int r, int c) {    // A tile 128x32 bf16
    int b = (r << 6) | (c << 1);
    return b ^ (((r >> 1) & 7) << 4);
}
__device__ __forceinline__ int swizB(int k, int n) {    // B tile 32x128 bf16
    int b = (k << 8) | (n << 1);
    return b ^ ((k & 7) << 4);
}

__device__ __forceinline__ void cp16(uint32_t dst, const void* src, int sz) {
    asm volatile("cp.async.cg.shared.global [%0], [%1], 16, %2;"
                 :: "r"(dst), "l"(src), "r"(sz));
}

// per-stage layout: Ah @0 (8KB) | Al @8192 | Bh @16384 | Bl @24576 ; stride 32768
#define GEMM_STAGES 3
#define GEMM_SMEM (GEMM_STAGES * 32768)

__device__ __forceinline__ void gemm_issue_stage(
    uint32_t stage, const bf16* __restrict__ Ah, const bf16* __restrict__ Al,
    const bf16* __restrict__ Bh, const bf16* __restrict__ Bl,
    int M, int N, int Kd, int bm, int bn, int k0, int tid) {
    int arow = tid >> 1, akc = (tid & 1) << 4;
    int avalid = ((bm + arow) < M) ? 16 : 0;
    size_t arIdx = (size_t)(avalid ? (bm + arow) : 0);
    const bf16* agh = Ah + arIdx * Kd + k0 + akc;
    const bf16* agl = Al + arIdx * Kd + k0 + akc;
    uint32_t d0 = stage + swizA(arow, akc);
    uint32_t d1 = stage + swizA(arow, akc + 8);
    cp16(d0, agh, avalid);            cp16(d1, agh + 8, avalid);
    cp16(d0 + 8192u, agl, avalid);    cp16(d1 + 8192u, agl + 8, avalid);
    int bk = tid >> 3, bnc = (tid & 7) << 4;
    const bf16* bgh = Bh + (size_t)(k0 + bk) * N + bn + bnc;
    const bf16* bgl = Bl + (size_t)(k0 + bk) * N + bn + bnc;
    uint32_t e0 = stage + 16384u + swizB(bk, bnc);
    uint32_t e1 = stage + 16384u + swizB(bk, bnc + 8);
    cp16(e0, bgh, 16);                cp16(e1, bgh + 8, 16);
    cp16(e0 + 8192u, bgl, 16);        cp16(e1 + 8192u, bgl + 8, 16);
}

__global__ void __launch_bounds__(256)
gemm_tc_kernel(const bf16* __restrict__ Ah, const bf16* __restrict__ Al,
               const bf16* __restrict__ Bh, const bf16* __restrict__ Bl,
               const float* __restrict__ bias,
               float* __restrict__ Cm,
               bf16* __restrict__ Ch, bf16* __restrict__ Cl,
               int M, int N, int Kd, int act) {
    extern __shared__ __align__(16) char sm[];
    uint32_t sb = (uint32_t)__cvta_generic_to_shared(sm);
    const int tid  = threadIdx.x;
    const int lane = tid & 31;
    const int w    = tid >> 5;
    const int wm   = w & 1;
    const int wn   = w >> 1;
    const int bm   = blockIdx.y * 128;
    const int bn   = blockIdx.x * 128;

    // ldmatrix offsets relative to stage base
    int aOff[4][2], bOff[2][2];
    {
        int ar = wm * 64 + (lane & 15);
        int ac = (lane >> 4) << 3;
        #pragma unroll
        for (int i = 0; i < 4; i++)
            #pragma unroll
            for (int s = 0; s < 2; s++)
                aOff[i][s] = swizA(ar + 16 * i, ac + 16 * s);
        int bk  = lane & 15;
        int bn0 = wn * 32 + ((lane >> 4) << 3);
        #pragma unroll
        for (int jp = 0; jp < 2; jp++)
            #pragma unroll
            for (int s = 0; s < 2; s++)
                bOff[jp][s] = 16384 + swizB(bk + 16 * s, bn0 + 16 * jp);
    }

    float acc[4][4][4];
    #pragma unroll
    for (int i = 0; i < 4; i++)
        #pragma unroll
        for (int j = 0; j < 4; j++)
            #pragma unroll
            for (int r = 0; r < 4; r++) acc[i][j][r] = 0.f;

    const int nCh = Kd >> 5;

    // prologue: stages 0..S-2
    #pragma unroll
    for (int p = 0; p < GEMM_STAGES - 1; p++) {
        gemm_issue_stage(sb + (uint32_t)p * 32768u, Ah, Al, Bh, Bl,
                         M, N, Kd, bm, bn, p << 5, tid);
        asm volatile("cp.async.commit_group;");
    }

    for (int kc = 0; kc < nCh; kc++) {
        asm volatile("cp.async.wait_group %0;" :: "n"(GEMM_STAGES - 2));
        __syncthreads();
        int pf = kc + GEMM_STAGES - 1;
        if (pf < nCh)
            gemm_issue_stage(sb + (uint32_t)(pf % GEMM_STAGES) * 32768u,
                             Ah, Al, Bh, Bl, M, N, Kd, bm, bn, pf << 5, tid);
        asm volatile("cp.async.commit_group;");

        uint32_t stage = sb + (uint32_t)(kc % GEMM_STAGES) * 32768u;
        #pragma unroll
        for (int s = 0; s < 2; s++) {
            uint32_t ah[4][4], al[4][4], bh[2][4], bl[2][4];
            #pragma unroll
            for (int i = 0; i < 4; i++) {
                LDSM4(ah[i], stage + aOff[i][s]);
                LDSM4(al[i], stage + aOff[i][s] + 8192u);
            }
            #pragma unroll
            for (int jp = 0; jp < 2; jp++) {
                LDSM4T(bh[jp], stage + bOff[jp][s]);
                LDSM4T(bl[jp], stage + bOff[jp][s] + 8192u);
            }
            #pragma unroll
            for (int i = 0; i < 4; i++) {
                #pragma unroll
                for (int j = 0; j < 4; j++) {
                    const uint32_t* bhj = &bh[j >> 1][(j & 1) * 2];
                    const uint32_t* blj = &bl[j >> 1][(j & 1) * 2];
                    MMA_BF16(acc[i][j], ah[i], bhj[0], bhj[1]);
                    MMA_BF16(acc[i][j], ah[i], blj[0], blj[1]);
                    MMA_BF16(acc[i][j], al[i], bhj[0], bhj[1]);
                }
            }
        }
    }

    // epilogue
    #pragma unroll
    for (int i = 0; i < 4; i++) {
        int r0 = bm + wm * 64 + i * 16 + (lane >> 2);
        #pragma unroll
        for (int j = 0; j < 4; j++) {
            int c0 = bn + wn * 32 + j * 8 + (lane & 3) * 2;
            float b0 = bias ? bias[c0] : 0.f;
            float b1 = bias ? bias[c0 + 1] : 0.f;
            float v0 = acc[i][j][0] + b0, v1 = acc[i][j][1] + b1;
            float v2 = acc[i][j][2] + b0, v3 = acc[i][j][3] + b1;
            if (act == 1) {
                v0 = 0.5f * v0 * (1.f + erff(v0 * 0.70710678118654752f));
                v1 = 0.5f * v1 * (1.f + erff(v1 * 0.70710678118654752f));
                v2 = 0.5f * v2 * (1.f + erff(v2 * 0.70710678118654752f));
                v3 = 0.5f * v3 * (1.f + erff(v3 * 0.70710678118654752f));
            }
            if (Ch) {
                unsigned short h0,l0,h1,l1;
                if (r0 < M) {
                    split2(v0, h0, l0); split2(v1, h1, l1);
                    *(uint32_t*)&Ch[(size_t)r0 * N + c0] = (uint32_t)h0 | ((uint32_t)h1 << 16);
                    *(uint32_t*)&Cl[(size_t)r0 * N + c0] = (uint32_t)l0 | ((uint32_t)l1 << 16);
                }
                if (r0 + 8 < M) {
                    split2(v2, h0, l0); split2(v3, h1, l1);
                    *(uint32_t*)&Ch[(size_t)(r0 + 8) * N + c0] = (uint32_t)h0 | ((uint32_t)h1 << 16);
                    *(uint32_t*)&Cl[(size_t)(r0 + 8) * N + c0] = (uint32_t)l0 | ((uint32_t)l1 << 16);
                }
            } else {
                if (r0 < M)     *(float2*)&Cm[(size_t)r0 * N + c0]       = make_float2(v0, v1);
                if (r0 + 8 < M) *(float2*)&Cm[(size_t)(r0 + 8) * N + c0] = make_float2(v2, v3);
            }
        }
    }
}

// ------------------------- LayerNorm primitives -----------------------------
__device__ __forceinline__ float2 ln_stats(const float* __restrict__ src) {
    __shared__ float sm0[8], sm1[8];
    float s = 0.f, ss = 0.f;
    for (int c = threadIdx.x; c < CDIM; c += blockDim.x) {
        float v = src[c];
        s += v; ss += v * v;
    }
    #pragma unroll
    for (int o = 16; o > 0; o >>= 1) {
        s  += __shfl_down_sync(0xffffffffu, s,  o);
        ss += __shfl_down_sync(0xffffffffu, ss, o);
    }
    int w = threadIdx.x >> 5;
    if ((threadIdx.x & 31) == 0) { sm0[w] = s; sm1[w] = ss; }
    __syncthreads();
    if (threadIdx.x == 0) {
        float a = 0.f, b2 = 0.f;
        int nw = blockDim.x >> 5;
        for (int i = 0; i < nw; i++) { a += sm0[i]; b2 += sm1[i]; }
        sm0[0] = a; sm1[0] = b2;
    }
    __syncthreads();
    float mean = sm0[0] * (1.f / CDIM);
    float var  = sm1[0] * (1.f / CDIM) - mean * mean;
    return make_float2(mean, rsqrtf(var + 1e-5f));
}

__device__ __forceinline__ void ln_row(const float* __restrict__ src,
                                       float* __restrict__ dst,
                                       const float* __restrict__ g,
                                       const float* __restrict__ bta) {
    float2 st = ln_stats(src);
    for (int c = threadIdx.x; c < CDIM; c += blockDim.x)
        dst[c] = (src[c] - st.x) * st.y * g[c] + bta[c];
}

__device__ __forceinline__ void ln_row_split(const float* __restrict__ src,
                                             bf16* __restrict__ dh, bf16* __restrict__ dl,
                                             const float* __restrict__ g,
                                             const float* __restrict__ bta) {
    float2 st = ln_stats(src);
    for (int c = threadIdx.x; c < CDIM; c += blockDim.x) {
        float v = (src[c] - st.x) * st.y * g[c] + bta[c];
        unsigned short h, l;
        split2(v, h, l);
        dh[c] = __ushort_as_bfloat16(h);
        dl[c] = __ushort_as_bfloat16(l);
    }
}

// LN over xt: writes f32 (for gather) + split planes (for qkv16 GEMM)
__global__ void ln_xt_kernel(const float* __restrict__ x, float* __restrict__ out,
                             bf16* __restrict__ oh, bf16* __restrict__ ol,
                             const float* __restrict__ g, const float* __restrict__ b) {
    int r = blockIdx.x;
    int bb = r / (KPATCH * TT);
    int off = r % (KPATCH * TT);
    const float* src = x + ((size_t)bb * LSEQ + 1 + off) * CDIM;
    float2 st = ln_stats(src);
    for (int c = threadIdx.x; c < CDIM; c += blockDim.x) {
        float v = (src[c] - st.x) * st.y * g[c] + b[c];
        out[(size_t)r * CDIM + c] = v;
        unsigned short h, l;
        split2(v, h, l);
        oh[(size_t)r * CDIM + c] = __ushort_as_bfloat16(h);
        ol[(size_t)r * CDIM + c] = __ushort_as_bfloat16(l);
    }
}

__global__ void ln_contig_split_kernel(const float* __restrict__ in,
                                       bf16* __restrict__ oh, bf16* __restrict__ ol,
                                       const float* __restrict__ g, const float* __restrict__ b,
                                       int M) {
    int r = blockIdx.x;
    if (r >= M) return;
    ln_row_split(in + (size_t)r * CDIM, oh + (size_t)r * CDIM, ol + (size_t)r * CDIM, g, b);
}

__global__ void ln_cls_kernel(const float* __restrict__ in, float* __restrict__ out,
                              const float* __restrict__ g, const float* __restrict__ b) {
    int r = blockIdx.x;
    ln_row(in + (size_t)r * LSP * CDIM, out + (size_t)r * CDIM, g, b);
}

// Build spatial sequences + LN1, emit split planes
__global__ void build_xs_ln_kernel(const float* __restrict__ x, const float* __restrict__ xtfull,
                                   const float* __restrict__ g, const float* __restrict__ bta,
                                   bf16* __restrict__ oh, bf16* __restrict__ ol) {
    int r = blockIdx.x;
    int s = r / LSP, i = r % LSP;
    int bb = s / TT, t = s % TT;
    const float* src = (i == 0)
        ? (x + (size_t)bb * LSEQ * CDIM)
        : (xtfull + ((size_t)bb * KPATCH * TT + (size_t)(i - 1) * TT + t) * CDIM);
    ln_row_split(src, oh + (size_t)r * CDIM, ol + (size_t)r * CDIM, g, bta);
}

// ------------------------- gather temporal tail (f32 -> split planes) -------
__global__ void gather_tail_kernel(const float* __restrict__ in,
                                   bf16* __restrict__ oh, bf16* __restrict__ ol, int Ts) {
    size_t idx = (size_t)blockIdx.x * blockDim.x + threadIdx.x;
    size_t tot = (size_t)BKR * Ts * CDIM;
    if (idx >= tot) return;
    int c = (int)(idx % CDIM);
    size_t row = idx / CDIM;
    int j = (int)(row / Ts), t = (int)(row % Ts);
    float v = in[((size_t)j * TT + (TT - Ts) + t) * CDIM + c];
    unsigned short h, l;
    split2(v, h, l);
    oh[idx] = __ushort_as_bfloat16(h);
    ol[idx] = __ushort_as_bfloat16(l);
}

// ------------------------- batched attention --------------------------------
__global__ void attn_scores_kernel(const float* __restrict__ qkv, float* __restrict__ S,
                                   int L, float scale) {
    int bh = blockIdx.z;
    int s = bh / NHEAD, h = bh % NHEAD;
    int qT = blockIdx.y * 16, kT = blockIdx.x * 16;
    __shared__ float qs[16][17], ks[16][17];
    float acc = 0.f;
    const float* qbase = qkv + (size_t)s * L * 3 * CDIM + (size_t)h * HDIM;
    const float* kbase = qbase + CDIM;
    for (int d0 = 0; d0 < HDIM; d0 += 16) {
        int qr = qT + threadIdx.y;
        qs[threadIdx.y][threadIdx.x] = (qr < L) ? qbase[(size_t)qr * 3 * CDIM + d0 + threadIdx.x] : 0.f;
        int kr = kT + threadIdx.y;
        ks[threadIdx.y][threadIdx.x] = (kr < L) ? kbase[(size_t)kr * 3 * CDIM + d0 + threadIdx.x] : 0.f;
        __syncthreads();
        #pragma unroll
        for (int dd = 0; dd < 16; dd++)
            acc = fmaf(qs[threadIdx.y][dd], ks[threadIdx.x][dd], acc);
        __syncthreads();
    }
    int qi = qT + threadIdx.y, ki = kT + threadIdx.x;
    if (qi < L && ki < L)
        S[(size_t)bh * L * L + (size_t)qi * L + ki] = acc * scale;
}

__global__ void softmax_kernel(float* __restrict__ S, int rows, int L) {
    int row = blockIdx.x * 8 + (threadIdx.x >> 5);
    if (row >= rows) return;
    int lane = threadIdx.x & 31;
    float* p = S + (size_t)row * L;
    float mx = -1e30f;
    for (int i = lane; i < L; i += 32) mx = fmaxf(mx, p[i]);
    #pragma unroll
    for (int o = 16; o > 0; o >>= 1) mx = fmaxf(mx, __shfl_xor_sync(0xffffffffu, mx, o));
    float sum = 0.f;
    for (int i = lane; i < L; i += 32) { float e = expf(p[i] - mx); p[i] = e; sum += e; }
    #pragma unroll
    for (int o = 16; o > 0; o >>= 1) sum += __shfl_xor_sync(0xffffffffu, sum, o);
    float inv = 1.f / sum;
    for (int i = lane; i < L; i += 32) p[i] *= inv;
}

// attn_out writes split bf16 planes directly (proj-GEMM A input)
__global__ void attn_out_kernel(const float* __restrict__ qkv, const float* __restrict__ S,
                                bf16* __restrict__ oh, bf16* __restrict__ ol, int L) {
    int bh = blockIdx.y;
    int s = bh / NHEAD, h = bh % NHEAD;
    int q = blockIdx.x * blockDim.y + threadIdx.y;
    if (q >= L) return;
    int d = threadIdx.x;
    const float* p  = S + ((size_t)bh * L + q) * L;
    const float* vb = qkv + (size_t)s * L * 3 * CDIM + 2 * CDIM + (size_t)h * HDIM + d;
    float acc = 0.f;
    for (int k = 0; k < L; k++)
        acc = fmaf(p[k], vb[(size_t)k * 3 * CDIM], acc);
    size_t o = ((size_t)s * L + q) * CDIM + (size_t)h * HDIM + d;
    unsigned short hh, ll;
    split2(acc, hh, ll);
    oh[o] = __ushort_as_bfloat16(hh);
    ol[o] = __ushort_as_bfloat16(ll);
}

// ------------------------- pointwise steps ----------------------------------
__global__ void combine_kernel(float* __restrict__ x16, const float* __restrict__ x8,
                               const float* __restrict__ x4,
                               bf16* __restrict__ oh, bf16* __restrict__ ol) {
    size_t idx = (size_t)blockIdx.x * blockDim.x + threadIdx.x;
    size_t tot = (size_t)MT * CDIM;
    if (idx >= tot) return;
    int c = (int)(idx % CDIM);
    size_t row = idx / CDIM;
    int j = (int)(row / TT), t = (int)(row % TT);
    float v = x16[idx];
    if (t >= 8) {
        float v8 = x8[((size_t)j * 8 + (t - 8)) * CDIM + c];
        if (t >= 12) v8 = 0.5f * v8 + 0.5f * x4[((size_t)j * 4 + (t - 12)) * CDIM + c];
        v = 0.5f * v + 0.5f * v8;
    }
    unsigned short h, l;
    split2(v, h, l);
    oh[idx] = __ushort_as_bfloat16(h);
    ol[idx] = __ushort_as_bfloat16(l);
}

__global__ void add_x_residual_kernel(float* __restrict__ xtfull, const float* __restrict__ x) {
    size_t idx = (size_t)blockIdx.x * blockDim.x + threadIdx.x;
    size_t tot = (size_t)MT * CDIM;
    if (idx >= tot) return;
    int c = (int)(idx % CDIM);
    size_t row = idx / CDIM;
    int bb = (int)(row / (KPATCH * TT));
    int off = (int)(row % (KPATCH * TT));
    xtfull[idx] += x[((size_t)bb * LSEQ + 1 + off) * CDIM + c];
}

__global__ void cls_attn_kernel(const float* __restrict__ clssp, float* __restrict__ out) {
    int b = blockIdx.x;
    __shared__ float dots[TT];
    __shared__ float wts[TT];
    int w = threadIdx.x >> 5, lane = threadIdx.x & 31;
    const float* base = clssp + (size_t)b * TT * CDIM;
    const float* tgt = base + (size_t)(TT - 1) * CDIM;
    for (int t = w; t < TT; t += 8) {
        float sd = 0.f;
        for (int c = lane; c < CDIM; c += 32) sd = fmaf(tgt[c], base[(size_t)t * CDIM + c], sd);
        #pragma unroll
        for (int o = 16; o > 0; o >>= 1) sd += __shfl_xor_sync(0xffffffffu, sd, o);
        if (lane == 0) dots[t] = sd;
    }
    __syncthreads();
    if (threadIdx.x == 0) {
        float mx = -1e30f;
        for (int t = 0; t < TT; t++) mx = fmaxf(mx, dots[t]);
        float s = 0.f;
        for (int t = 0; t < TT; t++) { float e = expf(dots[t] - mx); wts[t] = e; s += e; }
        float inv = 1.f / s;
        for (int t = 0; t < TT; t++) wts[t] *= inv;
    }
    __syncthreads();
    for (int c = threadIdx.x; c < CDIM; c += blockDim.x) {
        float a = 0.f;
        #pragma unroll
        for (int t = 0; t < TT; t++) a = fmaf(wts[t], base[(size_t)t * CDIM + c], a);
        out[(size_t)b * CDIM + c] = a;
    }
}

__global__ void build_xcat_kernel(const float* __restrict__ x, const float* __restrict__ xtfull,
                                  const float* __restrict__ ressp, const float* __restrict__ clsout,
                                  float* __restrict__ xcat) {
    size_t idx = (size_t)blockIdx.x * blockDim.x + threadIdx.x;
    size_t tot = (size_t)MOUT * CDIM;
    if (idx >= tot) return;
    int c = (int)(idx % CDIM);
    size_t row = idx / CDIM;
    int bb = (int)(row / LSEQ);
    int i = (int)(row % LSEQ);
    float v;
    if (i == 0) {
        v = x[idx] + clsout[(size_t)bb * CDIM + c];
    } else {
        int n = i - 1;
        int k = n / TT, t = n % TT;
        v = xtfull[((size_t)bb * KPATCH * TT + n) * CDIM + c]
          + ressp[(((size_t)(bb * TT + t)) * LSP + 1 + k) * CDIM + c];
    }
    xcat[idx] = v;
}

__global__ void final_add_kernel(const float* __restrict__ xcat, const float* __restrict__ h2,
                                 float* __restrict__ out) {
    size_t idx = (size_t)blockIdx.x * blockDim.x + threadIdx.x;
    size_t tot = (size_t)MOUT * CDIM;
    if (idx >= tot) return;
    out[idx] = xcat[idx] + h2[idx];
}

// ------------------------- host orchestration -------------------------------
static inline void gemm5(const bf16* Ah, const bf16* Al, const bf16* Bh, const bf16* Bl,
                         const float* bias, float* C, bf16* Ch, bf16* Cl,
                         int M, int N, int K, int act) {
    dim3 blk(256);
    dim3 grd(N / 128, (M + 127) / 128);
    gemm_tc_kernel<<<grd, blk, GEMM_SMEM>>>(Ah, Al, Bh, Bl, bias, C, Ch, Cl, M, N, K, act);
}

extern "C" void kernel_launch(void* const* d_in, const int* in_sizes, int n_in,
                              void* d_out, int out_size) {
    const float* x       = (const float*)d_in[0];
    const float* ln1_g   = (const float*)d_in[4];
    const float* ln1_b   = (const float*)d_in[5];
    const float* lnt_g   = (const float*)d_in[6];
    const float* lnt_b   = (const float*)d_in[7];
    const float* ln2_g   = (const float*)d_in[8];
    const float* ln2_b   = (const float*)d_in[9];
    const float* lncls_g = (const float*)d_in[10];
    const float* lncls_b = (const float*)d_in[11];
    const float* Wqkv_s  = (const float*)d_in[12];
    const float* Wproj_s = (const float*)d_in[13];
    const float* bproj_s = (const float*)d_in[14];
    const float* Wqkv4   = (const float*)d_in[15];
    const float* Wqkv8   = (const float*)d_in[16];
    const float* Wqkv16  = (const float*)d_in[17];
    const float* Wp4     = (const float*)d_in[18];
    const float* bp4     = (const float*)d_in[19];
    const float* Wp8     = (const float*)d_in[20];
    const float* bp8     = (const float*)d_in[21];
    const float* Wp16    = (const float*)d_in[22];
    const float* bp16    = (const float*)d_in[23];
    const float* Wtfc    = (const float*)d_in[24];
    const float* btfc    = (const float*)d_in[25];
    const float* Wfc1    = (const float*)d_in[26];
    const float* bfc1    = (const float*)d_in[27];
    const float* Wfc2    = (const float*)d_in[28];
    const float* bfc2    = (const float*)d_in[29];
    float* out = (float*)d_out;

    cudaFuncSetAttribute(gemm_tc_kernel,
                         cudaFuncAttributeMaxDynamicSharedMemorySize, GEMM_SMEM);

    float *xtn, *gathf, *qkv, *x16, *x8, *x4, *xtfull, *xsn, *ressp,
          *scores, *clssp, *clsout, *xcat, *h2;
    bf16 *pah, *pal, *pbh, *pbl, *h1h, *h1l, *wh, *wl;
    cudaGetSymbolAddress((void**)&xtn,    g_xtn);
    cudaGetSymbolAddress((void**)&gathf,  g_gathf);
    cudaGetSymbolAddress((void**)&qkv,    g_qkv);
    cudaGetSymbolAddress((void**)&x16,    g_x16);
    cudaGetSymbolAddress((void**)&x8,     g_x8);
    cudaGetSymbolAddress((void**)&x4,     g_x4);
    cudaGetSymbolAddress((void**)&xtfull, g_xtfull);
    cudaGetSymbolAddress((void**)&xsn,    g_xsn);
    cudaGetSymbolAddress((void**)&ressp,  g_ressp);
    cudaGetSymbolAddress((void**)&scores, g_scores);
    cudaGetSymbolAddress((void**)&clssp,  g_clssp);
    cudaGetSymbolAddress((void**)&clsout, g_clsout);
    cudaGetSymbolAddress((void**)&xcat,   g_xcat);
    cudaGetSymbolAddress((void**)&h2,     g_h2);
    cudaGetSymbolAddress((void**)&pah,    g_pah);
    cudaGetSymbolAddress((void**)&pal,    g_pal);
    cudaGetSymbolAddress((void**)&pbh,    g_pbh);
    cudaGetSymbolAddress((void**)&pbl,    g_pbl);
    cudaGetSymbolAddress((void**)&h1h,    g_h1h);
    cudaGetSymbolAddress((void**)&h1l,    g_h1l);
    cudaGetSymbolAddress((void**)&wh,     g_wh);
    cudaGetSymbolAddress((void**)&wl,     g_wl);

    const size_t EW = 256;
    #define CONV(src, dh, dl, nel) do {                                          \
        size_t n4_ = (size_t)(nel) / 4;                                          \
        convA_kernel<<<(int)((n4_ + 255) / 256), 256>>>((src), (dh), (dl), n4_); \
    } while (0)

    // 0) weight splits (elementwise, [K,N] layout preserved)
    CONV(Wqkv_s,  wh + OFF_QKV_S, wl + OFF_QKV_S, 768 * 2304);
    CONV(Wqkv4,   wh + OFF_QKV4,  wl + OFF_QKV4,  768 * 2304);
    CONV(Wqkv8,   wh + OFF_QKV8,  wl + OFF_QKV8,  768 * 2304);
    CONV(Wqkv16,  wh + OFF_QKV16, wl + OFF_QKV16, 768 * 2304);
    CONV(Wproj_s, wh + OFF_P_S,   wl + OFF_P_S,   768 * 768);
    CONV(Wp4,     wh + OFF_P4,    wl + OFF_P4,    768 * 768);
    CONV(Wp8,     wh + OFF_P8,    wl + OFF_P8,    768 * 768);
    CONV(Wp16,    wh + OFF_P16,   wl + OFF_P16,   768 * 768);
    CONV(Wtfc,    wh + OFF_TFC,   wl + OFF_TFC,   768 * 768);
    CONV(Wfc1,    wh + OFF_FC1,   wl + OFF_FC1,   768 * 3072);
    CONV(Wfc2,    wh + OFF_FC2,   wl + OFF_FC2,   3072 * 768);

    // 1) LN over temporal sequences (f32 + split planes)
    ln_xt_kernel<<<MT, 256>>>(x, xtn, pah, pal, lnt_g, lnt_b);

    // ---- temporal MHA helper expansion ----
    #define RUN_MHA(AH, AL, QKVOFF, POFF, BP, OUTF, NSEQ, L) do {                \
        int M_ = (NSEQ) * (L);                                                   \
        gemm5((AH), (AL), wh + (QKVOFF), wl + (QKVOFF), nullptr, qkv,            \
              nullptr, nullptr, M_, 3 * CDIM, CDIM, 0);                          \
        { dim3 blk_(16, 16);                                                     \
          dim3 grd_(((L) + 15) / 16, ((L) + 15) / 16, (NSEQ) * NHEAD);           \
          attn_scores_kernel<<<grd_, blk_>>>(qkv, scores, (L), ATT_SCALE); }     \
        { int rows_ = (NSEQ) * NHEAD * (L);                                      \
          softmax_kernel<<<(rows_ + 7) / 8, 256>>>(scores, rows_, (L)); }        \
        { dim3 blk_(HDIM, 4);                                                    \
          dim3 grd_(((L) + 3) / 4, (NSEQ) * NHEAD);                              \
          attn_out_kernel<<<grd_, blk_>>>(qkv, scores, pbh, pbl, (L)); }         \
        gemm5(pbh, pbl, wh + (POFF), wl + (POFF), (BP), (OUTF),                  \
              nullptr, nullptr, M_, CDIM, CDIM, 0);                              \
    } while (0)

    // 2) Temporal MHAs
    RUN_MHA(pah, pal, OFF_QKV16, OFF_P16, bp16, x16, BKR, 16);

    {
        size_t tot = (size_t)BKR * 8 * CDIM;
        gather_tail_kernel<<<(int)((tot + EW - 1) / EW), (int)EW>>>(xtn, pah, pal, 8);
    }
    RUN_MHA(pah, pal, OFF_QKV8, OFF_P8, bp8, x8, BKR, 8);

    {
        size_t tot = (size_t)BKR * 4 * CDIM;
        gather_tail_kernel<<<(int)((tot + EW - 1) / EW), (int)EW>>>(xtn, pah, pal, 4);
    }
    RUN_MHA(pah, pal, OFF_QKV4, OFF_P4, bp4, x4, BKR, 4);

    // 3) Blend scales -> split planes for Wtfc
    {
        size_t tot = (size_t)MT * CDIM;
        combine_kernel<<<(int)((tot + EW - 1) / EW), (int)EW>>>(x16, x8, x4, pah, pal);
    }

    // 4) xt_full = x16 @ Wtfc + btfc + x[:,1:,:]
    gemm5(pah, pal, wh + OFF_TFC, wl + OFF_TFC, btfc, xtfull, nullptr, nullptr,
          MT, CDIM, CDIM, 0);
    {
        size_t tot = (size_t)MT * CDIM;
        add_x_residual_kernel<<<(int)((tot + EW - 1) / EW), (int)EW>>>(xtfull, x);
    }

    // 5) Spatial MHA
    build_xs_ln_kernel<<<MSP, 256>>>(x, xtfull, ln1_g, ln1_b, pah, pal);
    RUN_MHA(pah, pal, OFF_QKV_S, OFF_P_S, bproj_s, ressp, SSP, LSP);

    // 6) CLS path
    ln_cls_kernel<<<SSP, 256>>>(ressp, clssp, lncls_g, lncls_b);
    cls_attn_kernel<<<BBATCH, 256>>>(clssp, clsout);

    // 7) x_cat
    {
        size_t tot = (size_t)MOUT * CDIM;
        build_xcat_kernel<<<(int)((tot + EW - 1) / EW), (int)EW>>>(x, xtfull, ressp, clsout, xcat);
    }

    // 8) MLP: LN2 (split) -> fc1 (GELU, split out) -> fc2 -> residual
    ln_contig_split_kernel<<<MOUT, 256>>>(xcat, pah, pal, ln2_g, ln2_b, MOUT);
    gemm5(pah, pal, wh + OFF_FC1, wl + OFF_FC1, bfc1, nullptr, h1h, h1l,
          MOUT, HID, CDIM, 1);
    gemm5(h1h, h1l, wh + OFF_FC2, wl + OFF_FC2, bfc2, h2, nullptr, nullptr,
          MOUT, CDIM, HID, 0);
    {
        size_t tot = (size_t)MOUT * CDIM;
        final_add_kernel<<<(int)((tot + EW - 1) / EW), (int)EW>>>(xcat, h2, out);
    }
    #undef RUN_MHA
    #undef CONV
}

// round 5
// speedup vs baseline: 2.8365x; 1.1514x over previous
#include <cuda_runtime.h>
#include <cuda_fp16.h>
#include <math.h>
#include <stddef.h>
#include <stdint.h>

#define CDIM 768
#define NHEAD 12
#define HDIM 64
#define BBATCH 4
#define TT 16
#define KPATCH 196
#define LSEQ 3137           // 1 + K*T
#define BKR 784             // B*K
#define MT 12544            // BKR*TT
#define SSP 64              // B*T
#define LSP 197             // 1 + K
#define MSP 12608           // SSP*LSP
#define MOUT 12548          // B*LSEQ
#define HID 3072
#define ATT_SCALE 0.125f    // (64)^-0.5

typedef __half h16;

// ------------------------- device scratch (static, allocation-free) ---------
__device__ float g_xtn   [(size_t)MT   * CDIM];
__device__ float g_qkv   [(size_t)MSP  * 3 * CDIM];
__device__ float g_x16   [(size_t)MT   * CDIM];
__device__ float g_x8    [(size_t)BKR * 8 * CDIM];
__device__ float g_x4    [(size_t)BKR * 4 * CDIM];
__device__ float g_xtfull[(size_t)MT   * CDIM];
__device__ float g_ressp [(size_t)MSP  * CDIM];
__device__ float g_scores[(size_t)SSP * NHEAD * LSP * LSP];
__device__ float g_clssp [(size_t)SSP  * CDIM];
__device__ float g_clsout[(size_t)BBATCH * CDIM];
__device__ float g_xcat  [(size_t)MOUT * CDIM];
__device__ float g_h2    [(size_t)MOUT * CDIM];

// activation planes (fp16 hi/lo)
#define PA_ELEMS ((size_t)MSP * CDIM)
__device__ h16 g_pah[PA_ELEMS];
__device__ h16 g_pal[PA_ELEMS];
__device__ h16 g_pbh[PA_ELEMS];
__device__ h16 g_pbl[PA_ELEMS];
__device__ h16 g_h1h[(size_t)MOUT * HID];
__device__ h16 g_h1l[(size_t)MOUT * HID];

// weight plane (fp16 single), [K,N] row-major, same layout as f32 source
#define WPOOL 14745600
__device__ h16 g_wh[(size_t)WPOOL];
#define OFF_QKV_S   0u
#define OFF_QKV4    1769472u
#define OFF_QKV8    3538944u
#define OFF_QKV16   5308416u
#define OFF_P_S     7077888u
#define OFF_P4      7667712u
#define OFF_P8      8257536u
#define OFF_P16     8847360u
#define OFF_TFC     9437184u
#define OFF_FC1    10027008u
#define OFF_FC2    12386304u

// ------------------------- split helpers ------------------------------------
__device__ __forceinline__ void split2(float v, unsigned short& h, unsigned short& l) {
    h16 hh = __float2half_rn(v);
    h16 ll = __float2half_rn(v - __half2float(hh));
    h = __half_as_ushort(hh);
    l = __half_as_ushort(ll);
}

// weights: f32 -> fp16 single plane (vectorized)
__global__ void convW_kernel(const float* __restrict__ in, h16* __restrict__ hp, size_t n4) {
    size_t i = (size_t)blockIdx.x * blockDim.x + threadIdx.x;
    if (i >= n4) return;
    float4 v = ((const float4*)in)[i];
    unsigned short h0 = __half_as_ushort(__float2half_rn(v.x));
    unsigned short h1 = __half_as_ushort(__float2half_rn(v.y));
    unsigned short h2 = __half_as_ushort(__float2half_rn(v.z));
    unsigned short h3 = __half_as_ushort(__float2half_rn(v.w));
    ((uint2*)hp)[i] = make_uint2((uint32_t)h0 | ((uint32_t)h1 << 16),
                                 (uint32_t)h2 | ((uint32_t)h3 << 16));
}

// ======================= tensor-core GEMM (fp16, 2-term A split) ============
// C = (Ah+Al) * Bh, fp32 accumulate. CTA 128x128, BK=32, cp.async 3 stages.

#define LDSM4(R, addr) \
    asm volatile("ldmatrix.sync.aligned.m8n8.x4.shared.b16 {%0,%1,%2,%3}, [%4];" \
                 : "=r"(R[0]), "=r"(R[1]), "=r"(R[2]), "=r"(R[3]) : "r"(addr))
#define LDSM4T(R, addr) \
    asm volatile("ldmatrix.sync.aligned.m8n8.x4.trans.shared.b16 {%0,%1,%2,%3}, [%4];" \
                 : "=r"(R[0]), "=r"(R[1]), "=r"(R[2]), "=r"(R[3]) : "r"(addr))
#define MMA_F16(d, a, b0, b1) \
    asm volatile("mma.sync.aligned.m16n8k16.row.col.f32.f16.f16.f32 " \
                 "{%0,%1,%2,%3}, {%4,%5,%6,%7}, {%8,%9}, {%0,%1,%2,%3};" \
                 : "+f"(d[0]), "+f"(d[1]), "+f"(d[2]), "+f"(d[3]) \
                 : "r"(a[0]), "r"(a[1]), "r"(a[2]), "r"(a[3]), "r"(b0), "r"(b1))

__device__ __forceinline__ int swizA(int r, int c) {    // A tile 128x32 fp16
    int b = (r << 6) | (c << 1);
    return b ^ (((r >> 1) & 7) << 4);
}
__device__ __forceinline__ int swizB(int k, int n) {    // B tile 32x128 fp16
    int b = (k << 8) | (n << 1);
    return b ^ ((k & 7) << 4);
}

__device__ __forceinline__ void cp16(uint32_t dst, const void* src, int sz) {
    asm volatile("cp.async.cg.shared.global [%0], [%1], 16, %2;"
                 :: "r"(dst), "l"(src), "r"(sz));
}

// per-stage: Ah @0 (8KB) | Al @8192 | Bh @16384 ; stride 24576
#define GEMM_STAGES 3
#define STAGE_BYTES 24576u
#define GEMM_SMEM (GEMM_STAGES * 24576)

__device__ __forceinline__ void gemm_issue_stage(
    uint32_t stage, const h16* __restrict__ Ah, const h16* __restrict__ Al,
    const h16* __restrict__ Bh,
    int M, int N, int Kd, int bm, int bn, int k0, int tid) {
    int arow = tid >> 1, akc = (tid & 1) << 4;
    int avalid = ((bm + arow) < M) ? 16 : 0;
    size_t arIdx = (size_t)(avalid ? (bm + arow) : 0);
    const h16* agh = Ah + arIdx * Kd + k0 + akc;
    const h16* agl = Al + arIdx * Kd + k0 + akc;
    uint32_t d0 = stage + swizA(arow, akc);
    uint32_t d1 = stage + swizA(arow, akc + 8);
    cp16(d0, agh, avalid);            cp16(d1, agh + 8, avalid);
    cp16(d0 + 8192u, agl, avalid);    cp16(d1 + 8192u, agl + 8, avalid);
    int bk = tid >> 3, bnc = (tid & 7) << 4;
    const h16* bgh = Bh + (size_t)(k0 + bk) * N + bn + bnc;
    uint32_t e0 = stage + 16384u + swizB(bk, bnc);
    uint32_t e1 = stage + 16384u + swizB(bk, bnc + 8);
    cp16(e0, bgh, 16);                cp16(e1, bgh + 8, 16);
}

__global__ void __launch_bounds__(256)
gemm_tc_kernel(const h16* __restrict__ Ah, const h16* __restrict__ Al,
               const h16* __restrict__ Bh,
               const float* __restrict__ bias,
               float* __restrict__ Cm,
               h16* __restrict__ Ch, h16* __restrict__ Cl,
               int M, int N, int Kd, int act) {
    extern __shared__ __align__(16) char sm[];
    uint32_t sb = (uint32_t)__cvta_generic_to_shared(sm);
    const int tid  = threadIdx.x;
    const int lane = tid & 31;
    const int w    = tid >> 5;
    const int wm   = w & 1;
    const int wn   = w >> 1;
    const int bm   = blockIdx.y * 128;
    const int bn   = blockIdx.x * 128;

    int aOff[4][2], bOff[2][2];
    {
        int ar = wm * 64 + (lane & 15);
        int ac = (lane >> 4) << 3;
        #pragma unroll
        for (int i = 0; i < 4; i++)
            #pragma unroll
            for (int s = 0; s < 2; s++)
                aOff[i][s] = swizA(ar + 16 * i, ac + 16 * s);
        int bk  = lane & 15;
        int bn0 = wn * 32 + ((lane >> 4) << 3);
        #pragma unroll
        for (int jp = 0; jp < 2; jp++)
            #pragma unroll
            for (int s = 0; s < 2; s++)
                bOff[jp][s] = 16384 + swizB(bk + 16 * s, bn0 + 16 * jp);
    }

    float acc[4][4][4];
    #pragma unroll
    for (int i = 0; i < 4; i++)
        #pragma unroll
        for (int j = 0; j < 4; j++)
            #pragma unroll
            for (int r = 0; r < 4; r++) acc[i][j][r] = 0.f;

    const int nCh = Kd >> 5;

    #pragma unroll
    for (int p = 0; p < GEMM_STAGES - 1; p++) {
        gemm_issue_stage(sb + (uint32_t)p * STAGE_BYTES, Ah, Al, Bh,
                         M, N, Kd, bm, bn, p << 5, tid);
        asm volatile("cp.async.commit_group;");
    }

    for (int kc = 0; kc < nCh; kc++) {
        asm volatile("cp.async.wait_group %0;" :: "n"(GEMM_STAGES - 2));
        __syncthreads();
        int pf = kc + GEMM_STAGES - 1;
        if (pf < nCh)
            gemm_issue_stage(sb + (uint32_t)(pf % GEMM_STAGES) * STAGE_BYTES,
                             Ah, Al, Bh, M, N, Kd, bm, bn, pf << 5, tid);
        asm volatile("cp.async.commit_group;");

        uint32_t stage = sb + (uint32_t)(kc % GEMM_STAGES) * STAGE_BYTES;
        #pragma unroll
        for (int s = 0; s < 2; s++) {
            uint32_t ah[4][4], al[4][4], bh[2][4];
            #pragma unroll
            for (int i = 0; i < 4; i++) {
                LDSM4(ah[i], stage + aOff[i][s]);
                LDSM4(al[i], stage + aOff[i][s] + 8192u);
            }
            #pragma unroll
            for (int jp = 0; jp < 2; jp++)
                LDSM4T(bh[jp], stage + bOff[jp][s]);
            #pragma unroll
            for (int i = 0; i < 4; i++) {
                #pragma unroll
                for (int j = 0; j < 4; j++) {
                    const uint32_t* bhj = &bh[j >> 1][(j & 1) * 2];
                    MMA_F16(acc[i][j], ah[i], bhj[0], bhj[1]);
                    MMA_F16(acc[i][j], al[i], bhj[0], bhj[1]);
                }
            }
        }
    }

    // epilogue
    #pragma unroll
    for (int i = 0; i < 4; i++) {
        int r0 = bm + wm * 64 + i * 16 + (lane >> 2);
        #pragma unroll
        for (int j = 0; j < 4; j++) {
            int c0 = bn + wn * 32 + j * 8 + (lane & 3) * 2;
            float b0 = bias ? bias[c0] : 0.f;
            float b1 = bias ? bias[c0 + 1] : 0.f;
            float v0 = acc[i][j][0] + b0, v1 = acc[i][j][1] + b1;
            float v2 = acc[i][j][2] + b0, v3 = acc[i][j][3] + b1;
            if (act == 1) {
                v0 = 0.5f * v0 * (1.f + erff(v0 * 0.70710678118654752f));
                v1 = 0.5f * v1 * (1.f + erff(v1 * 0.70710678118654752f));
                v2 = 0.5f * v2 * (1.f + erff(v2 * 0.70710678118654752f));
                v3 = 0.5f * v3 * (1.f + erff(v3 * 0.70710678118654752f));
            }
            if (Ch) {
                unsigned short h0,l0,h1,l1;
                if (r0 < M) {
                    split2(v0, h0, l0); split2(v1, h1, l1);
                    *(uint32_t*)&Ch[(size_t)r0 * N + c0] = (uint32_t)h0 | ((uint32_t)h1 << 16);
                    *(uint32_t*)&Cl[(size_t)r0 * N + c0] = (uint32_t)l0 | ((uint32_t)l1 << 16);
                }
                if (r0 + 8 < M) {
                    split2(v2, h0, l0); split2(v3, h1, l1);
                    *(uint32_t*)&Ch[(size_t)(r0 + 8) * N + c0] = (uint32_t)h0 | ((uint32_t)h1 << 16);
                    *(uint32_t*)&Cl[(size_t)(r0 + 8) * N + c0] = (uint32_t)l0 | ((uint32_t)l1 << 16);
                }
            } else {
                if (r0 < M)     *(float2*)&Cm[(size_t)r0 * N + c0]       = make_float2(v0, v1);
                if (r0 + 8 < M) *(float2*)&Cm[(size_t)(r0 + 8) * N + c0] = make_float2(v2, v3);
            }
        }
    }
}

// ------------------------- LayerNorm primitives -----------------------------
__device__ __forceinline__ float2 ln_stats(const float* __restrict__ src) {
    __shared__ float sm0[8], sm1[8];
    float s = 0.f, ss = 0.f;
    for (int c = threadIdx.x; c < CDIM; c += blockDim.x) {
        float v = src[c];
        s += v; ss += v * v;
    }
    #pragma unroll
    for (int o = 16; o > 0; o >>= 1) {
        s  += __shfl_down_sync(0xffffffffu, s,  o);
        ss += __shfl_down_sync(0xffffffffu, ss, o);
    }
    int w = threadIdx.x >> 5;
    if ((threadIdx.x & 31) == 0) { sm0[w] = s; sm1[w] = ss; }
    __syncthreads();
    if (threadIdx.x == 0) {
        float a = 0.f, b2 = 0.f;
        int nw = blockDim.x >> 5;
        for (int i = 0; i < nw; i++) { a += sm0[i]; b2 += sm1[i]; }
        sm0[0] = a; sm1[0] = b2;
    }
    __syncthreads();
    float mean = sm0[0] * (1.f / CDIM);
    float var  = sm1[0] * (1.f / CDIM) - mean * mean;
    return make_float2(mean, rsqrtf(var + 1e-5f));
}

__device__ __forceinline__ void ln_row(const float* __restrict__ src,
                                       float* __restrict__ dst,
                                       const float* __restrict__ g,
                                       const float* __restrict__ bta) {
    float2 st = ln_stats(src);
    for (int c = threadIdx.x; c < CDIM; c += blockDim.x)
        dst[c] = (src[c] - st.x) * st.y * g[c] + bta[c];
}

__device__ __forceinline__ void ln_row_split(const float* __restrict__ src,
                                             h16* __restrict__ dh, h16* __restrict__ dl,
                                             const float* __restrict__ g,
                                             const float* __restrict__ bta) {
    float2 st = ln_stats(src);
    for (int c = threadIdx.x; c < CDIM; c += blockDim.x) {
        float v = (src[c] - st.x) * st.y * g[c] + bta[c];
        unsigned short h, l;
        split2(v, h, l);
        dh[c] = __ushort_as_half(h);
        dl[c] = __ushort_as_half(l);
    }
}

// LN over xt: writes f32 (for gather) + split planes (for qkv16 GEMM)
__global__ void ln_xt_kernel(const float* __restrict__ x, float* __restrict__ out,
                             h16* __restrict__ oh, h16* __restrict__ ol,
                             const float* __restrict__ g, const float* __restrict__ b) {
    int r = blockIdx.x;
    int bb = r / (KPATCH * TT);
    int off = r % (KPATCH * TT);
    const float* src = x + ((size_t)bb * LSEQ + 1 + off) * CDIM;
    float2 st = ln_stats(src);
    for (int c = threadIdx.x; c < CDIM; c += blockDim.x) {
        float v = (src[c] - st.x) * st.y * g[c] + b[c];
        out[(size_t)r * CDIM + c] = v;
        unsigned short h, l;
        split2(v, h, l);
        oh[(size_t)r * CDIM + c] = __ushort_as_half(h);
        ol[(size_t)r * CDIM + c] = __ushort_as_half(l);
    }
}

__global__ void ln_contig_split_kernel(const float* __restrict__ in,
                                       h16* __restrict__ oh, h16* __restrict__ ol,
                                       const float* __restrict__ g, const float* __restrict__ b,
                                       int M) {
    int r = blockIdx.x;
    if (r >= M) return;
    ln_row_split(in + (size_t)r * CDIM, oh + (size_t)r * CDIM, ol + (size_t)r * CDIM, g, b);
}

__global__ void ln_cls_kernel(const float* __restrict__ in, float* __restrict__ out,
                              const float* __restrict__ g, const float* __restrict__ b) {
    int r = blockIdx.x;
    ln_row(in + (size_t)r * LSP * CDIM, out + (size_t)r * CDIM, g, b);
}

__global__ void build_xs_ln_kernel(const float* __restrict__ x, const float* __restrict__ xtfull,
                                   const float* __restrict__ g, const float* __restrict__ bta,
                                   h16* __restrict__ oh, h16* __restrict__ ol) {
    int r = blockIdx.x;
    int s = r / LSP, i = r % LSP;
    int bb = s / TT, t = s % TT;
    const float* src = (i == 0)
        ? (x + (size_t)bb * LSEQ * CDIM)
        : (xtfull + ((size_t)bb * KPATCH * TT + (size_t)(i - 1) * TT + t) * CDIM);
    ln_row_split(src, oh + (size_t)r * CDIM, ol + (size_t)r * CDIM, g, bta);
}

// ------------------------- gather temporal tail (f32 -> split planes) -------
__global__ void gather_tail_kernel(const float* __restrict__ in,
                                   h16* __restrict__ oh, h16* __restrict__ ol, int Ts) {
    size_t idx = (size_t)blockIdx.x * blockDim.x + threadIdx.x;
    size_t tot = (size_t)BKR * Ts * CDIM;
    if (idx >= tot) return;
    int c = (int)(idx % CDIM);
    size_t row = idx / CDIM;
    int j = (int)(row / Ts), t = (int)(row % Ts);
    float v = in[((size_t)j * TT + (TT - Ts) + t) * CDIM + c];
    unsigned short h, l;
    split2(v, h, l);
    oh[idx] = __ushort_as_half(h);
    ol[idx] = __ushort_as_half(l);
}

// ------------------------- batched attention --------------------------------
__global__ void attn_scores_kernel(const float* __restrict__ qkv, float* __restrict__ S,
                                   int L, float scale) {
    int bh = blockIdx.z;
    int s = bh / NHEAD, h = bh % NHEAD;
    int qT = blockIdx.y * 16, kT = blockIdx.x * 16;
    __shared__ float qs[16][17], ks[16][17];
    float acc = 0.f;
    const float* qbase = qkv + (size_t)s * L * 3 * CDIM + (size_t)h * HDIM;
    const float* kbase = qbase + CDIM;
    for (int d0 = 0; d0 < HDIM; d0 += 16) {
        int qr = qT + threadIdx.y;
        qs[threadIdx.y][threadIdx.x] = (qr < L) ? qbase[(size_t)qr * 3 * CDIM + d0 + threadIdx.x] : 0.f;
        int kr = kT + threadIdx.y;
        ks[threadIdx.y][threadIdx.x] = (kr < L) ? kbase[(size_t)kr * 3 * CDIM + d0 + threadIdx.x] : 0.f;
        __syncthreads();
        #pragma unroll
        for (int dd = 0; dd < 16; dd++)
            acc = fmaf(qs[threadIdx.y][dd], ks[threadIdx.x][dd], acc);
        __syncthreads();
    }
    int qi = qT + threadIdx.y, ki = kT + threadIdx.x;
    if (qi < L && ki < L)
        S[(size_t)bh * L * L + (size_t)qi * L + ki] = acc * scale;
}

__global__ void softmax_kernel(float* __restrict__ S, int rows, int L) {
    int row = blockIdx.x * 8 + (threadIdx.x >> 5);
    if (row >= rows) return;
    int lane = threadIdx.x & 31;
    float* p = S + (size_t)row * L;
    float mx = -1e30f;
    for (int i = lane; i < L; i += 32) mx = fmaxf(mx, p[i]);
    #pragma unroll
    for (int o = 16; o > 0; o >>= 1) mx = fmaxf(mx, __shfl_xor_sync(0xffffffffu, mx, o));
    float sum = 0.f;
    for (int i = lane; i < L; i += 32) { float e = expf(p[i] - mx); p[i] = e; sum += e; }
    #pragma unroll
    for (int o = 16; o > 0; o >>= 1) sum += __shfl_xor_sync(0xffffffffu, sum, o);
    float inv = 1.f / sum;
    for (int i = lane; i < L; i += 32) p[i] *= inv;
}

// attn_out writes split fp16 planes directly (proj-GEMM A input)
__global__ void attn_out_kernel(const float* __restrict__ qkv, const float* __restrict__ S,
                                h16* __restrict__ oh, h16* __restrict__ ol, int L) {
    int bh = blockIdx.y;
    int s = bh / NHEAD, h = bh % NHEAD;
    int q = blockIdx.x * blockDim.y + threadIdx.y;
    if (q >= L) return;
    int d = threadIdx.x;
    const float* p  = S + ((size_t)bh * L + q) * L;
    const float* vb = qkv + (size_t)s * L * 3 * CDIM + 2 * CDIM + (size_t)h * HDIM + d;
    float acc = 0.f;
    for (int k = 0; k < L; k++)
        acc = fmaf(p[k], vb[(size_t)k * 3 * CDIM], acc);
    size_t o = ((size_t)s * L + q) * CDIM + (size_t)h * HDIM + d;
    unsigned short hh, ll;
    split2(acc, hh, ll);
    oh[o] = __ushort_as_half(hh);
    ol[o] = __ushort_as_half(ll);
}

// ------------------------- pointwise steps ----------------------------------
__global__ void combine_kernel(float* __restrict__ x16, const float* __restrict__ x8,
                               const float* __restrict__ x4,
                               h16* __restrict__ oh, h16* __restrict__ ol) {
    size_t idx = (size_t)blockIdx.x * blockDim.x + threadIdx.x;
    size_t tot = (size_t)MT * CDIM;
    if (idx >= tot) return;
    int c = (int)(idx % CDIM);
    size_t row = idx / CDIM;
    int j = (int)(row / TT), t = (int)(row % TT);
    float v = x16[idx];
    if (t >= 8) {
        float v8 = x8[((size_t)j * 8 + (t - 8)) * CDIM + c];
        if (t >= 12) v8 = 0.5f * v8 + 0.5f * x4[((size_t)j * 4 + (t - 12)) * CDIM + c];
        v = 0.5f * v + 0.5f * v8;
    }
    unsigned short h, l;
    split2(v, h, l);
    oh[idx] = __ushort_as_half(h);
    ol[idx] = __ushort_as_half(l);
}

__global__ void add_x_residual_kernel(float* __restrict__ xtfull, const float* __restrict__ x) {
    size_t idx = (size_t)blockIdx.x * blockDim.x + threadIdx.x;
    size_t tot = (size_t)MT * CDIM;
    if (idx >= tot) return;
    int c = (int)(idx % CDIM);
    size_t row = idx / CDIM;
    int bb = (int)(row / (KPATCH * TT));
    int off = (int)(row % (KPATCH * TT));
    xtfull[idx] += x[((size_t)bb * LSEQ + 1 + off) * CDIM + c];
}

__global__ void cls_attn_kernel(const float* __restrict__ clssp, float* __restrict__ out) {
    int b = blockIdx.x;
    __shared__ float dots[TT];
    __shared__ float wts[TT];
    int w = threadIdx.x >> 5, lane = threadIdx.x & 31;
    const float* base = clssp + (size_t)b * TT * CDIM;
    const float* tgt = base + (size_t)(TT - 1) * CDIM;
    for (int t = w; t < TT; t += 8) {
        float sd = 0.f;
        for (int c = lane; c < CDIM; c += 32) sd = fmaf(tgt[c], base[(size_t)t * CDIM + c], sd);
        #pragma unroll
        for (int o = 16; o > 0; o >>= 1) sd += __shfl_xor_sync(0xffffffffu, sd, o);
        if (lane == 0) dots[t] = sd;
    }
    __syncthreads();
    if (threadIdx.x == 0) {
        float mx = -1e30f;
        for (int t = 0; t < TT; t++) mx = fmaxf(mx, dots[t]);
        float s = 0.f;
        for (int t = 0; t < TT; t++) { float e = expf(dots[t] - mx); wts[t] = e; s += e; }
        float inv = 1.f / s;
        for (int t = 0; t < TT; t++) wts[t] *= inv;
    }
    __syncthreads();
    for (int c = threadIdx.x; c < CDIM; c += blockDim.x) {
        float a = 0.f;
        #pragma unroll
        for (int t = 0; t < TT; t++) a = fmaf(wts[t], base[(size_t)t * CDIM + c], a);
        out[(size_t)b * CDIM + c] = a;
    }
}

__global__ void build_xcat_kernel(const float* __restrict__ x, const float* __restrict__ xtfull,
                                  const float* __restrict__ ressp, const float* __restrict__ clsout,
                                  float* __restrict__ xcat) {
    size_t idx = (size_t)blockIdx.x * blockDim.x + threadIdx.x;
    size_t tot = (size_t)MOUT * CDIM;
    if (idx >= tot) return;
    int c = (int)(idx % CDIM);
    size_t row = idx / CDIM;
    int bb = (int)(row / LSEQ);
    int i = (int)(row % LSEQ);
    float v;
    if (i == 0) {
        v = x[idx] + clsout[(size_t)bb * CDIM + c];
    } else {
        int n = i - 1;
        int k = n / TT, t = n % TT;
        v = xtfull[((size_t)bb * KPATCH * TT + n) * CDIM + c]
          + ressp[(((size_t)(bb * TT + t)) * LSP + 1 + k) * CDIM + c];
    }
    xcat[idx] = v;
}

__global__ void final_add_kernel(const float* __restrict__ xcat, const float* __restrict__ h2,
                                 float* __restrict__ out) {
    size_t idx = (size_t)blockIdx.x * blockDim.x + threadIdx.x;
    size_t tot = (size_t)MOUT * CDIM;
    if (idx >= tot) return;
    out[idx] = xcat[idx] + h2[idx];
}

// ------------------------- host orchestration -------------------------------
static inline void gemm5(const h16* Ah, const h16* Al, const h16* Bh,
                         const float* bias, float* C, h16* Ch, h16* Cl,
                         int M, int N, int K, int act) {
    dim3 blk(256);
    dim3 grd(N / 128, (M + 127) / 128);
    gemm_tc_kernel<<<grd, blk, GEMM_SMEM>>>(Ah, Al, Bh, bias, C, Ch, Cl, M, N, K, act);
}

extern "C" void kernel_launch(void* const* d_in, const int* in_sizes, int n_in,
                              void* d_out, int out_size) {
    const float* x       = (const float*)d_in[0];
    const float* ln1_g   = (const float*)d_in[4];
    const float* ln1_b   = (const float*)d_in[5];
    const float* lnt_g   = (const float*)d_in[6];
    const float* lnt_b   = (const float*)d_in[7];
    const float* ln2_g   = (const float*)d_in[8];
    const float* ln2_b   = (const float*)d_in[9];
    const float* lncls_g = (const float*)d_in[10];
    const float* lncls_b = (const float*)d_in[11];
    const float* Wqkv_s  = (const float*)d_in[12];
    const float* Wproj_s = (const float*)d_in[13];
    const float* bproj_s = (const float*)d_in[14];
    const float* Wqkv4   = (const float*)d_in[15];
    const float* Wqkv8   = (const float*)d_in[16];
    const float* Wqkv16  = (const float*)d_in[17];
    const float* Wp4     = (const float*)d_in[18];
    const float* bp4     = (const float*)d_in[19];
    const float* Wp8     = (const float*)d_in[20];
    const float* bp8     = (const float*)d_in[21];
    const float* Wp16    = (const float*)d_in[22];
    const float* bp16    = (const float*)d_in[23];
    const float* Wtfc    = (const float*)d_in[24];
    const float* btfc    = (const float*)d_in[25];
    const float* Wfc1    = (const float*)d_in[26];
    const float* bfc1    = (const float*)d_in[27];
    const float* Wfc2    = (const float*)d_in[28];
    const float* bfc2    = (const float*)d_in[29];
    float* out = (float*)d_out;

    cudaFuncSetAttribute(gemm_tc_kernel,
                         cudaFuncAttributeMaxDynamicSharedMemorySize, GEMM_SMEM);

    float *xtn, *qkv, *x16, *x8, *x4, *xtfull, *ressp,
          *scores, *clssp, *clsout, *xcat, *h2;
    h16 *pah, *pal, *pbh, *pbl, *h1h, *h1l, *wh;
    cudaGetSymbolAddress((void**)&xtn,    g_xtn);
    cudaGetSymbolAddress((void**)&qkv,    g_qkv);
    cudaGetSymbolAddress((void**)&x16,    g_x16);
    cudaGetSymbolAddress((void**)&x8,     g_x8);
    cudaGetSymbolAddress((void**)&x4,     g_x4);
    cudaGetSymbolAddress((void**)&xtfull, g_xtfull);
    cudaGetSymbolAddress((void**)&ressp,  g_ressp);
    cudaGetSymbolAddress((void**)&scores, g_scores);
    cudaGetSymbolAddress((void**)&clssp,  g_clssp);
    cudaGetSymbolAddress((void**)&clsout, g_clsout);
    cudaGetSymbolAddress((void**)&xcat,   g_xcat);
    cudaGetSymbolAddress((void**)&h2,     g_h2);
    cudaGetSymbolAddress((void**)&pah,    g_pah);
    cudaGetSymbolAddress((void**)&pal,    g_pal);
    cudaGetSymbolAddress((void**)&pbh,    g_pbh);
    cudaGetSymbolAddress((void**)&pbl,    g_pbl);
    cudaGetSymbolAddress((void**)&h1h,    g_h1h);
    cudaGetSymbolAddress((void**)&h1l,    g_h1l);
    cudaGetSymbolAddress((void**)&wh,     g_wh);

    const size_t EW = 256;
    #define CONVW(src, dh, nel) do {                                             \
        size_t n4_ = (size_t)(nel) / 4;                                          \
        convW_kernel<<<(int)((n4_ + 255) / 256), 256>>>((src), (dh), n4_);       \
    } while (0)

    // 0) weight fp16 conversion ([K,N] layout preserved)
    CONVW(Wqkv_s,  wh + OFF_QKV_S, 768 * 2304);
    CONVW(Wqkv4,   wh + OFF_QKV4,  768 * 2304);
    CONVW(Wqkv8,   wh + OFF_QKV8,  768 * 2304);
    CONVW(Wqkv16,  wh + OFF_QKV16, 768 * 2304);
    CONVW(Wproj_s, wh + OFF_P_S,   768 * 768);
    CONVW(Wp4,     wh + OFF_P4,    768 * 768);
    CONVW(Wp8,     wh + OFF_P8,    768 * 768);
    CONVW(Wp16,    wh + OFF_P16,   768 * 768);
    CONVW(Wtfc,    wh + OFF_TFC,   768 * 768);
    CONVW(Wfc1,    wh + OFF_FC1,   768 * 3072);
    CONVW(Wfc2,    wh + OFF_FC2,   3072 * 768);

    // 1) LN over temporal sequences (f32 + split planes)
    ln_xt_kernel<<<MT, 256>>>(x, xtn, pah, pal, lnt_g, lnt_b);

    #define RUN_MHA(AH, AL, QKVOFF, POFF, BP, OUTF, NSEQ, L) do {                \
        int M_ = (NSEQ) * (L);                                                   \
        gemm5((AH), (AL), wh + (QKVOFF), nullptr, qkv,                           \
              nullptr, nullptr, M_, 3 * CDIM, CDIM, 0);                          \
        { dim3 blk_(16, 16);                                                     \
          dim3 grd_(((L) + 15) / 16, ((L) + 15) / 16, (NSEQ) * NHEAD);           \
          attn_scores_kernel<<<grd_, blk_>>>(qkv, scores, (L), ATT_SCALE); }     \
        { int rows_ = (NSEQ) * NHEAD * (L);                                      \
          softmax_kernel<<<(rows_ + 7) / 8, 256>>>(scores, rows_, (L)); }        \
        { dim3 blk_(HDIM, 4);                                                    \
          dim3 grd_(((L) + 3) / 4, (NSEQ) * NHEAD);                              \
          attn_out_kernel<<<grd_, blk_>>>(qkv, scores, pbh, pbl, (L)); }         \
        gemm5(pbh, pbl, wh + (POFF), (BP), (OUTF),                               \
              nullptr, nullptr, M_, CDIM, CDIM, 0);                              \
    } while (0)

    // 2) Temporal MHAs
    RUN_MHA(pah, pal, OFF_QKV16, OFF_P16, bp16, x16, BKR, 16);

    {
        size_t tot = (size_t)BKR * 8 * CDIM;
        gather_tail_kernel<<<(int)((tot + EW - 1) / EW), (int)EW>>>(xtn, pah, pal, 8);
    }
    RUN_MHA(pah, pal, OFF_QKV8, OFF_P8, bp8, x8, BKR, 8);

    {
        size_t tot = (size_t)BKR * 4 * CDIM;
        gather_tail_kernel<<<(int)((tot + EW - 1) / EW), (int)EW>>>(xtn, pah, pal, 4);
    }
    RUN_MHA(pah, pal, OFF_QKV4, OFF_P4, bp4, x4, BKR, 4);

    // 3) Blend scales -> split planes for Wtfc
    {
        size_t tot = (size_t)MT * CDIM;
        combine_kernel<<<(int)((tot + EW - 1) / EW), (int)EW>>>(x16, x8, x4, pah, pal);
    }

    // 4) xt_full = x16 @ Wtfc + btfc + x[:,1:,:]
    gemm5(pah, pal, wh + OFF_TFC, btfc, xtfull, nullptr, nullptr,
          MT, CDIM, CDIM, 0);
    {
        size_t tot = (size_t)MT * CDIM;
        add_x_residual_kernel<<<(int)((tot + EW - 1) / EW), (int)EW>>>(xtfull, x);
    }

    // 5) Spatial MHA
    build_xs_ln_kernel<<<MSP, 256>>>(x, xtfull, ln1_g, ln1_b, pah, pal);
    RUN_MHA(pah, pal, OFF_QKV_S, OFF_P_S, bproj_s, ressp, SSP, LSP);

    // 6) CLS path
    ln_cls_kernel<<<SSP, 256>>>(ressp, clssp, lncls_g, lncls_b);
    cls_attn_kernel<<<BBATCH, 256>>>(clssp, clsout);

    // 7) x_cat
    {
        size_t tot = (size_t)MOUT * CDIM;
        build_xcat_kernel<<<(int)((tot + EW - 1) / EW), (int)EW>>>(x, xtfull, ressp, clsout, xcat);
    }

    // 8) MLP
    ln_contig_split_kernel<<<MOUT, 256>>>(xcat, pah, pal, ln2_g, ln2_b, MOUT);
    gemm5(pah, pal, wh + OFF_FC1, bfc1, nullptr, h1h, h1l, MOUT, HID, CDIM, 1);
    gemm5(h1h, h1l, wh + OFF_FC2, bfc2, h2, nullptr, nullptr, MOUT, CDIM, HID, 0);
    {
        size_t tot = (size_t)MOUT * CDIM;
        final_add_kernel<<<(int)((tot + EW - 1) / EW), (int)EW>>>(xcat, h2, out);
    }
    #undef RUN_MHA
    #undef CONVW
}

// round 6
// speedup vs baseline: 2.8377x; 1.0004x over previous
#include <cuda_runtime.h>
#include <cuda_fp16.h>
#include <math.h>
#include <stddef.h>
#include <stdint.h>

#define CDIM 768
#define NHEAD 12
#define HDIM 64
#define BBATCH 4
#define TT 16
#define KPATCH 196
#define LSEQ 3137           // 1 + K*T
#define BKR 784             // B*K
#define MT 12544            // BKR*TT
#define SSP 64              // B*T
#define LSP 197             // 1 + K
#define MSP 12608           // SSP*LSP
#define MOUT 12548          // B*LSEQ
#define HID 3072
#define ATT_SCALE 0.125f    // (64)^-0.5

typedef __half h16;

// ------------------------- device scratch (static, allocation-free) ---------
__device__ float g_xtn   [(size_t)MT   * CDIM];
__device__ float g_qkv   [(size_t)MSP  * 3 * CDIM];
__device__ float g_x16   [(size_t)MT   * CDIM];
__device__ float g_x8    [(size_t)BKR * 8 * CDIM];
__device__ float g_x4    [(size_t)BKR * 4 * CDIM];
__device__ float g_xtfull[(size_t)MT   * CDIM];
__device__ float g_ressp [(size_t)MSP  * CDIM];
__device__ float g_scores[(size_t)SSP * NHEAD * LSP * LSP];
__device__ float g_clssp [(size_t)SSP  * CDIM];
__device__ float g_clsout[(size_t)BBATCH * CDIM];
__device__ float g_xcat  [(size_t)MOUT * CDIM];
__device__ float g_h2    [(size_t)MOUT * CDIM];

// activation planes (fp16 hi/lo)
#define PA_ELEMS ((size_t)MSP * CDIM)
__device__ h16 g_pah[PA_ELEMS];
__device__ h16 g_pal[PA_ELEMS];
__device__ h16 g_pbh[PA_ELEMS];
__device__ h16 g_pbl[PA_ELEMS];
__device__ h16 g_h1h[(size_t)MOUT * HID];
__device__ h16 g_h1l[(size_t)MOUT * HID];

// weight plane (fp16 single), [K,N] row-major, same layout as f32 source
#define WPOOL 14745600
__device__ h16 g_wh[(size_t)WPOOL];
#define OFF_QKV_S   0u
#define OFF_QKV4    1769472u
#define OFF_QKV8    3538944u
#define OFF_QKV16   5308416u
#define OFF_P_S     7077888u
#define OFF_P4      7667712u
#define OFF_P8      8257536u
#define OFF_P16     8847360u
#define OFF_TFC     9437184u
#define OFF_FC1    10027008u
#define OFF_FC2    12386304u

// ------------------------- split helpers ------------------------------------
__device__ __forceinline__ void split2(float v, unsigned short& h, unsigned short& l) {
    h16 hh = __float2half_rn(v);
    h16 ll = __float2half_rn(v - __half2float(hh));
    h = __half_as_ushort(hh);
    l = __half_as_ushort(ll);
}

// weights: f32 -> fp16 single plane (vectorized)
__global__ void convW_kernel(const float* __restrict__ in, h16* __restrict__ hp, size_t n4) {
    size_t i = (size_t)blockIdx.x * blockDim.x + threadIdx.x;
    if (i >= n4) return;
    float4 v = ((const float4*)in)[i];
    unsigned short h0 = __half_as_ushort(__float2half_rn(v.x));
    unsigned short h1 = __half_as_ushort(__float2half_rn(v.y));
    unsigned short h2 = __half_as_ushort(__float2half_rn(v.z));
    unsigned short h3 = __half_as_ushort(__float2half_rn(v.w));
    ((uint2*)hp)[i] = make_uint2((uint32_t)h0 | ((uint32_t)h1 << 16),
                                 (uint32_t)h2 | ((uint32_t)h3 << 16));
}

// ======================= tensor-core GEMM (fp16, 2-term A split) ============
// C = (Ah+Al) * Bh, fp32 accumulate. CTA 128x128, BK=32, cp.async 3 stages.

#define LDSM4(R, addr) \
    asm volatile("ldmatrix.sync.aligned.m8n8.x4.shared.b16 {%0,%1,%2,%3}, [%4];" \
                 : "=r"(R[0]), "=r"(R[1]), "=r"(R[2]), "=r"(R[3]) : "r"(addr))
#define LDSM4T(R, addr) \
    asm volatile("ldmatrix.sync.aligned.m8n8.x4.trans.shared.b16 {%0,%1,%2,%3}, [%4];" \
                 : "=r"(R[0]), "=r"(R[1]), "=r"(R[2]), "=r"(R[3]) : "r"(addr))
#define MMA_F16(d, a, b0, b1) \
    asm volatile("mma.sync.aligned.m16n8k16.row.col.f32.f16.f16.f32 " \
                 "{%0,%1,%2,%3}, {%4,%5,%6,%7}, {%8,%9}, {%0,%1,%2,%3};" \
                 : "+f"(d[0]), "+f"(d[1]), "+f"(d[2]), "+f"(d[3]) \
                 : "r"(a[0]), "r"(a[1]), "r"(a[2]), "r"(a[3]), "r"(b0), "r"(b1))

__device__ __forceinline__ int swizA(int r, int c) {    // A tile 128x32 fp16
    int b = (r << 6) | (c << 1);
    return b ^ (((r >> 1) & 7) << 4);
}
__device__ __forceinline__ int swizB(int k, int n) {    // B tile 32x128 fp16
    int b = (k << 8) | (n << 1);
    return b ^ ((k & 7) << 4);
}

__device__ __forceinline__ void cp16(uint32_t dst, const void* src, int sz) {
    asm volatile("cp.async.cg.shared.global [%0], [%1], 16, %2;"
                 :: "r"(dst), "l"(src), "r"(sz));
}

// per-stage: Ah @0 (8KB) | Al @8192 | Bh @16384 ; stride 24576
#define GEMM_STAGES 3
#define STAGE_BYTES 24576u
#define GEMM_SMEM (GEMM_STAGES * 24576)

__device__ __forceinline__ void gemm_issue_stage(
    uint32_t stage, const h16* __restrict__ Ah, const h16* __restrict__ Al,
    const h16* __restrict__ Bh,
    int M, int N, int Kd, int bm, int bn, int k0, int tid) {
    int arow = tid >> 1, akc = (tid & 1) << 4;
    int avalid = ((bm + arow) < M) ? 16 : 0;
    size_t arIdx = (size_t)(avalid ? (bm + arow) : 0);
    const h16* agh = Ah + arIdx * Kd + k0 + akc;
    const h16* agl = Al + arIdx * Kd + k0 + akc;
    uint32_t d0 = stage + swizA(arow, akc);
    uint32_t d1 = stage + swizA(arow, akc + 8);
    cp16(d0, agh, avalid);            cp16(d1, agh + 8, avalid);
    cp16(d0 + 8192u, agl, avalid);    cp16(d1 + 8192u, agl + 8, avalid);
    int bk = tid >> 3, bnc = (tid & 7) << 4;
    const h16* bgh = Bh + (size_t)(k0 + bk) * N + bn + bnc;
    uint32_t e0 = stage + 16384u + swizB(bk, bnc);
    uint32_t e1 = stage + 16384u + swizB(bk, bnc + 8);
    cp16(e0, bgh, 16);                cp16(e1, bgh + 8, 16);
}

__global__ void __launch_bounds__(256)
gemm_tc_kernel(const h16* __restrict__ Ah, const h16* __restrict__ Al,
               const h16* __restrict__ Bh,
               const float* __restrict__ bias,
               float* __restrict__ Cm,
               h16* __restrict__ Ch, h16* __restrict__ Cl,
               int M, int N, int Kd, int act) {
    extern __shared__ __align__(16) char sm[];
    uint32_t sb = (uint32_t)__cvta_generic_to_shared(sm);
    const int tid  = threadIdx.x;
    const int lane = tid & 31;
    const int w    = tid >> 5;
    const int wm   = w & 1;
    const int wn   = w >> 1;
    const int bm   = blockIdx.y * 128;
    const int bn   = blockIdx.x * 128;

    int aOff[4][2], bOff[2][2];
    {
        int ar = wm * 64 + (lane & 15);
        int ac = (lane >> 4) << 3;
        #pragma unroll
        for (int i = 0; i < 4; i++)
            #pragma unroll
            for (int s = 0; s < 2; s++)
                aOff[i][s] = swizA(ar + 16 * i, ac + 16 * s);
        int bk  = lane & 15;
        int bn0 = wn * 32 + ((lane >> 4) << 3);
        #pragma unroll
        for (int jp = 0; jp < 2; jp++)
            #pragma unroll
            for (int s = 0; s < 2; s++)
                bOff[jp][s] = 16384 + swizB(bk + 16 * s, bn0 + 16 * jp);
    }

    float acc[4][4][4];
    #pragma unroll
    for (int i = 0; i < 4; i++)
        #pragma unroll
        for (int j = 0; j < 4; j++)
            #pragma unroll
            for (int r = 0; r < 4; r++) acc[i][j][r] = 0.f;

    const int nCh = Kd >> 5;

    #pragma unroll
    for (int p = 0; p < GEMM_STAGES - 1; p++) {
        gemm_issue_stage(sb + (uint32_t)p * STAGE_BYTES, Ah, Al, Bh,
                         M, N, Kd, bm, bn, p << 5, tid);
        asm volatile("cp.async.commit_group;");
    }

    for (int kc = 0; kc < nCh; kc++) {
        asm volatile("cp.async.wait_group %0;" :: "n"(GEMM_STAGES - 2));
        __syncthreads();
        int pf = kc + GEMM_STAGES - 1;
        if (pf < nCh)
            gemm_issue_stage(sb + (uint32_t)(pf % GEMM_STAGES) * STAGE_BYTES,
                             Ah, Al, Bh, M, N, Kd, bm, bn, pf << 5, tid);
        asm volatile("cp.async.commit_group;");

        uint32_t stage = sb + (uint32_t)(kc % GEMM_STAGES) * STAGE_BYTES;
        #pragma unroll
        for (int s = 0; s < 2; s++) {
            uint32_t ah[4][4], al[4][4], bh[2][4];
            #pragma unroll
            for (int i = 0; i < 4; i++) {
                LDSM4(ah[i], stage + aOff[i][s]);
                LDSM4(al[i], stage + aOff[i][s] + 8192u);
            }
            #pragma unroll
            for (int jp = 0; jp < 2; jp++)
                LDSM4T(bh[jp], stage + bOff[jp][s]);
            #pragma unroll
            for (int i = 0; i < 4; i++) {
                #pragma unroll
                for (int j = 0; j < 4; j++) {
                    const uint32_t* bhj = &bh[j >> 1][(j & 1) * 2];
                    MMA_F16(acc[i][j], ah[i], bhj[0], bhj[1]);
                    MMA_F16(acc[i][j], al[i], bhj[0], bhj[1]);
                }
            }
        }
    }

    // epilogue
    #pragma unroll
    for (int i = 0; i < 4; i++) {
        int r0 = bm + wm * 64 + i * 16 + (lane >> 2);
        #pragma unroll
        for (int j = 0; j < 4; j++) {
            int c0 = bn + wn * 32 + j * 8 + (lane & 3) * 2;
            float b0 = bias ? bias[c0] : 0.f;
            float b1 = bias ? bias[c0 + 1] : 0.f;
            float v0 = acc[i][j][0] + b0, v1 = acc[i][j][1] + b1;
            float v2 = acc[i][j][2] + b0, v3 = acc[i][j][3] + b1;
            if (act == 1) {
                v0 = 0.5f * v0 * (1.f + erff(v0 * 0.70710678118654752f));
                v1 = 0.5f * v1 * (1.f + erff(v1 * 0.70710678118654752f));
                v2 = 0.5f * v2 * (1.f + erff(v2 * 0.70710678118654752f));
                v3 = 0.5f * v3 * (1.f + erff(v3 * 0.70710678118654752f));
            }
            if (Ch) {
                unsigned short h0,l0,h1,l1;
                if (r0 < M) {
                    split2(v0, h0, l0); split2(v1, h1, l1);
                    *(uint32_t*)&Ch[(size_t)r0 * N + c0] = (uint32_t)h0 | ((uint32_t)h1 << 16);
                    *(uint32_t*)&Cl[(size_t)r0 * N + c0] = (uint32_t)l0 | ((uint32_t)l1 << 16);
                }
                if (r0 + 8 < M) {
                    split2(v2, h0, l0); split2(v3, h1, l1);
                    *(uint32_t*)&Ch[(size_t)(r0 + 8) * N + c0] = (uint32_t)h0 | ((uint32_t)h1 << 16);
                    *(uint32_t*)&Cl[(size_t)(r0 + 8) * N + c0] = (uint32_t)l0 | ((uint32_t)l1 << 16);
                }
            } else {
                if (r0 < M)     *(float2*)&Cm[(size_t)r0 * N + c0]       = make_float2(v0, v1);
                if (r0 + 8 < M) *(float2*)&Cm[(size_t)(r0 + 8) * N + c0] = make_float2(v2, v3);
            }
        }
    }
}

// ------------------------- LayerNorm primitives -----------------------------
__device__ __forceinline__ float2 ln_stats(const float* __restrict__ src) {
    __shared__ float sm0[8], sm1[8];
    float s = 0.f, ss = 0.f;
    for (int c = threadIdx.x; c < CDIM; c += blockDim.x) {
        float v = src[c];
        s += v; ss += v * v;
    }
    #pragma unroll
    for (int o = 16; o > 0; o >>= 1) {
        s  += __shfl_down_sync(0xffffffffu, s,  o);
        ss += __shfl_down_sync(0xffffffffu, ss, o);
    }
    int w = threadIdx.x >> 5;
    if ((threadIdx.x & 31) == 0) { sm0[w] = s; sm1[w] = ss; }
    __syncthreads();
    if (threadIdx.x == 0) {
        float a = 0.f, b2 = 0.f;
        int nw = blockDim.x >> 5;
        for (int i = 0; i < nw; i++) { a += sm0[i]; b2 += sm1[i]; }
        sm0[0] = a; sm1[0] = b2;
    }
    __syncthreads();
    float mean = sm0[0] * (1.f / CDIM);
    float var  = sm1[0] * (1.f / CDIM) - mean * mean;
    return make_float2(mean, rsqrtf(var + 1e-5f));
}

__device__ __forceinline__ void ln_row(const float* __restrict__ src,
                                       float* __restrict__ dst,
                                       const float* __restrict__ g,
                                       const float* __restrict__ bta) {
    float2 st = ln_stats(src);
    for (int c = threadIdx.x; c < CDIM; c += blockDim.x)
        dst[c] = (src[c] - st.x) * st.y * g[c] + bta[c];
}

__device__ __forceinline__ void ln_row_split(const float* __restrict__ src,
                                             h16* __restrict__ dh, h16* __restrict__ dl,
                                             const float* __restrict__ g,
                                             const float* __restrict__ bta) {
    float2 st = ln_stats(src);
    for (int c = threadIdx.x; c < CDIM; c += blockDim.x) {
        float v = (src[c] - st.x) * st.y * g[c] + bta[c];
        unsigned short h, l;
        split2(v, h, l);
        dh[c] = __ushort_as_half(h);
        dl[c] = __ushort_as_half(l);
    }
}

// LN over xt: writes f32 (for gather) + split planes (for qkv16 GEMM)
__global__ void ln_xt_kernel(const float* __restrict__ x, float* __restrict__ out,
                             h16* __restrict__ oh, h16* __restrict__ ol,
                             const float* __restrict__ g, const float* __restrict__ b) {
    int r = blockIdx.x;
    int bb = r / (KPATCH * TT);
    int off = r % (KPATCH * TT);
    const float* src = x + ((size_t)bb * LSEQ + 1 + off) * CDIM;
    float2 st = ln_stats(src);
    for (int c = threadIdx.x; c < CDIM; c += blockDim.x) {
        float v = (src[c] - st.x) * st.y * g[c] + b[c];
        out[(size_t)r * CDIM + c] = v;
        unsigned short h, l;
        split2(v, h, l);
        oh[(size_t)r * CDIM + c] = __ushort_as_half(h);
        ol[(size_t)r * CDIM + c] = __ushort_as_half(l);
    }
}

__global__ void ln_contig_split_kernel(const float* __restrict__ in,
                                       h16* __restrict__ oh, h16* __restrict__ ol,
                                       const float* __restrict__ g, const float* __restrict__ b,
                                       int M) {
    int r = blockIdx.x;
    if (r >= M) return;
    ln_row_split(in + (size_t)r * CDIM, oh + (size_t)r * CDIM, ol + (size_t)r * CDIM, g, b);
}

__global__ void ln_cls_kernel(const float* __restrict__ in, float* __restrict__ out,
                              const float* __restrict__ g, const float* __restrict__ b) {
    int r = blockIdx.x;
    ln_row(in + (size_t)r * LSP * CDIM, out + (size_t)r * CDIM, g, b);
}

__global__ void build_xs_ln_kernel(const float* __restrict__ x, const float* __restrict__ xtfull,
                                   const float* __restrict__ g, const float* __restrict__ bta,
                                   h16* __restrict__ oh, h16* __restrict__ ol) {
    int r = blockIdx.x;
    int s = r / LSP, i = r % LSP;
    int bb = s / TT, t = s % TT;
    const float* src = (i == 0)
        ? (x + (size_t)bb * LSEQ * CDIM)
        : (xtfull + ((size_t)bb * KPATCH * TT + (size_t)(i - 1) * TT + t) * CDIM);
    ln_row_split(src, oh + (size_t)r * CDIM, ol + (size_t)r * CDIM, g, bta);
}

// ------------------------- gather temporal tail (f32 -> split planes) -------
__global__ void gather_tail_kernel(const float* __restrict__ in,
                                   h16* __restrict__ oh, h16* __restrict__ ol, int Ts) {
    size_t idx = (size_t)blockIdx.x * blockDim.x + threadIdx.x;
    size_t tot = (size_t)BKR * Ts * CDIM;
    if (idx >= tot) return;
    int c = (int)(idx % CDIM);
    size_t row = idx / CDIM;
    int j = (int)(row / Ts), t = (int)(row % Ts);
    float v = in[((size_t)j * TT + (TT - Ts) + t) * CDIM + c];
    unsigned short h, l;
    split2(v, h, l);
    oh[idx] = __ushort_as_half(h);
    ol[idx] = __ushort_as_half(l);
}

// ------------------------- batched attention --------------------------------
__global__ void attn_scores_kernel(const float* __restrict__ qkv, float* __restrict__ S,
                                   int L, float scale) {
    int bh = blockIdx.z;
    int s = bh / NHEAD, h = bh % NHEAD;
    int qT = blockIdx.y * 16, kT = blockIdx.x * 16;
    __shared__ float qs[16][17], ks[16][17];
    float acc = 0.f;
    const float* qbase = qkv + (size_t)s * L * 3 * CDIM + (size_t)h * HDIM;
    const float* kbase = qbase + CDIM;
    for (int d0 = 0; d0 < HDIM; d0 += 16) {
        int qr = qT + threadIdx.y;
        qs[threadIdx.y][threadIdx.x] = (qr < L) ? qbase[(size_t)qr * 3 * CDIM + d0 + threadIdx.x] : 0.f;
        int kr = kT + threadIdx.y;
        ks[threadIdx.y][threadIdx.x] = (kr < L) ? kbase[(size_t)kr * 3 * CDIM + d0 + threadIdx.x] : 0.f;
        __syncthreads();
        #pragma unroll
        for (int dd = 0; dd < 16; dd++)
            acc = fmaf(qs[threadIdx.y][dd], ks[threadIdx.x][dd], acc);
        __syncthreads();
    }
    int qi = qT + threadIdx.y, ki = kT + threadIdx.x;
    if (qi < L && ki < L)
        S[(size_t)bh * L * L + (size_t)qi * L + ki] = acc * scale;
}

__global__ void softmax_kernel(float* __restrict__ S, int rows, int L) {
    int row = blockIdx.x * 8 + (threadIdx.x >> 5);
    if (row >= rows) return;
    int lane = threadIdx.x & 31;
    float* p = S + (size_t)row * L;
    float mx = -1e30f;
    for (int i = lane; i < L; i += 32) mx = fmaxf(mx, p[i]);
    #pragma unroll
    for (int o = 16; o > 0; o >>= 1) mx = fmaxf(mx, __shfl_xor_sync(0xffffffffu, mx, o));
    float sum = 0.f;
    for (int i = lane; i < L; i += 32) { float e = expf(p[i] - mx); p[i] = e; sum += e; }
    #pragma unroll
    for (int o = 16; o > 0; o >>= 1) sum += __shfl_xor_sync(0xffffffffu, sum, o);
    float inv = 1.f / sum;
    for (int i = lane; i < L; i += 32) p[i] *= inv;
}

// attn_out writes split fp16 planes directly (proj-GEMM A input)
__global__ void attn_out_kernel(const float* __restrict__ qkv, const float* __restrict__ S,
                                h16* __restrict__ oh, h16* __restrict__ ol, int L) {
    int bh = blockIdx.y;
    int s = bh / NHEAD, h = bh % NHEAD;
    int q = blockIdx.x * blockDim.y + threadIdx.y;
    if (q >= L) return;
    int d = threadIdx.x;
    const float* p  = S + ((size_t)bh * L + q) * L;
    const float* vb = qkv + (size_t)s * L * 3 * CDIM + 2 * CDIM + (size_t)h * HDIM + d;
    float acc = 0.f;
    for (int k = 0; k < L; k++)
        acc = fmaf(p[k], vb[(size_t)k * 3 * CDIM], acc);
    size_t o = ((size_t)s * L + q) * CDIM + (size_t)h * HDIM + d;
    unsigned short hh, ll;
    split2(acc, hh, ll);
    oh[o] = __ushort_as_half(hh);
    ol[o] = __ushort_as_half(ll);
}

// ------------------------- pointwise steps ----------------------------------
__global__ void combine_kernel(float* __restrict__ x16, const float* __restrict__ x8,
                               const float* __restrict__ x4,
                               h16* __restrict__ oh, h16* __restrict__ ol) {
    size_t idx = (size_t)blockIdx.x * blockDim.x + threadIdx.x;
    size_t tot = (size_t)MT * CDIM;
    if (idx >= tot) return;
    int c = (int)(idx % CDIM);
    size_t row = idx / CDIM;
    int j = (int)(row / TT), t = (int)(row % TT);
    float v = x16[idx];
    if (t >= 8) {
        float v8 = x8[((size_t)j * 8 + (t - 8)) * CDIM + c];
        if (t >= 12) v8 = 0.5f * v8 + 0.5f * x4[((size_t)j * 4 + (t - 12)) * CDIM + c];
        v = 0.5f * v + 0.5f * v8;
    }
    unsigned short h, l;
    split2(v, h, l);
    oh[idx] = __ushort_as_half(h);
    ol[idx] = __ushort_as_half(l);
}

__global__ void add_x_residual_kernel(float* __restrict__ xtfull, const float* __restrict__ x) {
    size_t idx = (size_t)blockIdx.x * blockDim.x + threadIdx.x;
    size_t tot = (size_t)MT * CDIM;
    if (idx >= tot) return;
    int c = (int)(idx % CDIM);
    size_t row = idx / CDIM;
    int bb = (int)(row / (KPATCH * TT));
    int off = (int)(row % (KPATCH * TT));
    xtfull[idx] += x[((size_t)bb * LSEQ + 1 + off) * CDIM + c];
}

__global__ void cls_attn_kernel(const float* __restrict__ clssp, float* __restrict__ out) {
    int b = blockIdx.x;
    __shared__ float dots[TT];
    __shared__ float wts[TT];
    int w = threadIdx.x >> 5, lane = threadIdx.x & 31;
    const float* base = clssp + (size_t)b * TT * CDIM;
    const float* tgt = base + (size_t)(TT - 1) * CDIM;
    for (int t = w; t < TT; t += 8) {
        float sd = 0.f;
        for (int c = lane; c < CDIM; c += 32) sd = fmaf(tgt[c], base[(size_t)t * CDIM + c], sd);
        #pragma unroll
        for (int o = 16; o > 0; o >>= 1) sd += __shfl_xor_sync(0xffffffffu, sd, o);
        if (lane == 0) dots[t] = sd;
    }
    __syncthreads();
    if (threadIdx.x == 0) {
        float mx = -1e30f;
        for (int t = 0; t < TT; t++) mx = fmaxf(mx, dots[t]);
        float s = 0.f;
        for (int t = 0; t < TT; t++) { float e = expf(dots[t] - mx); wts[t] = e; s += e; }
        float inv = 1.f / s;
        for (int t = 0; t < TT; t++) wts[t] *= inv;
    }
    __syncthreads();
    for (int c = threadIdx.x; c < CDIM; c += blockDim.x) {
        float a = 0.f;
        #pragma unroll
        for (int t = 0; t < TT; t++) a = fmaf(wts[t], base[(size_t)t * CDIM + c], a);
        out[(size_t)b * CDIM + c] = a;
    }
}

__global__ void build_xcat_kernel(const float* __restrict__ x, const float* __restrict__ xtfull,
                                  const float* __restrict__ ressp, const float* __restrict__ clsout,
                                  float* __restrict__ xcat) {
    size_t idx = (size_t)blockIdx.x * blockDim.x + threadIdx.x;
    size_t tot = (size_t)MOUT * CDIM;
    if (idx >= tot) return;
    int c = (int)(idx % CDIM);
    size_t row = idx / CDIM;
    int bb = (int)(row / LSEQ);
    int i = (int)(row % LSEQ);
    float v;
    if (i == 0) {
        v = x[idx] + clsout[(size_t)bb * CDIM + c];
    } else {
        int n = i - 1;
        int k = n / TT, t = n % TT;
        v = xtfull[((size_t)bb * KPATCH * TT + n) * CDIM + c]
          + ressp[(((size_t)(bb * TT + t)) * LSP + 1 + k) * CDIM + c];
    }
    xcat[idx] = v;
}

__global__ void final_add_kernel(const float* __restrict__ xcat, const float* __restrict__ h2,
                                 float* __restrict__ out) {
    size_t idx = (size_t)blockIdx.x * blockDim.x + threadIdx.x;
    size_t tot = (size_t)MOUT * CDIM;
    if (idx >= tot) return;
    out[idx] = xcat[idx] + h2[idx];
}

// ------------------------- host orchestration -------------------------------
static inline void gemm5(const h16* Ah, const h16* Al, const h16* Bh,
                         const float* bias, float* C, h16* Ch, h16* Cl,
                         int M, int N, int K, int act) {
    dim3 blk(256);
    dim3 grd(N / 128, (M + 127) / 128);
    gemm_tc_kernel<<<grd, blk, GEMM_SMEM>>>(Ah, Al, Bh, bias, C, Ch, Cl, M, N, K, act);
}

extern "C" void kernel_launch(void* const* d_in, const int* in_sizes, int n_in,
                              void* d_out, int out_size) {
    const float* x       = (const float*)d_in[0];
    const float* ln1_g   = (const float*)d_in[4];
    const float* ln1_b   = (const float*)d_in[5];
    const float* lnt_g   = (const float*)d_in[6];
    const float* lnt_b   = (const float*)d_in[7];
    const float* ln2_g   = (const float*)d_in[8];
    const float* ln2_b   = (const float*)d_in[9];
    const float* lncls_g = (const float*)d_in[10];
    const float* lncls_b = (const float*)d_in[11];
    const float* Wqkv_s  = (const float*)d_in[12];
    const float* Wproj_s = (const float*)d_in[13];
    const float* bproj_s = (const float*)d_in[14];
    const float* Wqkv4   = (const float*)d_in[15];
    const float* Wqkv8   = (const float*)d_in[16];
    const float* Wqkv16  = (const float*)d_in[17];
    const float* Wp4     = (const float*)d_in[18];
    const float* bp4     = (const float*)d_in[19];
    const float* Wp8     = (const float*)d_in[20];
    const float* bp8     = (const float*)d_in[21];
    const float* Wp16    = (const float*)d_in[22];
    const float* bp16    = (const float*)d_in[23];
    const float* Wtfc    = (const float*)d_in[24];
    const float* btfc    = (const float*)d_in[25];
    const float* Wfc1    = (const float*)d_in[26];
    const float* bfc1    = (const float*)d_in[27];
    const float* Wfc2    = (const float*)d_in[28];
    const float* bfc2    = (const float*)d_in[29];
    float* out = (float*)d_out;

    cudaFuncSetAttribute(gemm_tc_kernel,
                         cudaFuncAttributeMaxDynamicSharedMemorySize, GEMM_SMEM);

    float *xtn, *qkv, *x16, *x8, *x4, *xtfull, *ressp,
          *scores, *clssp, *clsout, *xcat, *h2;
    h16 *pah, *pal, *pbh, *pbl, *h1h, *h1l, *wh;
    cudaGetSymbolAddress((void**)&xtn,    g_xtn);
    cudaGetSymbolAddress((void**)&qkv,    g_qkv);
    cudaGetSymbolAddress((void**)&x16,    g_x16);
    cudaGetSymbolAddress((void**)&x8,     g_x8);
    cudaGetSymbolAddress((void**)&x4,     g_x4);
    cudaGetSymbolAddress((void**)&xtfull, g_xtfull);
    cudaGetSymbolAddress((void**)&ressp,  g_ressp);
    cudaGetSymbolAddress((void**)&scores, g_scores);
    cudaGetSymbolAddress((void**)&clssp,  g_clssp);
    cudaGetSymbolAddress((void**)&clsout, g_clsout);
    cudaGetSymbolAddress((void**)&xcat,   g_xcat);
    cudaGetSymbolAddress((void**)&h2,     g_h2);
    cudaGetSymbolAddress((void**)&pah,    g_pah);
    cudaGetSymbolAddress((void**)&pal,    g_pal);
    cudaGetSymbolAddress((void**)&pbh,    g_pbh);
    cudaGetSymbolAddress((void**)&pbl,    g_pbl);
    cudaGetSymbolAddress((void**)&h1h,    g_h1h);
    cudaGetSymbolAddress((void**)&h1l,    g_h1l);
    cudaGetSymbolAddress((void**)&wh,     g_wh);

    const size_t EW = 256;
    #define CONVW(src, dh, nel) do {                                             \
        size_t n4_ = (size_t)(nel) / 4;                                          \
        convW_kernel<<<(int)((n4_ + 255) / 256), 256>>>((src), (dh), n4_);       \
    } while (0)

    // 0) weight fp16 conversion ([K,N] layout preserved)
    CONVW(Wqkv_s,  wh + OFF_QKV_S, 768 * 2304);
    CONVW(Wqkv4,   wh + OFF_QKV4,  768 * 2304);
    CONVW(Wqkv8,   wh + OFF_QKV8,  768 * 2304);
    CONVW(Wqkv16,  wh + OFF_QKV16, 768 * 2304);
    CONVW(Wproj_s, wh + OFF_P_S,   768 * 768);
    CONVW(Wp4,     wh + OFF_P4,    768 * 768);
    CONVW(Wp8,     wh + OFF_P8,    768 * 768);
    CONVW(Wp16,    wh + OFF_P16,   768 * 768);
    CONVW(Wtfc,    wh + OFF_TFC,   768 * 768);
    CONVW(Wfc1,    wh + OFF_FC1,   768 * 3072);
    CONVW(Wfc2,    wh + OFF_FC2,   3072 * 768);

    // 1) LN over temporal sequences (f32 + split planes)
    ln_xt_kernel<<<MT, 256>>>(x, xtn, pah, pal, lnt_g, lnt_b);

    #define RUN_MHA(AH, AL, QKVOFF, POFF, BP, OUTF, NSEQ, L) do {                \
        int M_ = (NSEQ) * (L);                                                   \
        gemm5((AH), (AL), wh + (QKVOFF), nullptr, qkv,                           \
              nullptr, nullptr, M_, 3 * CDIM, CDIM, 0);                          \
        { dim3 blk_(16, 16);                                                     \
          dim3 grd_(((L) + 15) / 16, ((L) + 15) / 16, (NSEQ) * NHEAD);           \
          attn_scores_kernel<<<grd_, blk_>>>(qkv, scores, (L), ATT_SCALE); }     \
        { int rows_ = (NSEQ) * NHEAD * (L);                                      \
          softmax_kernel<<<(rows_ + 7) / 8, 256>>>(scores, rows_, (L)); }        \
        { dim3 blk_(HDIM, 4);                                                    \
          dim3 grd_(((L) + 3) / 4, (NSEQ) * NHEAD);                              \
          attn_out_kernel<<<grd_, blk_>>>(qkv, scores, pbh, pbl, (L)); }         \
        gemm5(pbh, pbl, wh + (POFF), (BP), (OUTF),                               \
              nullptr, nullptr, M_, CDIM, CDIM, 0);                              \
    } while (0)

    // 2) Temporal MHAs
    RUN_MHA(pah, pal, OFF_QKV16, OFF_P16, bp16, x16, BKR, 16);

    {
        size_t tot = (size_t)BKR * 8 * CDIM;
        gather_tail_kernel<<<(int)((tot + EW - 1) / EW), (int)EW>>>(xtn, pah, pal, 8);
    }
    RUN_MHA(pah, pal, OFF_QKV8, OFF_P8, bp8, x8, BKR, 8);

    {
        size_t tot = (size_t)BKR * 4 * CDIM;
        gather_tail_kernel<<<(int)((tot + EW - 1) / EW), (int)EW>>>(xtn, pah, pal, 4);
    }
    RUN_MHA(pah, pal, OFF_QKV4, OFF_P4, bp4, x4, BKR, 4);

    // 3) Blend scales -> split planes for Wtfc
    {
        size_t tot = (size_t)MT * CDIM;
        combine_kernel<<<(int)((tot + EW - 1) / EW), (int)EW>>>(x16, x8, x4, pah, pal);
    }

    // 4) xt_full = x16 @ Wtfc + btfc + x[:,1:,:]
    gemm5(pah, pal, wh + OFF_TFC, btfc, xtfull, nullptr, nullptr,
          MT, CDIM, CDIM, 0);
    {
        size_t tot = (size_t)MT * CDIM;
        add_x_residual_kernel<<<(int)((tot + EW - 1) / EW), (int)EW>>>(xtfull, x);
    }

    // 5) Spatial MHA
    build_xs_ln_kernel<<<MSP, 256>>>(x, xtfull, ln1_g, ln1_b, pah, pal);
    RUN_MHA(pah, pal, OFF_QKV_S, OFF_P_S, bproj_s, ressp, SSP, LSP);

    // 6) CLS path
    ln_cls_kernel<<<SSP, 256>>>(ressp, clssp, lncls_g, lncls_b);
    cls_attn_kernel<<<BBATCH, 256>>>(clssp, clsout);

    // 7) x_cat
    {
        size_t tot = (size_t)MOUT * CDIM;
        build_xcat_kernel<<<(int)((tot + EW - 1) / EW), (int)EW>>>(x, xtfull, ressp, clsout, xcat);
    }

    // 8) MLP
    ln_contig_split_kernel<<<MOUT, 256>>>(xcat, pah, pal, ln2_g, ln2_b, MOUT);
    gemm5(pah, pal, wh + OFF_FC1, bfc1, nullptr, h1h, h1l, MOUT, HID, CDIM, 1);
    gemm5(h1h, h1l, wh + OFF_FC2, bfc2, h2, nullptr, nullptr, MOUT, CDIM, HID, 0);
    {
        size_t tot = (size_t)MOUT * CDIM;
        final_add_kernel<<<(int)((tot + EW - 1) / EW), (int)EW>>>(xcat, h2, out);
    }
    #undef RUN_MHA
    #undef CONVW
}

// round 7
// speedup vs baseline: 3.7924x; 1.3365x over previous
#include <cuda_runtime.h>
#include <cuda_fp16.h>
#include <math.h>
#include <stddef.h>
#include <stdint.h>

#define CDIM 768
#define NHEAD 12
#define HDIM 64
#define BBATCH 4
#define TT 16
#define KPATCH 196
#define LSEQ 3137           // 1 + K*T
#define BKR 784             // B*K
#define MT 12544            // BKR*TT
#define SSP 64              // B*T
#define LSP 197             // 1 + K
#define MSP 12608           // SSP*LSP
#define MOUT 12548          // B*LSEQ
#define HID 3072
#define ATT_SCALE 0.125f    // (64)^-0.5

typedef __half h16;

// ------------------------- device scratch (static, allocation-free) ---------
__device__ float g_xtn   [(size_t)MT   * CDIM];
__device__ float g_qkv   [(size_t)MSP  * 3 * CDIM];
__device__ float g_x16   [(size_t)MT   * CDIM];
__device__ float g_x8    [(size_t)BKR * 8 * CDIM];
__device__ float g_x4    [(size_t)BKR * 4 * CDIM];
__device__ float g_xtfull[(size_t)MT   * CDIM];
__device__ float g_ressp [(size_t)MSP  * CDIM];
__device__ float g_scores[(size_t)SSP * NHEAD * LSP * LSP];
__device__ float g_clssp [(size_t)SSP  * CDIM];
__device__ float g_clsout[(size_t)BBATCH * CDIM];
__device__ float g_xcat  [(size_t)MOUT * CDIM];
__device__ float g_h2    [(size_t)MOUT * CDIM];

// activation planes (fp16 single)
#define PA_ELEMS ((size_t)MSP * CDIM)
__device__ h16 g_pah[PA_ELEMS];
__device__ h16 g_pbh[PA_ELEMS];
__device__ h16 g_h1h[(size_t)MOUT * HID];

// weight plane (fp16 single), [K,N] row-major, same layout as f32 source
#define WPOOL 14745600
__device__ h16 g_wh[(size_t)WPOOL];
#define OFF_QKV_S   0u
#define OFF_QKV4    1769472u
#define OFF_QKV8    3538944u
#define OFF_QKV16   5308416u
#define OFF_P_S     7077888u
#define OFF_P4      7667712u
#define OFF_P8      8257536u
#define OFF_P16     8847360u
#define OFF_TFC     9437184u
#define OFF_FC1    10027008u
#define OFF_FC2    12386304u

// weights: f32 -> fp16 single plane (vectorized)
__global__ void convW_kernel(const float* __restrict__ in, h16* __restrict__ hp, size_t n4) {
    size_t i = (size_t)blockIdx.x * blockDim.x + threadIdx.x;
    if (i >= n4) return;
    float4 v = ((const float4*)in)[i];
    unsigned short h0 = __half_as_ushort(__float2half_rn(v.x));
    unsigned short h1 = __half_as_ushort(__float2half_rn(v.y));
    unsigned short h2 = __half_as_ushort(__float2half_rn(v.z));
    unsigned short h3 = __half_as_ushort(__float2half_rn(v.w));
    ((uint2*)hp)[i] = make_uint2((uint32_t)h0 | ((uint32_t)h1 << 16),
                                 (uint32_t)h2 | ((uint32_t)h3 << 16));
}

// ======================= tensor-core GEMM (fp16 single-plane) ===============
// C = A * B, fp32 accumulate. CTA 128x128, BK=32, cp.async 4 stages.

#define LDSM4(R, addr) \
    asm volatile("ldmatrix.sync.aligned.m8n8.x4.shared.b16 {%0,%1,%2,%3}, [%4];" \
                 : "=r"(R[0]), "=r"(R[1]), "=r"(R[2]), "=r"(R[3]) : "r"(addr))
#define LDSM4T(R, addr) \
    asm volatile("ldmatrix.sync.aligned.m8n8.x4.trans.shared.b16 {%0,%1,%2,%3}, [%4];" \
                 : "=r"(R[0]), "=r"(R[1]), "=r"(R[2]), "=r"(R[3]) : "r"(addr))
#define MMA_F16(d, a, b0, b1) \
    asm volatile("mma.sync.aligned.m16n8k16.row.col.f32.f16.f16.f32 " \
                 "{%0,%1,%2,%3}, {%4,%5,%6,%7}, {%8,%9}, {%0,%1,%2,%3};" \
                 : "+f"(d[0]), "+f"(d[1]), "+f"(d[2]), "+f"(d[3]) \
                 : "r"(a[0]), "r"(a[1]), "r"(a[2]), "r"(a[3]), "r"(b0), "r"(b1))

__device__ __forceinline__ int swizA(int r, int c) {    // A tile 128x32 fp16
    int b = (r << 6) | (c << 1);
    return b ^ (((r >> 1) & 7) << 4);
}
__device__ __forceinline__ int swizB(int k, int n) {    // B tile 32x128 fp16
    int b = (k << 8) | (n << 1);
    return b ^ ((k & 7) << 4);
}

__device__ __forceinline__ void cp16(uint32_t dst, const void* src, int sz) {
    asm volatile("cp.async.cg.shared.global [%0], [%1], 16, %2;"
                 :: "r"(dst), "l"(src), "r"(sz));
}

// per-stage: A @0 (8KB) | B @8192 (8KB); stride 16384
#define GEMM_STAGES 4
#define STAGE_BYTES 16384u
#define GEMM_SMEM (GEMM_STAGES * 16384)

__device__ __forceinline__ void gemm_issue_stage(
    uint32_t stage, const h16* __restrict__ Ah, const h16* __restrict__ Bh,
    int M, int N, int Kd, int bm, int bn, int k0, int tid) {
    int arow = tid >> 1, akc = (tid & 1) << 4;
    int avalid = ((bm + arow) < M) ? 16 : 0;
    size_t arIdx = (size_t)(avalid ? (bm + arow) : 0);
    const h16* agh = Ah + arIdx * Kd + k0 + akc;
    uint32_t d0 = stage + swizA(arow, akc);
    uint32_t d1 = stage + swizA(arow, akc + 8);
    cp16(d0, agh, avalid);  cp16(d1, agh + 8, avalid);
    int bk = tid >> 3, bnc = (tid & 7) << 4;
    const h16* bgh = Bh + (size_t)(k0 + bk) * N + bn + bnc;
    uint32_t e0 = stage + 8192u + swizB(bk, bnc);
    uint32_t e1 = stage + 8192u + swizB(bk, bnc + 8);
    cp16(e0, bgh, 16);      cp16(e1, bgh + 8, 16);
}

__global__ void __launch_bounds__(256)
gemm_tc_kernel(const h16* __restrict__ Ah, const h16* __restrict__ Bh,
               const float* __restrict__ bias,
               float* __restrict__ Cm, h16* __restrict__ Ch,
               int M, int N, int Kd, int act) {
    extern __shared__ __align__(16) char sm[];
    uint32_t sb = (uint32_t)__cvta_generic_to_shared(sm);
    const int tid  = threadIdx.x;
    const int lane = tid & 31;
    const int w    = tid >> 5;
    const int wm   = w & 1;
    const int wn   = w >> 1;
    const int bm   = blockIdx.y * 128;
    const int bn   = blockIdx.x * 128;

    int aOff[4][2], bOff[2][2];
    {
        int ar = wm * 64 + (lane & 15);
        int ac = (lane >> 4) << 3;
        #pragma unroll
        for (int i = 0; i < 4; i++)
            #pragma unroll
            for (int s = 0; s < 2; s++)
                aOff[i][s] = swizA(ar + 16 * i, ac + 16 * s);
        int bk  = lane & 15;
        int bn0 = wn * 32 + ((lane >> 4) << 3);
        #pragma unroll
        for (int jp = 0; jp < 2; jp++)
            #pragma unroll
            for (int s = 0; s < 2; s++)
                bOff[jp][s] = 8192 + swizB(bk + 16 * s, bn0 + 16 * jp);
    }

    float acc[4][4][4];
    #pragma unroll
    for (int i = 0; i < 4; i++)
        #pragma unroll
        for (int j = 0; j < 4; j++)
            #pragma unroll
            for (int r = 0; r < 4; r++) acc[i][j][r] = 0.f;

    const int nCh = Kd >> 5;

    #pragma unroll
    for (int p = 0; p < GEMM_STAGES - 1; p++) {
        gemm_issue_stage(sb + (uint32_t)p * STAGE_BYTES, Ah, Bh,
                         M, N, Kd, bm, bn, p << 5, tid);
        asm volatile("cp.async.commit_group;");
    }

    for (int kc = 0; kc < nCh; kc++) {
        asm volatile("cp.async.wait_group %0;" :: "n"(GEMM_STAGES - 2));
        __syncthreads();
        int pf = kc + GEMM_STAGES - 1;
        if (pf < nCh)
            gemm_issue_stage(sb + (uint32_t)(pf % GEMM_STAGES) * STAGE_BYTES,
                             Ah, Bh, M, N, Kd, bm, bn, pf << 5, tid);
        asm volatile("cp.async.commit_group;");

        uint32_t stage = sb + (uint32_t)(kc % GEMM_STAGES) * STAGE_BYTES;
        #pragma unroll
        for (int s = 0; s < 2; s++) {
            uint32_t ah[4][4], bh[2][4];
            #pragma unroll
            for (int i = 0; i < 4; i++)
                LDSM4(ah[i], stage + aOff[i][s]);
            #pragma unroll
            for (int jp = 0; jp < 2; jp++)
                LDSM4T(bh[jp], stage + bOff[jp][s]);
            #pragma unroll
            for (int i = 0; i < 4; i++) {
                #pragma unroll
                for (int j = 0; j < 4; j++) {
                    const uint32_t* bhj = &bh[j >> 1][(j & 1) * 2];
                    MMA_F16(acc[i][j], ah[i], bhj[0], bhj[1]);
                }
            }
        }
    }

    // epilogue
    #pragma unroll
    for (int i = 0; i < 4; i++) {
        int r0 = bm + wm * 64 + i * 16 + (lane >> 2);
        #pragma unroll
        for (int j = 0; j < 4; j++) {
            int c0 = bn + wn * 32 + j * 8 + (lane & 3) * 2;
            float b0 = bias ? bias[c0] : 0.f;
            float b1 = bias ? bias[c0 + 1] : 0.f;
            float v0 = acc[i][j][0] + b0, v1 = acc[i][j][1] + b1;
            float v2 = acc[i][j][2] + b0, v3 = acc[i][j][3] + b1;
            if (act == 1) {
                v0 = 0.5f * v0 * (1.f + erff(v0 * 0.70710678118654752f));
                v1 = 0.5f * v1 * (1.f + erff(v1 * 0.70710678118654752f));
                v2 = 0.5f * v2 * (1.f + erff(v2 * 0.70710678118654752f));
                v3 = 0.5f * v3 * (1.f + erff(v3 * 0.70710678118654752f));
            }
            if (Ch) {
                if (r0 < M) {
                    uint32_t p = (uint32_t)__half_as_ushort(__float2half_rn(v0))
                               | ((uint32_t)__half_as_ushort(__float2half_rn(v1)) << 16);
                    *(uint32_t*)&Ch[(size_t)r0 * N + c0] = p;
                }
                if (r0 + 8 < M) {
                    uint32_t p = (uint32_t)__half_as_ushort(__float2half_rn(v2))
                               | ((uint32_t)__half_as_ushort(__float2half_rn(v3)) << 16);
                    *(uint32_t*)&Ch[(size_t)(r0 + 8) * N + c0] = p;
                }
            } else {
                if (r0 < M)     *(float2*)&Cm[(size_t)r0 * N + c0]       = make_float2(v0, v1);
                if (r0 + 8 < M) *(float2*)&Cm[(size_t)(r0 + 8) * N + c0] = make_float2(v2, v3);
            }
        }
    }
}

// ------------------------- LayerNorm primitives -----------------------------
__device__ __forceinline__ float2 ln_stats(const float* __restrict__ src) {
    __shared__ float sm0[8], sm1[8];
    float s = 0.f, ss = 0.f;
    for (int c = threadIdx.x; c < CDIM; c += blockDim.x) {
        float v = src[c];
        s += v; ss += v * v;
    }
    #pragma unroll
    for (int o = 16; o > 0; o >>= 1) {
        s  += __shfl_down_sync(0xffffffffu, s,  o);
        ss += __shfl_down_sync(0xffffffffu, ss, o);
    }
    int w = threadIdx.x >> 5;
    if ((threadIdx.x & 31) == 0) { sm0[w] = s; sm1[w] = ss; }
    __syncthreads();
    if (threadIdx.x == 0) {
        float a = 0.f, b2 = 0.f;
        int nw = blockDim.x >> 5;
        for (int i = 0; i < nw; i++) { a += sm0[i]; b2 += sm1[i]; }
        sm0[0] = a; sm1[0] = b2;
    }
    __syncthreads();
    float mean = sm0[0] * (1.f / CDIM);
    float var  = sm1[0] * (1.f / CDIM) - mean * mean;
    return make_float2(mean, rsqrtf(var + 1e-5f));
}

__device__ __forceinline__ void ln_row(const float* __restrict__ src,
                                       float* __restrict__ dst,
                                       const float* __restrict__ g,
                                       const float* __restrict__ bta) {
    float2 st = ln_stats(src);
    for (int c = threadIdx.x; c < CDIM; c += blockDim.x)
        dst[c] = (src[c] - st.x) * st.y * g[c] + bta[c];
}

__device__ __forceinline__ void ln_row_h(const float* __restrict__ src,
                                         h16* __restrict__ dh,
                                         const float* __restrict__ g,
                                         const float* __restrict__ bta) {
    float2 st = ln_stats(src);
    for (int c = threadIdx.x; c < CDIM; c += blockDim.x) {
        float v = (src[c] - st.x) * st.y * g[c] + bta[c];
        dh[c] = __float2half_rn(v);
    }
}

// LN over xt: writes f32 (for gather) + fp16 plane (for qkv16 GEMM)
__global__ void ln_xt_kernel(const float* __restrict__ x, float* __restrict__ out,
                             h16* __restrict__ oh,
                             const float* __restrict__ g, const float* __restrict__ b) {
    int r = blockIdx.x;
    int bb = r / (KPATCH * TT);
    int off = r % (KPATCH * TT);
    const float* src = x + ((size_t)bb * LSEQ + 1 + off) * CDIM;
    float2 st = ln_stats(src);
    for (int c = threadIdx.x; c < CDIM; c += blockDim.x) {
        float v = (src[c] - st.x) * st.y * g[c] + b[c];
        out[(size_t)r * CDIM + c] = v;
        oh[(size_t)r * CDIM + c] = __float2half_rn(v);
    }
}

__global__ void ln_contig_h_kernel(const float* __restrict__ in,
                                   h16* __restrict__ oh,
                                   const float* __restrict__ g, const float* __restrict__ b,
                                   int M) {
    int r = blockIdx.x;
    if (r >= M) return;
    ln_row_h(in + (size_t)r * CDIM, oh + (size_t)r * CDIM, g, b);
}

__global__ void ln_cls_kernel(const float* __restrict__ in, float* __restrict__ out,
                              const float* __restrict__ g, const float* __restrict__ b) {
    int r = blockIdx.x;
    ln_row(in + (size_t)r * LSP * CDIM, out + (size_t)r * CDIM, g, b);
}

__global__ void build_xs_ln_kernel(const float* __restrict__ x, const float* __restrict__ xtfull,
                                   const float* __restrict__ g, const float* __restrict__ bta,
                                   h16* __restrict__ oh) {
    int r = blockIdx.x;
    int s = r / LSP, i = r % LSP;
    int bb = s / TT, t = s % TT;
    const float* src = (i == 0)
        ? (x + (size_t)bb * LSEQ * CDIM)
        : (xtfull + ((size_t)bb * KPATCH * TT + (size_t)(i - 1) * TT + t) * CDIM);
    ln_row_h(src, oh + (size_t)r * CDIM, g, bta);
}

// ------------------------- gather temporal tail (f32 -> fp16 plane) ---------
__global__ void gather_tail_kernel(const float* __restrict__ in,
                                   h16* __restrict__ oh, int Ts) {
    size_t idx = (size_t)blockIdx.x * blockDim.x + threadIdx.x;
    size_t tot = (size_t)BKR * Ts * CDIM;
    if (idx >= tot) return;
    int c = (int)(idx % CDIM);
    size_t row = idx / CDIM;
    int j = (int)(row / Ts), t = (int)(row % Ts);
    float v = in[((size_t)j * TT + (TT - Ts) + t) * CDIM + c];
    oh[idx] = __float2half_rn(v);
}

// ------------------------- batched attention --------------------------------
__global__ void attn_scores_kernel(const float* __restrict__ qkv, float* __restrict__ S,
                                   int L, float scale) {
    int bh = blockIdx.z;
    int s = bh / NHEAD, h = bh % NHEAD;
    int qT = blockIdx.y * 16, kT = blockIdx.x * 16;
    __shared__ float qs[16][17], ks[16][17];
    float acc = 0.f;
    const float* qbase = qkv + (size_t)s * L * 3 * CDIM + (size_t)h * HDIM;
    const float* kbase = qbase + CDIM;
    for (int d0 = 0; d0 < HDIM; d0 += 16) {
        int qr = qT + threadIdx.y;
        qs[threadIdx.y][threadIdx.x] = (qr < L) ? qbase[(size_t)qr * 3 * CDIM + d0 + threadIdx.x] : 0.f;
        int kr = kT + threadIdx.y;
        ks[threadIdx.y][threadIdx.x] = (kr < L) ? kbase[(size_t)kr * 3 * CDIM + d0 + threadIdx.x] : 0.f;
        __syncthreads();
        #pragma unroll
        for (int dd = 0; dd < 16; dd++)
            acc = fmaf(qs[threadIdx.y][dd], ks[threadIdx.x][dd], acc);
        __syncthreads();
    }
    int qi = qT + threadIdx.y, ki = kT + threadIdx.x;
    if (qi < L && ki < L)
        S[(size_t)bh * L * L + (size_t)qi * L + ki] = acc * scale;
}

__global__ void softmax_kernel(float* __restrict__ S, int rows, int L) {
    int row = blockIdx.x * 8 + (threadIdx.x >> 5);
    if (row >= rows) return;
    int lane = threadIdx.x & 31;
    float* p = S + (size_t)row * L;
    float mx = -1e30f;
    for (int i = lane; i < L; i += 32) mx = fmaxf(mx, p[i]);
    #pragma unroll
    for (int o = 16; o > 0; o >>= 1) mx = fmaxf(mx, __shfl_xor_sync(0xffffffffu, mx, o));
    float sum = 0.f;
    for (int i = lane; i < L; i += 32) { float e = expf(p[i] - mx); p[i] = e; sum += e; }
    #pragma unroll
    for (int o = 16; o > 0; o >>= 1) sum += __shfl_xor_sync(0xffffffffu, sum, o);
    float inv = 1.f / sum;
    for (int i = lane; i < L; i += 32) p[i] *= inv;
}

// attn_out writes fp16 plane directly (proj-GEMM A input)
__global__ void attn_out_kernel(const float* __restrict__ qkv, const float* __restrict__ S,
                                h16* __restrict__ oh, int L) {
    int bh = blockIdx.y;
    int s = bh / NHEAD, h = bh % NHEAD;
    int q = blockIdx.x * blockDim.y + threadIdx.y;
    if (q >= L) return;
    int d = threadIdx.x;
    const float* p  = S + ((size_t)bh * L + q) * L;
    const float* vb = qkv + (size_t)s * L * 3 * CDIM + 2 * CDIM + (size_t)h * HDIM + d;
    float acc = 0.f;
    for (int k = 0; k < L; k++)
        acc = fmaf(p[k], vb[(size_t)k * 3 * CDIM], acc);
    size_t o = ((size_t)s * L + q) * CDIM + (size_t)h * HDIM + d;
    oh[o] = __float2half_rn(acc);
}

// ------------------------- pointwise steps ----------------------------------
__global__ void combine_kernel(float* __restrict__ x16, const float* __restrict__ x8,
                               const float* __restrict__ x4, h16* __restrict__ oh) {
    size_t idx = (size_t)blockIdx.x * blockDim.x + threadIdx.x;
    size_t tot = (size_t)MT * CDIM;
    if (idx >= tot) return;
    int c = (int)(idx % CDIM);
    size_t row = idx / CDIM;
    int j = (int)(row / TT), t = (int)(row % TT);
    float v = x16[idx];
    if (t >= 8) {
        float v8 = x8[((size_t)j * 8 + (t - 8)) * CDIM + c];
        if (t >= 12) v8 = 0.5f * v8 + 0.5f * x4[((size_t)j * 4 + (t - 12)) * CDIM + c];
        v = 0.5f * v + 0.5f * v8;
    }
    oh[idx] = __float2half_rn(v);
}

__global__ void add_x_residual_kernel(float* __restrict__ xtfull, const float* __restrict__ x) {
    size_t idx = (size_t)blockIdx.x * blockDim.x + threadIdx.x;
    size_t tot = (size_t)MT * CDIM;
    if (idx >= tot) return;
    int c = (int)(idx % CDIM);
    size_t row = idx / CDIM;
    int bb = (int)(row / (KPATCH * TT));
    int off = (int)(row % (KPATCH * TT));
    xtfull[idx] += x[((size_t)bb * LSEQ + 1 + off) * CDIM + c];
}

__global__ void cls_attn_kernel(const float* __restrict__ clssp, float* __restrict__ out) {
    int b = blockIdx.x;
    __shared__ float dots[TT];
    __shared__ float wts[TT];
    int w = threadIdx.x >> 5, lane = threadIdx.x & 31;
    const float* base = clssp + (size_t)b * TT * CDIM;
    const float* tgt = base + (size_t)(TT - 1) * CDIM;
    for (int t = w; t < TT; t += 8) {
        float sd = 0.f;
        for (int c = lane; c < CDIM; c += 32) sd = fmaf(tgt[c], base[(size_t)t * CDIM + c], sd);
        #pragma unroll
        for (int o = 16; o > 0; o >>= 1) sd += __shfl_xor_sync(0xffffffffu, sd, o);
        if (lane == 0) dots[t] = sd;
    }
    __syncthreads();
    if (threadIdx.x == 0) {
        float mx = -1e30f;
        for (int t = 0; t < TT; t++) mx = fmaxf(mx, dots[t]);
        float s = 0.f;
        for (int t = 0; t < TT; t++) { float e = expf(dots[t] - mx); wts[t] = e; s += e; }
        float inv = 1.f / s;
        for (int t = 0; t < TT; t++) wts[t] *= inv;
    }
    __syncthreads();
    for (int c = threadIdx.x; c < CDIM; c += blockDim.x) {
        float a = 0.f;
        #pragma unroll
        for (int t = 0; t < TT; t++) a = fmaf(wts[t], base[(size_t)t * CDIM + c], a);
        out[(size_t)b * CDIM + c] = a;
    }
}

__global__ void build_xcat_kernel(const float* __restrict__ x, const float* __restrict__ xtfull,
                                  const float* __restrict__ ressp, const float* __restrict__ clsout,
                                  float* __restrict__ xcat) {
    size_t idx = (size_t)blockIdx.x * blockDim.x + threadIdx.x;
    size_t tot = (size_t)MOUT * CDIM;
    if (idx >= tot) return;
    int c = (int)(idx % CDIM);
    size_t row = idx / CDIM;
    int bb = (int)(row / LSEQ);
    int i = (int)(row % LSEQ);
    float v;
    if (i == 0) {
        v = x[idx] + clsout[(size_t)bb * CDIM + c];
    } else {
        int n = i - 1;
        int k = n / TT, t = n % TT;
        v = xtfull[((size_t)bb * KPATCH * TT + n) * CDIM + c]
          + ressp[(((size_t)(bb * TT + t)) * LSP + 1 + k) * CDIM + c];
    }
    xcat[idx] = v;
}

__global__ void final_add_kernel(const float* __restrict__ xcat, const float* __restrict__ h2,
                                 float* __restrict__ out) {
    size_t idx = (size_t)blockIdx.x * blockDim.x + threadIdx.x;
    size_t tot = (size_t)MOUT * CDIM;
    if (idx >= tot) return;
    out[idx] = xcat[idx] + h2[idx];
}

// ------------------------- host orchestration -------------------------------
static inline void gemm5(const h16* Ah, const h16* Bh,
                         const float* bias, float* C, h16* Ch,
                         int M, int N, int K, int act) {
    dim3 blk(256);
    dim3 grd(N / 128, (M + 127) / 128);
    gemm_tc_kernel<<<grd, blk, GEMM_SMEM>>>(Ah, Bh, bias, C, Ch, M, N, K, act);
}

extern "C" void kernel_launch(void* const* d_in, const int* in_sizes, int n_in,
                              void* d_out, int out_size) {
    const float* x       = (const float*)d_in[0];
    const float* ln1_g   = (const float*)d_in[4];
    const float* ln1_b   = (const float*)d_in[5];
    const float* lnt_g   = (const float*)d_in[6];
    const float* lnt_b   = (const float*)d_in[7];
    const float* ln2_g   = (const float*)d_in[8];
    const float* ln2_b   = (const float*)d_in[9];
    const float* lncls_g = (const float*)d_in[10];
    const float* lncls_b = (const float*)d_in[11];
    const float* Wqkv_s  = (const float*)d_in[12];
    const float* Wproj_s = (const float*)d_in[13];
    const float* bproj_s = (const float*)d_in[14];
    const float* Wqkv4   = (const float*)d_in[15];
    const float* Wqkv8   = (const float*)d_in[16];
    const float* Wqkv16  = (const float*)d_in[17];
    const float* Wp4     = (const float*)d_in[18];
    const float* bp4     = (const float*)d_in[19];
    const float* Wp8     = (const float*)d_in[20];
    const float* bp8     = (const float*)d_in[21];
    const float* Wp16    = (const float*)d_in[22];
    const float* bp16    = (const float*)d_in[23];
    const float* Wtfc    = (const float*)d_in[24];
    const float* btfc    = (const float*)d_in[25];
    const float* Wfc1    = (const float*)d_in[26];
    const float* bfc1    = (const float*)d_in[27];
    const float* Wfc2    = (const float*)d_in[28];
    const float* bfc2    = (const float*)d_in[29];
    float* out = (float*)d_out;

    cudaFuncSetAttribute(gemm_tc_kernel,
                         cudaFuncAttributeMaxDynamicSharedMemorySize, GEMM_SMEM);

    float *xtn, *qkv, *x16, *x8, *x4, *xtfull, *ressp,
          *scores, *clssp, *clsout, *xcat, *h2;
    h16 *pah, *pbh, *h1h, *wh;
    cudaGetSymbolAddress((void**)&xtn,    g_xtn);
    cudaGetSymbolAddress((void**)&qkv,    g_qkv);
    cudaGetSymbolAddress((void**)&x16,    g_x16);
    cudaGetSymbolAddress((void**)&x8,     g_x8);
    cudaGetSymbolAddress((void**)&x4,     g_x4);
    cudaGetSymbolAddress((void**)&xtfull, g_xtfull);
    cudaGetSymbolAddress((void**)&ressp,  g_ressp);
    cudaGetSymbolAddress((void**)&scores, g_scores);
    cudaGetSymbolAddress((void**)&clssp,  g_clssp);
    cudaGetSymbolAddress((void**)&clsout, g_clsout);
    cudaGetSymbolAddress((void**)&xcat,   g_xcat);
    cudaGetSymbolAddress((void**)&h2,     g_h2);
    cudaGetSymbolAddress((void**)&pah,    g_pah);
    cudaGetSymbolAddress((void**)&pbh,    g_pbh);
    cudaGetSymbolAddress((void**)&h1h,    g_h1h);
    cudaGetSymbolAddress((void**)&wh,     g_wh);

    const size_t EW = 256;
    #define CONVW(src, dh, nel) do {                                             \
        size_t n4_ = (size_t)(nel) / 4;                                          \
        convW_kernel<<<(int)((n4_ + 255) / 256), 256>>>((src), (dh), n4_);       \
    } while (0)

    // 0) weight fp16 conversion ([K,N] layout preserved)
    CONVW(Wqkv_s,  wh + OFF_QKV_S, 768 * 2304);
    CONVW(Wqkv4,   wh + OFF_QKV4,  768 * 2304);
    CONVW(Wqkv8,   wh + OFF_QKV8,  768 * 2304);
    CONVW(Wqkv16,  wh + OFF_QKV16, 768 * 2304);
    CONVW(Wproj_s, wh + OFF_P_S,   768 * 768);
    CONVW(Wp4,     wh + OFF_P4,    768 * 768);
    CONVW(Wp8,     wh + OFF_P8,    768 * 768);
    CONVW(Wp16,    wh + OFF_P16,   768 * 768);
    CONVW(Wtfc,    wh + OFF_TFC,   768 * 768);
    CONVW(Wfc1,    wh + OFF_FC1,   768 * 3072);
    CONVW(Wfc2,    wh + OFF_FC2,   3072 * 768);

    // 1) LN over temporal sequences (f32 + fp16 plane)
    ln_xt_kernel<<<MT, 256>>>(x, xtn, pah, lnt_g, lnt_b);

    #define RUN_MHA(AH, QKVOFF, POFF, BP, OUTF, NSEQ, L) do {                    \
        int M_ = (NSEQ) * (L);                                                   \
        gemm5((AH), wh + (QKVOFF), nullptr, qkv, nullptr, M_, 3 * CDIM, CDIM, 0);\
        { dim3 blk_(16, 16);                                                     \
          dim3 grd_(((L) + 15) / 16, ((L) + 15) / 16, (NSEQ) * NHEAD);           \
          attn_scores_kernel<<<grd_, blk_>>>(qkv, scores, (L), ATT_SCALE); }     \
        { int rows_ = (NSEQ) * NHEAD * (L);                                      \
          softmax_kernel<<<(rows_ + 7) / 8, 256>>>(scores, rows_, (L)); }        \
        { dim3 blk_(HDIM, 4);                                                    \
          dim3 grd_(((L) + 3) / 4, (NSEQ) * NHEAD);                              \
          attn_out_kernel<<<grd_, blk_>>>(qkv, scores, pbh, (L)); }              \
        gemm5(pbh, wh + (POFF), (BP), (OUTF), nullptr, M_, CDIM, CDIM, 0);       \
    } while (0)

    // 2) Temporal MHAs
    RUN_MHA(pah, OFF_QKV16, OFF_P16, bp16, x16, BKR, 16);

    {
        size_t tot = (size_t)BKR * 8 * CDIM;
        gather_tail_kernel<<<(int)((tot + EW - 1) / EW), (int)EW>>>(xtn, pah, 8);
    }
    RUN_MHA(pah, OFF_QKV8, OFF_P8, bp8, x8, BKR, 8);

    {
        size_t tot = (size_t)BKR * 4 * CDIM;
        gather_tail_kernel<<<(int)((tot + EW - 1) / EW), (int)EW>>>(xtn, pah, 4);
    }
    RUN_MHA(pah, OFF_QKV4, OFF_P4, bp4, x4, BKR, 4);

    // 3) Blend scales -> fp16 plane for Wtfc
    {
        size_t tot = (size_t)MT * CDIM;
        combine_kernel<<<(int)((tot + EW - 1) / EW), (int)EW>>>(x16, x8, x4, pah);
    }

    // 4) xt_full = x16 @ Wtfc + btfc + x[:,1:,:]
    gemm5(pah, wh + OFF_TFC, btfc, xtfull, nullptr, MT, CDIM, CDIM, 0);
    {
        size_t tot = (size_t)MT * CDIM;
        add_x_residual_kernel<<<(int)((tot + EW - 1) / EW), (int)EW>>>(xtfull, x);
    }

    // 5) Spatial MHA
    build_xs_ln_kernel<<<MSP, 256>>>(x, xtfull, ln1_g, ln1_b, pah);
    RUN_MHA(pah, OFF_QKV_S, OFF_P_S, bproj_s, ressp, SSP, LSP);

    // 6) CLS path
    ln_cls_kernel<<<SSP, 256>>>(ressp, clssp, lncls_g, lncls_b);
    cls_attn_kernel<<<BBATCH, 256>>>(clssp, clsout);

    // 7) x_cat
    {
        size_t tot = (size_t)MOUT * CDIM;
        build_xcat_kernel<<<(int)((tot + EW - 1) / EW), (int)EW>>>(x, xtfull, ressp, clsout, xcat);
    }

    // 8) MLP
    ln_contig_h_kernel<<<MOUT, 256>>>(xcat, pah, ln2_g, ln2_b, MOUT);
    gemm5(pah, wh + OFF_FC1, bfc1, nullptr, h1h, MOUT, HID, CDIM, 1);
    gemm5(h1h, wh + OFF_FC2, bfc2, h2, nullptr, MOUT, CDIM, HID, 0);
    {
        size_t tot = (size_t)MOUT * CDIM;
        final_add_kernel<<<(int)((tot + EW - 1) / EW), (int)EW>>>(xcat, h2, out);
    }
    #undef RUN_MHA
    #undef CONVW
}

// round 8
// speedup vs baseline: 7.5226x; 1.9836x over previous
#include <cuda_runtime.h>
#include <cuda_fp16.h>
#include <math.h>
#include <stddef.h>
#include <stdint.h>

#define CDIM 768
#define NHEAD 12
#define HDIM 64
#define BBATCH 4
#define TT 16
#define KPATCH 196
#define LSEQ 3137           // 1 + K*T
#define BKR 784             // B*K
#define MT 12544            // BKR*TT
#define SSP 64              // B*T
#define LSP 197             // 1 + K
#define MSP 12608           // SSP*LSP
#define MOUT 12548          // B*LSEQ
#define HID 3072
#define KT 3136             // KPATCH*TT
#define ATT_SCALE 0.125f    // (64)^-0.5

typedef __half h16;

// ------------------------- device scratch (static, allocation-free) ---------
__device__ float g_qkv   [(size_t)MT * 3 * CDIM];               // temporal qkv (f32)
__device__ float g_x16   [(size_t)MT   * CDIM];
__device__ float g_x8    [(size_t)BKR * 8 * CDIM];
__device__ float g_x4    [(size_t)BKR * 4 * CDIM];
__device__ float g_xtfull[(size_t)MT   * CDIM];
__device__ float g_ressp [(size_t)MSP  * CDIM];
__device__ float g_scores[(size_t)BKR * NHEAD * TT * TT];       // temporal only
__device__ float g_clssp [(size_t)SSP  * CDIM];
__device__ float g_clsout[(size_t)BBATCH * CDIM];
__device__ float g_xcat  [(size_t)MOUT * CDIM];

// fp16 activation planes
#define PA_ELEMS ((size_t)MSP * CDIM)
__device__ h16 g_pah [PA_ELEMS];
__device__ h16 g_pbh [PA_ELEMS];
__device__ h16 g_pch [(size_t)MT * CDIM];
__device__ h16 g_h1h [(size_t)MOUT * HID];
__device__ h16 g_qkvh[(size_t)MSP * 3 * CDIM];                  // spatial qkv (fp16)

// weight plane (fp16), [K,N] row-major
#define WPOOL 14745600
__device__ h16 g_wh[(size_t)WPOOL];
#define OFF_QKV_S   0u
#define OFF_QKV4    1769472u
#define OFF_QKV8    3538944u
#define OFF_QKV16   5308416u
#define OFF_P_S     7077888u
#define OFF_P4      7667712u
#define OFF_P8      8257536u
#define OFF_P16     8847360u
#define OFF_TFC     9437184u
#define OFF_FC1    10027008u
#define OFF_FC2    12386304u

// weights: f32 -> fp16 (vectorized)
__global__ void convW_kernel(const float* __restrict__ in, h16* __restrict__ hp, size_t n4) {
    size_t i = (size_t)blockIdx.x * blockDim.x + threadIdx.x;
    if (i >= n4) return;
    float4 v = ((const float4*)in)[i];
    unsigned short h0 = __half_as_ushort(__float2half_rn(v.x));
    unsigned short h1 = __half_as_ushort(__float2half_rn(v.y));
    unsigned short h2 = __half_as_ushort(__float2half_rn(v.z));
    unsigned short h3 = __half_as_ushort(__float2half_rn(v.w));
    ((uint2*)hp)[i] = make_uint2((uint32_t)h0 | ((uint32_t)h1 << 16),
                                 (uint32_t)h2 | ((uint32_t)h3 << 16));
}

// ------------------------- MMA primitives ------------------------------------
#define LDSM4(R, addr) \
    asm volatile("ldmatrix.sync.aligned.m8n8.x4.shared.b16 {%0,%1,%2,%3}, [%4];" \
                 : "=r"(R[0]), "=r"(R[1]), "=r"(R[2]), "=r"(R[3]) : "r"(addr))
#define LDSM4T(R, addr) \
    asm volatile("ldmatrix.sync.aligned.m8n8.x4.trans.shared.b16 {%0,%1,%2,%3}, [%4];" \
                 : "=r"(R[0]), "=r"(R[1]), "=r"(R[2]), "=r"(R[3]) : "r"(addr))
#define MMA_F16(d, a, b0, b1) \
    asm volatile("mma.sync.aligned.m16n8k16.row.col.f32.f16.f16.f32 " \
                 "{%0,%1,%2,%3}, {%4,%5,%6,%7}, {%8,%9}, {%0,%1,%2,%3};" \
                 : "+f"(d[0]), "+f"(d[1]), "+f"(d[2]), "+f"(d[3]) \
                 : "r"(a[0]), "r"(a[1]), "r"(a[2]), "r"(a[3]), "r"(b0), "r"(b1))

__device__ __forceinline__ int swizA(int r, int c) {    // tile row stride 64B
    int b = (r << 6) | (c << 1);
    return b ^ (((r >> 1) & 7) << 4);
}
__device__ __forceinline__ int swizB(int k, int n) {    // tile row stride 256B
    int b = (k << 8) | (n << 1);
    return b ^ ((k & 7) << 4);
}
__device__ __forceinline__ int swiz128(int boff) {      // 128B rows
    return boff ^ ((boff >> 3) & 0x70);
}

__device__ __forceinline__ void cp16(uint32_t dst, const void* src, int sz) {
    asm volatile("cp.async.cg.shared.global [%0], [%1], 16, %2;"
                 :: "r"(dst), "l"(src), "r"(sz));
}

// ======================= tensor-core GEMM (fp16) =============================
// rmode: 0 none, 1 resid[r*N+c], 2 resid = x with row map r -> bb*LSEQ+1+off
#define GEMM_STAGES 4
#define STAGE_BYTES 16384u
#define GEMM_SMEM (GEMM_STAGES * 16384)

__device__ __forceinline__ void gemm_issue_stage(
    uint32_t stage, const h16* __restrict__ Ah, const h16* __restrict__ Bh,
    int M, int N, int Kd, int bm, int bn, int k0, int tid) {
    int arow = tid >> 1, akc = (tid & 1) << 4;
    int avalid = ((bm + arow) < M) ? 16 : 0;
    size_t arIdx = (size_t)(avalid ? (bm + arow) : 0);
    const h16* agh = Ah + arIdx * Kd + k0 + akc;
    uint32_t d0 = stage + swizA(arow, akc);
    uint32_t d1 = stage + swizA(arow, akc + 8);
    cp16(d0, agh, avalid);  cp16(d1, agh + 8, avalid);
    int bk = tid >> 3, bnc = (tid & 7) << 4;
    const h16* bgh = Bh + (size_t)(k0 + bk) * N + bn + bnc;
    uint32_t e0 = stage + 8192u + swizB(bk, bnc);
    uint32_t e1 = stage + 8192u + swizB(bk, bnc + 8);
    cp16(e0, bgh, 16);      cp16(e1, bgh + 8, 16);
}

__global__ void __launch_bounds__(256)
gemm_tc_kernel(const h16* __restrict__ Ah, const h16* __restrict__ Bh,
               const float* __restrict__ bias,
               const float* __restrict__ resid, int rmode,
               float* __restrict__ Cm, h16* __restrict__ Ch,
               int M, int N, int Kd, int act) {
    extern __shared__ __align__(16) char sm[];
    uint32_t sb = (uint32_t)__cvta_generic_to_shared(sm);
    const int tid  = threadIdx.x;
    const int lane = tid & 31;
    const int w    = tid >> 5;
    const int wm   = w & 1;
    const int wn   = w >> 1;
    const int bm   = blockIdx.y * 128;
    const int bn   = blockIdx.x * 128;

    int aOff[4][2], bOff[2][2];
    {
        int ar = wm * 64 + (lane & 15);
        int ac = (lane >> 4) << 3;
        #pragma unroll
        for (int i = 0; i < 4; i++)
            #pragma unroll
            for (int s = 0; s < 2; s++)
                aOff[i][s] = swizA(ar + 16 * i, ac + 16 * s);
        int bk  = lane & 15;
        int bn0 = wn * 32 + ((lane >> 4) << 3);
        #pragma unroll
        for (int jp = 0; jp < 2; jp++)
            #pragma unroll
            for (int s = 0; s < 2; s++)
                bOff[jp][s] = 8192 + swizB(bk + 16 * s, bn0 + 16 * jp);
    }

    float acc[4][4][4];
    #pragma unroll
    for (int i = 0; i < 4; i++)
        #pragma unroll
        for (int j = 0; j < 4; j++)
            #pragma unroll
            for (int r = 0; r < 4; r++) acc[i][j][r] = 0.f;

    const int nCh = Kd >> 5;
    #pragma unroll
    for (int p = 0; p < GEMM_STAGES - 1; p++) {
        gemm_issue_stage(sb + (uint32_t)p * STAGE_BYTES, Ah, Bh,
                         M, N, Kd, bm, bn, p << 5, tid);
        asm volatile("cp.async.commit_group;");
    }

    for (int kc = 0; kc < nCh; kc++) {
        asm volatile("cp.async.wait_group %0;" :: "n"(GEMM_STAGES - 2));
        __syncthreads();
        int pf = kc + GEMM_STAGES - 1;
        if (pf < nCh)
            gemm_issue_stage(sb + (uint32_t)(pf % GEMM_STAGES) * STAGE_BYTES,
                             Ah, Bh, M, N, Kd, bm, bn, pf << 5, tid);
        asm volatile("cp.async.commit_group;");

        uint32_t stage = sb + (uint32_t)(kc % GEMM_STAGES) * STAGE_BYTES;
        #pragma unroll
        for (int s = 0; s < 2; s++) {
            uint32_t ah[4][4], bh[2][4];
            #pragma unroll
            for (int i = 0; i < 4; i++)
                LDSM4(ah[i], stage + aOff[i][s]);
            #pragma unroll
            for (int jp = 0; jp < 2; jp++)
                LDSM4T(bh[jp], stage + bOff[jp][s]);
            #pragma unroll
            for (int i = 0; i < 4; i++) {
                #pragma unroll
                for (int j = 0; j < 4; j++) {
                    const uint32_t* bhj = &bh[j >> 1][(j & 1) * 2];
                    MMA_F16(acc[i][j], ah[i], bhj[0], bhj[1]);
                }
            }
        }
    }

    // epilogue
    #pragma unroll
    for (int i = 0; i < 4; i++) {
        int r0 = bm + wm * 64 + i * 16 + (lane >> 2);
        #pragma unroll
        for (int j = 0; j < 4; j++) {
            int c0 = bn + wn * 32 + j * 8 + (lane & 3) * 2;
            float b0 = bias ? bias[c0] : 0.f;
            float b1 = bias ? bias[c0 + 1] : 0.f;
            float v0 = acc[i][j][0] + b0, v1 = acc[i][j][1] + b1;
            float v2 = acc[i][j][2] + b0, v3 = acc[i][j][3] + b1;
            if (act == 1) {
                v0 = 0.5f * v0 * (1.f + erff(v0 * 0.70710678118654752f));
                v1 = 0.5f * v1 * (1.f + erff(v1 * 0.70710678118654752f));
                v2 = 0.5f * v2 * (1.f + erff(v2 * 0.70710678118654752f));
                v3 = 0.5f * v3 * (1.f + erff(v3 * 0.70710678118654752f));
            }
            if (rmode) {
                if (r0 < M) {
                    const float* rp = (rmode == 1)
                        ? resid + (size_t)r0 * N + c0
                        : resid + ((size_t)(r0 / KT) * LSEQ + 1 + (r0 % KT)) * CDIM + c0;
                    v0 += rp[0]; v1 += rp[1];
                }
                if (r0 + 8 < M) {
                    int r8 = r0 + 8;
                    const float* rp = (rmode == 1)
                        ? resid + (size_t)r8 * N + c0
                        : resid + ((size_t)(r8 / KT) * LSEQ + 1 + (r8 % KT)) * CDIM + c0;
                    v2 += rp[0]; v3 += rp[1];
                }
            }
            if (Ch) {
                if (r0 < M) {
                    uint32_t p = (uint32_t)__half_as_ushort(__float2half_rn(v0))
                               | ((uint32_t)__half_as_ushort(__float2half_rn(v1)) << 16);
                    *(uint32_t*)&Ch[(size_t)r0 * N + c0] = p;
                }
                if (r0 + 8 < M) {
                    uint32_t p = (uint32_t)__half_as_ushort(__float2half_rn(v2))
                               | ((uint32_t)__half_as_ushort(__float2half_rn(v3)) << 16);
                    *(uint32_t*)&Ch[(size_t)(r0 + 8) * N + c0] = p;
                }
            } else {
                if (r0 < M)     *(float2*)&Cm[(size_t)r0 * N + c0]       = make_float2(v0, v1);
                if (r0 + 8 < M) *(float2*)&Cm[(size_t)(r0 + 8) * N + c0] = make_float2(v2, v3);
            }
        }
    }
}

// ======================= fused spatial flash attention =======================
// One CTA per (s,h). L=197 padded to 208. qkvh fp16 [s*197+tok][3*768].
#define FLP 208
#define FNB 13
#define FQKV_BYTES 26624           // 208 * 128
#define FLASH_SMEM (3 * FQKV_BYTES)

__global__ void __launch_bounds__(256)
flash_sp_kernel(const h16* __restrict__ qkvh, h16* __restrict__ outp) {
    extern __shared__ __align__(16) char sm[];
    uint32_t sb = (uint32_t)__cvta_generic_to_shared(sm);
    const int bh = blockIdx.x;
    const int s = bh / NHEAD, h = bh % NHEAD;
    const int tid = threadIdx.x, lane = tid & 31, w = tid >> 5;

    // load Q|K|V tiles (zero-padded tokens >= 197)
    for (int i = tid; i < 3 * FLP * 8; i += 256) {
        int p = i / (FLP * 8);
        int rem = i % (FLP * 8);
        int tok = rem >> 3, c8 = rem & 7;
        uint4 v = make_uint4(0u, 0u, 0u, 0u);
        if (tok < LSP) {
            const h16* src = qkvh + ((size_t)(s * LSP + tok)) * (3 * CDIM)
                           + p * CDIM + h * HDIM + c8 * 8;
            v = *(const uint4*)src;
        }
        *(uint4*)(sm + p * FQKV_BYTES + swiz128(tok * 128 + c8 * 16)) = v;
    }
    __syncthreads();
    const uint32_t Qb = sb, Kb = sb + FQKV_BYTES, Vb = sb + 2u * FQKV_BYTES;

    const int lr = lane & 15, lc = (lane >> 4) * 8;
    const int c2 = (lane & 3) * 2;

    for (int qt = w; qt < FNB; qt += 8) {
        uint32_t qf[4][4];
        #pragma unroll
        for (int kc = 0; kc < 4; kc++)
            LDSM4(qf[kc], Qb + swiz128((qt * 16 + lr) * 128 + (lc + kc * 16) * 2));

        float o[8][4];
        #pragma unroll
        for (int n = 0; n < 8; n++)
            #pragma unroll
            for (int e = 0; e < 4; e++) o[n][e] = 0.f;
        float m0 = -1e30f, m1 = -1e30f, l0 = 0.f, l1 = 0.f;

        for (int blk = 0; blk < FNB; blk++) {
            float sacc[2][4];
            #pragma unroll
            for (int n = 0; n < 2; n++)
                #pragma unroll
                for (int e = 0; e < 4; e++) sacc[n][e] = 0.f;
            #pragma unroll
            for (int kc = 0; kc < 4; kc++) {
                uint32_t kf[4];
                LDSM4(kf, Kb + swiz128((blk * 16 + lr) * 128 + (lc + kc * 16) * 2));
                MMA_F16(sacc[0], qf[kc], kf[0], kf[2]);
                MMA_F16(sacc[1], qf[kc], kf[1], kf[3]);
            }
            // scale + mask
            #pragma unroll
            for (int nt = 0; nt < 2; nt++) {
                int nb = blk * 16 + nt * 8 + c2;
                sacc[nt][0] = (nb     < LSP) ? sacc[nt][0] * ATT_SCALE : -1e30f;
                sacc[nt][1] = (nb + 1 < LSP) ? sacc[nt][1] * ATT_SCALE : -1e30f;
                sacc[nt][2] = (nb     < LSP) ? sacc[nt][2] * ATT_SCALE : -1e30f;
                sacc[nt][3] = (nb + 1 < LSP) ? sacc[nt][3] * ATT_SCALE : -1e30f;
            }
            float bm0 = fmaxf(fmaxf(sacc[0][0], sacc[0][1]), fmaxf(sacc[1][0], sacc[1][1]));
            float bm1 = fmaxf(fmaxf(sacc[0][2], sacc[0][3]), fmaxf(sacc[1][2], sacc[1][3]));
            bm0 = fmaxf(bm0, __shfl_xor_sync(0xffffffffu, bm0, 1));
            bm0 = fmaxf(bm0, __shfl_xor_sync(0xffffffffu, bm0, 2));
            bm1 = fmaxf(bm1, __shfl_xor_sync(0xffffffffu, bm1, 1));
            bm1 = fmaxf(bm1, __shfl_xor_sync(0xffffffffu, bm1, 2));
            float mn0 = fmaxf(m0, bm0), mn1 = fmaxf(m1, bm1);
            float a0 = __expf(m0 - mn0), a1 = __expf(m1 - mn1);
            m0 = mn0; m1 = mn1;
            l0 *= a0; l1 *= a1;
            #pragma unroll
            for (int n = 0; n < 8; n++) {
                o[n][0] *= a0; o[n][1] *= a0;
                o[n][2] *= a1; o[n][3] *= a1;
            }
            uint32_t af[4];
            float ps0 = 0.f, ps1 = 0.f;
            #pragma unroll
            for (int nt = 0; nt < 2; nt++) {
                h16 p0 = __float2half_rn(__expf(sacc[nt][0] - mn0));
                h16 p1 = __float2half_rn(__expf(sacc[nt][1] - mn0));
                h16 p2 = __float2half_rn(__expf(sacc[nt][2] - mn1));
                h16 p3 = __float2half_rn(__expf(sacc[nt][3] - mn1));
                af[nt * 2]     = (uint32_t)__half_as_ushort(p0)
                               | ((uint32_t)__half_as_ushort(p1) << 16);
                af[nt * 2 + 1] = (uint32_t)__half_as_ushort(p2)
                               | ((uint32_t)__half_as_ushort(p3) << 16);
                ps0 += __half2float(p0) + __half2float(p1);
                ps1 += __half2float(p2) + __half2float(p3);
            }
            ps0 += __shfl_xor_sync(0xffffffffu, ps0, 1);
            ps0 += __shfl_xor_sync(0xffffffffu, ps0, 2);
            ps1 += __shfl_xor_sync(0xffffffffu, ps1, 1);
            ps1 += __shfl_xor_sync(0xffffffffu, ps1, 2);
            l0 += ps0; l1 += ps1;
            #pragma unroll
            for (int vd = 0; vd < 4; vd++) {
                uint32_t vf[4];
                LDSM4T(vf, Vb + swiz128((blk * 16 + lr) * 128 + (lc + vd * 16) * 2));
                MMA_F16(o[vd * 2],     af, vf[0], vf[1]);
                MMA_F16(o[vd * 2 + 1], af, vf[2], vf[3]);
            }
        }
        float inv0 = 1.f / l0, inv1 = 1.f / l1;
        int q0 = qt * 16 + (lane >> 2), q1 = q0 + 8;
        #pragma unroll
        for (int n = 0; n < 8; n++) {
            int dim = n * 8 + c2;
            if (q0 < LSP) {
                uint32_t p = (uint32_t)__half_as_ushort(__float2half_rn(o[n][0] * inv0))
                           | ((uint32_t)__half_as_ushort(__float2half_rn(o[n][1] * inv0)) << 16);
                *(uint32_t*)&outp[((size_t)(s * LSP + q0)) * CDIM + h * HDIM + dim] = p;
            }
            if (q1 < LSP) {
                uint32_t p = (uint32_t)__half_as_ushort(__float2half_rn(o[n][2] * inv1))
                           | ((uint32_t)__half_as_ushort(__float2half_rn(o[n][3] * inv1)) << 16);
                *(uint32_t*)&outp[((size_t)(s * LSP + q1)) * CDIM + h * HDIM + dim] = p;
            }
        }
    }
}

// ------------------------- LayerNorm primitives -----------------------------
__device__ __forceinline__ float2 ln_stats_val(float s, float ss) {
    __shared__ float sm0[8], sm1[8];
    #pragma unroll
    for (int o = 16; o > 0; o >>= 1) {
        s  += __shfl_down_sync(0xffffffffu, s,  o);
        ss += __shfl_down_sync(0xffffffffu, ss, o);
    }
    int w = threadIdx.x >> 5;
    if ((threadIdx.x & 31) == 0) { sm0[w] = s; sm1[w] = ss; }
    __syncthreads();
    if (threadIdx.x == 0) {
        float a = 0.f, b2 = 0.f;
        int nw = blockDim.x >> 5;
        for (int i = 0; i < nw; i++) { a += sm0[i]; b2 += sm1[i]; }
        sm0[0] = a; sm1[0] = b2;
    }
    __syncthreads();
    float mean = sm0[0] * (1.f / CDIM);
    float var  = sm1[0] * (1.f / CDIM) - mean * mean;
    return make_float2(mean, rsqrtf(var + 1e-5f));
}

__device__ __forceinline__ float2 ln_stats(const float* __restrict__ src) {
    float s = 0.f, ss = 0.f;
    for (int c = threadIdx.x; c < CDIM; c += blockDim.x) {
        float v = src[c];
        s += v; ss += v * v;
    }
    return ln_stats_val(s, ss);
}

__device__ __forceinline__ void ln_row(const float* __restrict__ src,
                                       float* __restrict__ dst,
                                       const float* __restrict__ g,
                                       const float* __restrict__ bta) {
    float2 st = ln_stats(src);
    for (int c = threadIdx.x; c < CDIM; c += blockDim.x)
        dst[c] = (src[c] - st.x) * st.y * g[c] + bta[c];
}

__device__ __forceinline__ void ln_row_h(const float* __restrict__ src,
                                         h16* __restrict__ dh,
                                         const float* __restrict__ g,
                                         const float* __restrict__ bta) {
    float2 st = ln_stats(src);
    for (int c = threadIdx.x; c < CDIM; c += blockDim.x)
        dh[c] = __float2half_rn((src[c] - st.x) * st.y * g[c] + bta[c]);
}

// LN over xt -> fp16 plane only
__global__ void ln_xt_kernel(const float* __restrict__ x, h16* __restrict__ oh,
                             const float* __restrict__ g, const float* __restrict__ b) {
    int r = blockIdx.x;
    int bb = r / KT, off = r % KT;
    ln_row_h(x + ((size_t)bb * LSEQ + 1 + off) * CDIM, oh + (size_t)r * CDIM, g, b);
}

__global__ void ln_cls_kernel(const float* __restrict__ in, float* __restrict__ out,
                              const float* __restrict__ g, const float* __restrict__ b) {
    int r = blockIdx.x;
    ln_row(in + (size_t)r * LSP * CDIM, out + (size_t)r * CDIM, g, b);
}

__global__ void build_xs_ln_kernel(const float* __restrict__ x, const float* __restrict__ xtfull,
                                   const float* __restrict__ g, const float* __restrict__ bta,
                                   h16* __restrict__ oh) {
    int r = blockIdx.x;
    int s = r / LSP, i = r % LSP;
    int bb = s / TT, t = s % TT;
    const float* src = (i == 0)
        ? (x + (size_t)bb * LSEQ * CDIM)
        : (xtfull + ((size_t)bb * KT + (size_t)(i - 1) * TT + t) * CDIM);
    ln_row_h(src, oh + (size_t)r * CDIM, g, bta);
}

// fused x_cat build + LN2 (writes xcat f32 + LN fp16 plane)
__global__ void build_xcat_ln_kernel(const float* __restrict__ x, const float* __restrict__ xtfull,
                                     const float* __restrict__ ressp, const float* __restrict__ clsout,
                                     const float* __restrict__ g, const float* __restrict__ bta,
                                     float* __restrict__ xcat, h16* __restrict__ oh) {
    int r = blockIdx.x;
    int bb = r / LSEQ, i = r % LSEQ;
    float v[3];
    float s = 0.f, ss = 0.f;
    #pragma unroll
    for (int e = 0; e < 3; e++) {
        int c = threadIdx.x + e * 256;
        float val;
        if (i == 0) {
            val = x[(size_t)bb * LSEQ * CDIM + c] + clsout[(size_t)bb * CDIM + c];
        } else {
            int n = i - 1;
            int k = n / TT, t = n % TT;
            val = xtfull[((size_t)bb * KT + n) * CDIM + c]
                + ressp[(((size_t)(bb * TT + t)) * LSP + 1 + k) * CDIM + c];
        }
        v[e] = val;
        xcat[(size_t)r * CDIM + c] = val;
        s += val; ss += val * val;
    }
    float2 st = ln_stats_val(s, ss);
    #pragma unroll
    for (int e = 0; e < 3; e++) {
        int c = threadIdx.x + e * 256;
        oh[(size_t)r * CDIM + c] = __float2half_rn((v[e] - st.x) * st.y * g[c] + bta[c]);
    }
}

// gather temporal tail (fp16 -> fp16)
__global__ void gather_tail_kernel(const h16* __restrict__ in,
                                   h16* __restrict__ oh, int Ts) {
    size_t idx = (size_t)blockIdx.x * blockDim.x + threadIdx.x;
    size_t tot = (size_t)BKR * Ts * CDIM;
    if (idx >= tot) return;
    int c = (int)(idx % CDIM);
    size_t row = idx / CDIM;
    int j = (int)(row / Ts), t = (int)(row % Ts);
    oh[idx] = in[((size_t)j * TT + (TT - Ts) + t) * CDIM + c];
}

// ------------------------- temporal attention (scalar, f32 qkv) --------------
__global__ void attn_scores_kernel(const float* __restrict__ qkv, float* __restrict__ S,
                                   int L, float scale) {
    int bh = blockIdx.z;
    int s = bh / NHEAD, h = bh % NHEAD;
    int qT = blockIdx.y * 16, kT = blockIdx.x * 16;
    __shared__ float qs[16][17], ks[16][17];
    float acc = 0.f;
    const float* qbase = qkv + (size_t)s * L * 3 * CDIM + (size_t)h * HDIM;
    const float* kbase = qbase + CDIM;
    for (int d0 = 0; d0 < HDIM; d0 += 16) {
        int qr = qT + threadIdx.y;
        qs[threadIdx.y][threadIdx.x] = (qr < L) ? qbase[(size_t)qr * 3 * CDIM + d0 + threadIdx.x] : 0.f;
        int kr = kT + threadIdx.y;
        ks[threadIdx.y][threadIdx.x] = (kr < L) ? kbase[(size_t)kr * 3 * CDIM + d0 + threadIdx.x] : 0.f;
        __syncthreads();
        #pragma unroll
        for (int dd = 0; dd < 16; dd++)
            acc = fmaf(qs[threadIdx.y][dd], ks[threadIdx.x][dd], acc);
        __syncthreads();
    }
    int qi = qT + threadIdx.y, ki = kT + threadIdx.x;
    if (qi < L && ki < L)
        S[(size_t)bh * L * L + (size_t)qi * L + ki] = acc * scale;
}

__global__ void softmax_kernel(float* __restrict__ S, int rows, int L) {
    int row = blockIdx.x * 8 + (threadIdx.x >> 5);
    if (row >= rows) return;
    int lane = threadIdx.x & 31;
    float* p = S + (size_t)row * L;
    float mx = -1e30f;
    for (int i = lane; i < L; i += 32) mx = fmaxf(mx, p[i]);
    #pragma unroll
    for (int o = 16; o > 0; o >>= 1) mx = fmaxf(mx, __shfl_xor_sync(0xffffffffu, mx, o));
    float sum = 0.f;
    for (int i = lane; i < L; i += 32) { float e = expf(p[i] - mx); p[i] = e; sum += e; }
    #pragma unroll
    for (int o = 16; o > 0; o >>= 1) sum += __shfl_xor_sync(0xffffffffu, sum, o);
    float inv = 1.f / sum;
    for (int i = lane; i < L; i += 32) p[i] *= inv;
}

__global__ void attn_out_kernel(const float* __restrict__ qkv, const float* __restrict__ S,
                                h16* __restrict__ oh, int L) {
    int bh = blockIdx.y;
    int s = bh / NHEAD, h = bh % NHEAD;
    int q = blockIdx.x * blockDim.y + threadIdx.y;
    if (q >= L) return;
    int d = threadIdx.x;
    const float* p  = S + ((size_t)bh * L + q) * L;
    const float* vb = qkv + (size_t)s * L * 3 * CDIM + 2 * CDIM + (size_t)h * HDIM + d;
    float acc = 0.f;
    for (int k = 0; k < L; k++)
        acc = fmaf(p[k], vb[(size_t)k * 3 * CDIM], acc);
    oh[((size_t)s * L + q) * CDIM + (size_t)h * HDIM + d] = __float2half_rn(acc);
}

// ------------------------- pointwise steps ----------------------------------
__global__ void combine_kernel(const float* __restrict__ x16, const float* __restrict__ x8,
                               const float* __restrict__ x4, h16* __restrict__ oh) {
    size_t idx = (size_t)blockIdx.x * blockDim.x + threadIdx.x;
    size_t tot = (size_t)MT * CDIM;
    if (idx >= tot) return;
    int c = (int)(idx % CDIM);
    size_t row = idx / CDIM;
    int j = (int)(row / TT), t = (int)(row % TT);
    float v = x16[idx];
    if (t >= 8) {
        float v8 = x8[((size_t)j * 8 + (t - 8)) * CDIM + c];
        if (t >= 12) v8 = 0.5f * v8 + 0.5f * x4[((size_t)j * 4 + (t - 12)) * CDIM + c];
        v = 0.5f * v + 0.5f * v8;
    }
    oh[idx] = __float2half_rn(v);
}

__global__ void cls_attn_kernel(const float* __restrict__ clssp, float* __restrict__ out) {
    int b = blockIdx.x;
    __shared__ float dots[TT];
    __shared__ float wts[TT];
    int w = threadIdx.x >> 5, lane = threadIdx.x & 31;
    const float* base = clssp + (size_t)b * TT * CDIM;
    const float* tgt = base + (size_t)(TT - 1) * CDIM;
    for (int t = w; t < TT; t += 8) {
        float sd = 0.f;
        for (int c = lane; c < CDIM; c += 32) sd = fmaf(tgt[c], base[(size_t)t * CDIM + c], sd);
        #pragma unroll
        for (int o = 16; o > 0; o >>= 1) sd += __shfl_xor_sync(0xffffffffu, sd, o);
        if (lane == 0) dots[t] = sd;
    }
    __syncthreads();
    if (threadIdx.x == 0) {
        float mx = -1e30f;
        for (int t = 0; t < TT; t++) mx = fmaxf(mx, dots[t]);
        float s = 0.f;
        for (int t = 0; t < TT; t++) { float e = expf(dots[t] - mx); wts[t] = e; s += e; }
        float inv = 1.f / s;
        for (int t = 0; t < TT; t++) wts[t] *= inv;
    }
    __syncthreads();
    for (int c = threadIdx.x; c < CDIM; c += blockDim.x) {
        float a = 0.f;
        #pragma unroll
        for (int t = 0; t < TT; t++) a = fmaf(wts[t], base[(size_t)t * CDIM + c], a);
        out[(size_t)b * CDIM + c] = a;
    }
}

// ------------------------- host orchestration -------------------------------
static inline void gemm5(const h16* Ah, const h16* Bh, const float* bias,
                         const float* resid, int rmode,
                         float* C, h16* Ch, int M, int N, int K, int act) {
    dim3 blk(256);
    dim3 grd(N / 128, (M + 127) / 128);
    gemm_tc_kernel<<<grd, blk, GEMM_SMEM>>>(Ah, Bh, bias, resid, rmode, C, Ch, M, N, K, act);
}

extern "C" void kernel_launch(void* const* d_in, const int* in_sizes, int n_in,
                              void* d_out, int out_size) {
    const float* x       = (const float*)d_in[0];
    const float* ln1_g   = (const float*)d_in[4];
    const float* ln1_b   = (const float*)d_in[5];
    const float* lnt_g   = (const float*)d_in[6];
    const float* lnt_b   = (const float*)d_in[7];
    const float* ln2_g   = (const float*)d_in[8];
    const float* ln2_b   = (const float*)d_in[9];
    const float* lncls_g = (const float*)d_in[10];
    const float* lncls_b = (const float*)d_in[11];
    const float* Wqkv_s  = (const float*)d_in[12];
    const float* Wproj_s = (const float*)d_in[13];
    const float* bproj_s = (const float*)d_in[14];
    const float* Wqkv4   = (const float*)d_in[15];
    const float* Wqkv8   = (const float*)d_in[16];
    const float* Wqkv16  = (const float*)d_in[17];
    const float* Wp4     = (const float*)d_in[18];
    const float* bp4     = (const float*)d_in[19];
    const float* Wp8     = (const float*)d_in[20];
    const float* bp8     = (const float*)d_in[21];
    const float* Wp16    = (const float*)d_in[22];
    const float* bp16    = (const float*)d_in[23];
    const float* Wtfc    = (const float*)d_in[24];
    const float* btfc    = (const float*)d_in[25];
    const float* Wfc1    = (const float*)d_in[26];
    const float* bfc1    = (const float*)d_in[27];
    const float* Wfc2    = (const float*)d_in[28];
    const float* bfc2    = (const float*)d_in[29];
    float* out = (float*)d_out;

    cudaFuncSetAttribute(gemm_tc_kernel,
                         cudaFuncAttributeMaxDynamicSharedMemorySize, GEMM_SMEM);
    cudaFuncSetAttribute(flash_sp_kernel,
                         cudaFuncAttributeMaxDynamicSharedMemorySize, FLASH_SMEM);

    float *qkv, *x16, *x8, *x4, *xtfull, *ressp, *scores, *clssp, *clsout, *xcat;
    h16 *pah, *pbh, *pch, *h1h, *wh, *qkvh;
    cudaGetSymbolAddress((void**)&qkv,    g_qkv);
    cudaGetSymbolAddress((void**)&x16,    g_x16);
    cudaGetSymbolAddress((void**)&x8,     g_x8);
    cudaGetSymbolAddress((void**)&x4,     g_x4);
    cudaGetSymbolAddress((void**)&xtfull, g_xtfull);
    cudaGetSymbolAddress((void**)&ressp,  g_ressp);
    cudaGetSymbolAddress((void**)&scores, g_scores);
    cudaGetSymbolAddress((void**)&clssp,  g_clssp);
    cudaGetSymbolAddress((void**)&clsout, g_clsout);
    cudaGetSymbolAddress((void**)&xcat,   g_xcat);
    cudaGetSymbolAddress((void**)&pah,    g_pah);
    cudaGetSymbolAddress((void**)&pbh,    g_pbh);
    cudaGetSymbolAddress((void**)&pch,    g_pch);
    cudaGetSymbolAddress((void**)&h1h,    g_h1h);
    cudaGetSymbolAddress((void**)&wh,     g_wh);
    cudaGetSymbolAddress((void**)&qkvh,   g_qkvh);

    const size_t EW = 256;
    #define CONVW(src, dh, nel) do {                                             \
        size_t n4_ = (size_t)(nel) / 4;                                          \
        convW_kernel<<<(int)((n4_ + 255) / 256), 256>>>((src), (dh), n4_);       \
    } while (0)

    // 0) weight fp16 conversion
    CONVW(Wqkv_s,  wh + OFF_QKV_S, 768 * 2304);
    CONVW(Wqkv4,   wh + OFF_QKV4,  768 * 2304);
    CONVW(Wqkv8,   wh + OFF_QKV8,  768 * 2304);
    CONVW(Wqkv16,  wh + OFF_QKV16, 768 * 2304);
    CONVW(Wproj_s, wh + OFF_P_S,   768 * 768);
    CONVW(Wp4,     wh + OFF_P4,    768 * 768);
    CONVW(Wp8,     wh + OFF_P8,    768 * 768);
    CONVW(Wp16,    wh + OFF_P16,   768 * 768);
    CONVW(Wtfc,    wh + OFF_TFC,   768 * 768);
    CONVW(Wfc1,    wh + OFF_FC1,   768 * 3072);
    CONVW(Wfc2,    wh + OFF_FC2,   3072 * 768);

    // 1) LN over temporal sequences -> fp16 plane
    ln_xt_kernel<<<MT, 256>>>(x, pah, lnt_g, lnt_b);

    #define RUN_TMHA(AH, QKVOFF, POFF, BP, OUTF, L) do {                         \
        int M_ = BKR * (L);                                                      \
        gemm5((AH), wh + (QKVOFF), nullptr, nullptr, 0, qkv, nullptr,            \
              M_, 3 * CDIM, CDIM, 0);                                            \
        { dim3 blk_(16, 16);                                                     \
          dim3 grd_(((L) + 15) / 16, ((L) + 15) / 16, BKR * NHEAD);              \
          attn_scores_kernel<<<grd_, blk_>>>(qkv, scores, (L), ATT_SCALE); }     \
        { int rows_ = BKR * NHEAD * (L);                                         \
          softmax_kernel<<<(rows_ + 7) / 8, 256>>>(scores, rows_, (L)); }        \
        { dim3 blk_(HDIM, 4);                                                    \
          dim3 grd_(((L) + 3) / 4, BKR * NHEAD);                                 \
          attn_out_kernel<<<grd_, blk_>>>(qkv, scores, pbh, (L)); }              \
        gemm5(pbh, wh + (POFF), (BP), nullptr, 0, (OUTF), nullptr,               \
              M_, CDIM, CDIM, 0);                                                \
    } while (0)

    // 2) Temporal MHAs
    RUN_TMHA(pah, OFF_QKV16, OFF_P16, bp16, x16, 16);
    {
        size_t tot = (size_t)BKR * 8 * CDIM;
        gather_tail_kernel<<<(int)((tot + EW - 1) / EW), (int)EW>>>(pah, pch, 8);
    }
    RUN_TMHA(pch, OFF_QKV8, OFF_P8, bp8, x8, 8);
    {
        size_t tot = (size_t)BKR * 4 * CDIM;
        gather_tail_kernel<<<(int)((tot + EW - 1) / EW), (int)EW>>>(pah, pch, 4);
    }
    RUN_TMHA(pch, OFF_QKV4, OFF_P4, bp4, x4, 4);

    // 3) Blend scales -> fp16 plane
    {
        size_t tot = (size_t)MT * CDIM;
        combine_kernel<<<(int)((tot + EW - 1) / EW), (int)EW>>>(x16, x8, x4, pch);
    }

    // 4) xt_full = blend @ Wtfc + btfc + x residual (fused epilogue)
    gemm5(pch, wh + OFF_TFC, btfc, x, 2, xtfull, nullptr, MT, CDIM, CDIM, 0);

    // 5) Spatial MHA: LN -> qkv(fp16) -> flash -> proj
    build_xs_ln_kernel<<<MSP, 256>>>(x, xtfull, ln1_g, ln1_b, pah);
    gemm5(pah, wh + OFF_QKV_S, nullptr, nullptr, 0, nullptr, qkvh, MSP, 3 * CDIM, CDIM, 0);
    flash_sp_kernel<<<SSP * NHEAD, 256, FLASH_SMEM>>>(qkvh, pbh);
    gemm5(pbh, wh + OFF_P_S, bproj_s, nullptr, 0, ressp, nullptr, MSP, CDIM, CDIM, 0);

    // 6) CLS path
    ln_cls_kernel<<<SSP, 256>>>(ressp, clssp, lncls_g, lncls_b);
    cls_attn_kernel<<<BBATCH, 256>>>(clssp, clsout);

    // 7) x_cat + LN2 fused
    build_xcat_ln_kernel<<<MOUT, 256>>>(x, xtfull, ressp, clsout, ln2_g, ln2_b, xcat, pah);

    // 8) MLP: fc1 (GELU, fp16 out) -> fc2 (+xcat residual, writes out)
    gemm5(pah, wh + OFF_FC1, bfc1, nullptr, 0, nullptr, h1h, MOUT, HID, CDIM, 1);
    gemm5(h1h, wh + OFF_FC2, bfc2, xcat, 1, out, nullptr, MOUT, CDIM, HID, 0);

    #undef RUN_TMHA
    #undef CONVW
}